// round 7
// baseline (speedup 1.0000x reference)
#include <cuda_runtime.h>
#include <cuda_bf16.h>
#include <cstdint>
#include <math.h>

// ---------------- problem constants ----------------
#define D_MODEL   1024
#define D_INNER   2048
#define D_STATE   64
#define HEADDIM   128
#define NHEADS    16
#define D_CONV    4
#define CONV_DIM  2176
#define D_IN_PROJ 4240
#define BATCH     2
#define SEQLEN    4096
#define NROWS     (BATCH*SEQLEN)  // 8192
#define RMS_EPS   1e-5f

#define LCHUNK    128
#define NCHUNK    (SEQLEN/LCHUNK)   // 32
#define SBLK      16                // staging block (steps)
#define NBLK      (LCHUNK/SBLK)     // 8

// ---------------- scratch ----------------
__device__ float g_zx [(size_t)NROWS * D_IN_PROJ];
__device__ float g_xbc[(size_t)NROWS * CONV_DIM];
__device__ float g_dec[(size_t)NROWS * NHEADS];
__device__ float g_y  [(size_t)NROWS * D_INNER];
__device__ float g_st [(size_t)BATCH * NHEADS * NCHUNK * HEADDIM * D_STATE];
__device__ float g_cum[(size_t)BATCH * NHEADS * NCHUNK * LCHUNK];
__device__ __nv_bfloat16 g_uhi [(size_t)NROWS * D_MODEL];
__device__ __nv_bfloat16 g_ulo [(size_t)NROWS * D_MODEL];
__device__ __nv_bfloat16 g_w1hi[(size_t)D_IN_PROJ * D_MODEL];
__device__ __nv_bfloat16 g_w1lo[(size_t)D_IN_PROJ * D_MODEL];
__device__ __nv_bfloat16 g_w2hi[(size_t)D_MODEL * D_INNER];
__device__ __nv_bfloat16 g_w2lo[(size_t)D_MODEL * D_INNER];
__device__ __nv_bfloat16 g_yghi[(size_t)NROWS * D_INNER];
__device__ __nv_bfloat16 g_yglo[(size_t)NROWS * D_INNER];

// ================= helpers =================
__device__ __forceinline__ uint32_t smem_to_u32(const void* p) {
    uint32_t a;
    asm("{ .reg .u64 t; cvta.to.shared.u64 t, %1; cvt.u32.u64 %0, t; }"
        : "=r"(a) : "l"(p));
    return a;
}
__device__ __forceinline__ uint32_t pack_bf16(float lo_elem, float hi_elem) {
    uint32_t r;
    asm("cvt.rn.bf16x2.f32 %0, %1, %2;" : "=r"(r) : "f"(hi_elem), "f"(lo_elem));
    return r;
}
__device__ __forceinline__ void mma_bf16(float* d, const uint32_t* a,
                                         const uint32_t* b) {
    asm volatile(
        "mma.sync.aligned.m16n8k16.row.col.f32.bf16.bf16.f32 "
        "{%0,%1,%2,%3},{%4,%5,%6,%7},{%8,%9},{%0,%1,%2,%3};"
        : "+f"(d[0]), "+f"(d[1]), "+f"(d[2]), "+f"(d[3])
        : "r"(a[0]), "r"(a[1]), "r"(a[2]), "r"(a[3]), "r"(b[0]), "r"(b[1]));
}
__device__ __forceinline__ void ldsm_x4(uint32_t& r0, uint32_t& r1,
                                        uint32_t& r2, uint32_t& r3,
                                        uint32_t addr) {
    asm volatile("ldmatrix.sync.aligned.m8n8.x4.shared.b16 {%0,%1,%2,%3}, [%4];"
                 : "=r"(r0), "=r"(r1), "=r"(r2), "=r"(r3) : "r"(addr));
}

// ================= split kernel: fp32 -> bf16 hi + bf16 lo =================
__global__ __launch_bounds__(256) void split_kernel(
    const float* __restrict__ in, __nv_bfloat16* __restrict__ hi,
    __nv_bfloat16* __restrict__ lo, int n4)
{
    int i = blockIdx.x * 256 + threadIdx.x;
    if (i >= n4) return;
    float4 v = ((const float4*)in)[i];
    uint32_t h01 = pack_bf16(v.x, v.y);
    uint32_t h23 = pack_bf16(v.z, v.w);
    float h0 = __uint_as_float(h01 << 16);
    float h1 = __uint_as_float(h01 & 0xffff0000u);
    float h2 = __uint_as_float(h23 << 16);
    float h3 = __uint_as_float(h23 & 0xffff0000u);
    uint32_t l01 = pack_bf16(v.x - h0, v.y - h1);
    uint32_t l23 = pack_bf16(v.z - h2, v.w - h3);
    ((uint2*)hi)[i] = make_uint2(h01, h23);
    ((uint2*)lo)[i] = make_uint2(l01, l23);
}

// ================= GEMM (bf16x3, ldmatrix + 3-stage cp.async) ==============
#define GB_M 128
#define GB_N 128
#define GB_K 32
#define GB_STAGE 32768
#define GB_SMEM_BYTES (3 * GB_STAGE)   // 98304

__global__ __launch_bounds__(256, 2) void gemm_bf16x3(
    const __nv_bfloat16* __restrict__ Ahi, const __nv_bfloat16* __restrict__ Alo,
    const __nv_bfloat16* __restrict__ Bhi, const __nv_bfloat16* __restrict__ Blo,
    float* __restrict__ C, int M, int N, int K)
{
    extern __shared__ char smem[];
    const uint32_t sbase = smem_to_u32(smem);
    const int tid = threadIdx.x;
    const int bm  = blockIdx.y * GB_M;
    const int bn  = blockIdx.x * GB_N;
    const int nch = K / GB_K;

    const int warp = tid >> 5;
    const int lane = tid & 31;
    const int wm = warp >> 2;
    const int wn = warp & 3;
    const int lr = lane >> 2;
    const int lc = lane & 3;

    float acc[4][4][4];
    #pragma unroll
    for (int mt = 0; mt < 4; mt++)
        #pragma unroll
        for (int nt = 0; nt < 4; nt++)
            #pragma unroll
            for (int q = 0; q < 4; q++) acc[mt][nt][q] = 0.f;

    auto load_stage = [&](int buf, int kt) {
        #pragma unroll
        for (int i = 0; i < 8; i++) {
            int idx = tid + i * 256;
            int cq = idx & 3;
            int r  = (idx >> 2) & 127;
            int t  = idx >> 9;
            uint32_t so = sbase + (uint32_t)buf * GB_STAGE + (uint32_t)t * 8192 +
                          (uint32_t)r * 64 + (uint32_t)((cq ^ ((r >> 1) & 3)) * 16);
            const __nv_bfloat16* g;
            if (t == 0)      g = Ahi + (size_t)(bm + r) * K;
            else if (t == 1) g = Alo + (size_t)(bm + r) * K;
            else {
                int gn = bn + r; if (gn >= N) gn = N - 1;
                g = (t == 2 ? Bhi : Blo) + (size_t)gn * K;
            }
            g += kt + cq * 8;
            asm volatile("cp.async.cg.shared.global [%0], [%1], 16;"
                         :: "r"(so), "l"(g));
        }
        asm volatile("cp.async.commit_group;");
    };

    load_stage(0, 0);
    if (nch > 1) load_stage(1, GB_K);

    const int rowA = wm * 64 + ((lane >> 3) & 1) * 8 + (lane & 7);
    const int rowB = wn * 32 + ((lane >> 4) & 1) * 8 + (lane & 7);
    const int sel  = ((lane & 7) >> 1) & 3;
    const int cAq  = (lane >> 4) & 1;
    const int cBq  = (lane >> 3) & 1;

    for (int c = 0; c < nch; c++) {
        if (c == nch - 1) asm volatile("cp.async.wait_group 0;");
        else              asm volatile("cp.async.wait_group 1;");
        __syncthreads();
        if (c + 2 < nch) load_stage((c + 2) % 3, (c + 2) * GB_K);

        const uint32_t stg = sbase + (uint32_t)(c % 3) * GB_STAGE;
        const uint32_t baseAhi = stg + (uint32_t)rowA * 64;
        const uint32_t baseAlo = baseAhi + 8192;
        const uint32_t baseBhi = stg + 16384 + (uint32_t)rowB * 64;
        const uint32_t baseBlo = baseBhi + 8192;

        #pragma unroll
        for (int ks = 0; ks < 2; ks++) {
            const uint32_t cAo = (uint32_t)(((ks * 2 + cAq) ^ sel) * 16);
            const uint32_t cBo = (uint32_t)(((ks * 2 + cBq) ^ sel) * 16);

            uint32_t bh[4][2], bl[4][2];
            #pragma unroll
            for (int ntp = 0; ntp < 2; ntp++) {
                uint32_t r0, r1, r2, r3;
                ldsm_x4(r0, r1, r2, r3, baseBhi + ntp * 1024 + cBo);
                bh[ntp*2][0] = r0; bh[ntp*2][1] = r1;
                bh[ntp*2+1][0] = r2; bh[ntp*2+1][1] = r3;
                ldsm_x4(r0, r1, r2, r3, baseBlo + ntp * 1024 + cBo);
                bl[ntp*2][0] = r0; bl[ntp*2][1] = r1;
                bl[ntp*2+1][0] = r2; bl[ntp*2+1][1] = r3;
            }
            #pragma unroll
            for (int mt = 0; mt < 4; mt++) {
                uint32_t ah[4], al[4];
                ldsm_x4(ah[0], ah[1], ah[2], ah[3], baseAhi + mt * 1024 + cAo);
                ldsm_x4(al[0], al[1], al[2], al[3], baseAlo + mt * 1024 + cAo);
                #pragma unroll
                for (int nt = 0; nt < 4; nt++) {
                    mma_bf16(acc[mt][nt], ah, bh[nt]);
                    mma_bf16(acc[mt][nt], ah, bl[nt]);
                    mma_bf16(acc[mt][nt], al, bh[nt]);
                }
            }
        }
    }

    #pragma unroll
    for (int mt = 0; mt < 4; mt++) {
        int row = bm + wm * 64 + mt * 16 + lr;
        #pragma unroll
        for (int nt = 0; nt < 4; nt++) {
            int col = bn + wn * 32 + nt * 8 + lc * 2;
            if (col < N) {
                *(float2*)(C + (size_t)row * N + col) =
                    make_float2(acc[mt][nt][0], acc[mt][nt][1]);
                *(float2*)(C + (size_t)(row + 8) * N + col) =
                    make_float2(acc[mt][nt][2], acc[mt][nt][3]);
            }
        }
    }
}

// ---------------- depthwise causal conv (k=4) + bias + SiLU ----------------
__global__ __launch_bounds__(256) void conv_kernel(
    const float* __restrict__ zx, const float* __restrict__ cw,
    const float* __restrict__ cb, float* __restrict__ xbc)
{
    int c = blockIdx.x * 256 + threadIdx.x;
    if (c >= CONV_DIM) return;
    int strip = blockIdx.y;
    int b     = blockIdx.z;
    int l0    = strip * 256;

    float w0 = cw[c*4+0], w1 = cw[c*4+1], w2 = cw[c*4+2], w3 = cw[c*4+3];
    float bias = cb[c];

    size_t colbase = (size_t)D_INNER + c;
    size_t rb = (size_t)b * SEQLEN;

    float xm3 = (l0-3 >= 0) ? zx[(rb + l0-3) * D_IN_PROJ + colbase] : 0.f;
    float xm2 = (l0-2 >= 0) ? zx[(rb + l0-2) * D_IN_PROJ + colbase] : 0.f;
    float xm1 = (l0-1 >= 0) ? zx[(rb + l0-1) * D_IN_PROJ + colbase] : 0.f;

    for (int l = l0; l < l0 + 256; l++) {
        float xv = zx[(rb + l) * D_IN_PROJ + colbase];
        float a = bias;
        a = fmaf(w0, xm3, a);
        a = fmaf(w1, xm2, a);
        a = fmaf(w2, xm1, a);
        a = fmaf(w3, xv,  a);
        float sv = a / (1.f + expf(-a));
        xbc[(rb + l) * CONV_DIM + c] = sv;
        xm3 = xm2; xm2 = xm1; xm1 = xv;
    }
}

// ---------------- dt -> softplus -> decay ----------------------------------
__global__ __launch_bounds__(256) void decay_kernel(
    const float* __restrict__ zx, const float* __restrict__ dt_bias,
    const float* __restrict__ A_log, float* __restrict__ dec)
{
    int idx = blockIdx.x * 256 + threadIdx.x;
    if (idx >= NROWS * NHEADS) return;
    int r = idx >> 4;
    int h = idx & 15;
    float raw = zx[(size_t)r * D_IN_PROJ + (D_IN_PROJ - NHEADS) + h] + dt_bias[h];
    float sp  = (raw > 20.f) ? raw : log1pf(expf(raw));
    float A   = -expf(A_log[h]);
    dec[idx]  = expf(sp * A);
}

// ---------------- chunked scan: stage 1 (thread=p, block-staged) -----------
// grid (c=NCHUNK, h, b), 128 threads; thread owns full 64-wide state of row p.
__global__ __launch_bounds__(128) void scan_local_kernel(
    const float* __restrict__ xbc, const float* __restrict__ dec,
    const float* __restrict__ Dvec, float* __restrict__ yout,
    float* __restrict__ states, float* __restrict__ cumout)
{
    const int c = blockIdx.x;
    const int h = blockIdx.y;
    const int b = blockIdx.z;
    const int p = threadIdx.x;

    __shared__ float sx [2][SBLK][128];
    __shared__ float sBC[2][SBLK][128];
    __shared__ float sdec[2][SBLK];

    float4 sv[16];
    #pragma unroll
    for (int q = 0; q < 16; q++) sv[q] = make_float4(0.f, 0.f, 0.f, 0.f);

    const float Dh = Dvec[h];
    const size_t base = (size_t)b * SEQLEN + (size_t)c * LCHUNK;
    const int xcol = h * HEADDIM;
    const size_t cumbase = (size_t)(((b * NHEADS + h) * NCHUNK) + c) * LCHUNK;

    const uint32_t sx_a   = smem_to_u32(sx);
    const uint32_t sbc_a  = smem_to_u32(sBC);
    const uint32_t sdec_a = smem_to_u32(sdec);

    // stage SBLK steps into buffer buf
    auto stage = [&](int buf, int l0) {
        #pragma unroll
        for (int i = 0; i < 8; i++) {
            int idx = p + i * 128;          // 0..1023
            int stp = idx >> 6;             // step 0..15
            int q   = idx & 63;             // float4 idx within 256-float row slice
            size_t row = (base + l0 + stp) * CONV_DIM;
            const float* src;
            uint32_t dst;
            if (q < 32) {
                src = xbc + row + xcol + q * 4;
                dst = sx_a + (uint32_t)((buf * SBLK + stp) * 128 + q * 4) * 4;
            } else {
                src = xbc + row + D_INNER + (q - 32) * 4;
                dst = sbc_a + (uint32_t)((buf * SBLK + stp) * 128 + (q - 32) * 4) * 4;
            }
            asm volatile("cp.async.cg.shared.global [%0], [%1], 16;"
                         :: "r"(dst), "l"(src));
        }
        if (p < SBLK) {
            const float* src = dec + (base + l0 + p) * NHEADS + h;
            uint32_t dst = sdec_a + (uint32_t)(buf * SBLK + p) * 4;
            asm volatile("cp.async.ca.shared.global [%0], [%1], 4;"
                         :: "r"(dst), "l"(src));
        }
        asm volatile("cp.async.commit_group;");
    };

    stage(0, 0);
    stage(1, SBLK);

    float cum = 1.f;

    for (int blk = 0; blk < NBLK; blk++) {
        if (blk >= NBLK - 2) asm volatile("cp.async.wait_group 0;");
        else                 asm volatile("cp.async.wait_group 1;");
        __syncthreads();
        const int cur = blk & 1;
        const int l0 = blk * SBLK;

        #pragma unroll
        for (int j = 0; j < SBLK; j++) {
            const float dcy = sdec[cur][j];
            const float xv  = sx[cur][j][p];
            const float4* Bq = (const float4*)&sBC[cur][j][0];
            const float4* Cq = (const float4*)&sBC[cur][j][64];
            float y0 = 0.f, y1 = 0.f, y2 = 0.f, y3 = 0.f;
            #pragma unroll
            for (int q = 0; q < 16; q += 4) {
                float4 b0 = Bq[q], b1 = Bq[q+1], b2 = Bq[q+2], b3 = Bq[q+3];
                float4 c0 = Cq[q], c1 = Cq[q+1], c2 = Cq[q+2], c3 = Cq[q+3];
                sv[q].x = fmaf(sv[q].x, dcy, b0.x * xv); y0 = fmaf(sv[q].x, c0.x, y0);
                sv[q].y = fmaf(sv[q].y, dcy, b0.y * xv); y0 = fmaf(sv[q].y, c0.y, y0);
                sv[q].z = fmaf(sv[q].z, dcy, b0.z * xv); y0 = fmaf(sv[q].z, c0.z, y0);
                sv[q].w = fmaf(sv[q].w, dcy, b0.w * xv); y0 = fmaf(sv[q].w, c0.w, y0);
                sv[q+1].x = fmaf(sv[q+1].x, dcy, b1.x * xv); y1 = fmaf(sv[q+1].x, c1.x, y1);
                sv[q+1].y = fmaf(sv[q+1].y, dcy, b1.y * xv); y1 = fmaf(sv[q+1].y, c1.y, y1);
                sv[q+1].z = fmaf(sv[q+1].z, dcy, b1.z * xv); y1 = fmaf(sv[q+1].z, c1.z, y1);
                sv[q+1].w = fmaf(sv[q+1].w, dcy, b1.w * xv); y1 = fmaf(sv[q+1].w, c1.w, y1);
                sv[q+2].x = fmaf(sv[q+2].x, dcy, b2.x * xv); y2 = fmaf(sv[q+2].x, c2.x, y2);
                sv[q+2].y = fmaf(sv[q+2].y, dcy, b2.y * xv); y2 = fmaf(sv[q+2].y, c2.y, y2);
                sv[q+2].z = fmaf(sv[q+2].z, dcy, b2.z * xv); y2 = fmaf(sv[q+2].z, c2.z, y2);
                sv[q+2].w = fmaf(sv[q+2].w, dcy, b2.w * xv); y2 = fmaf(sv[q+2].w, c2.w, y2);
                sv[q+3].x = fmaf(sv[q+3].x, dcy, b3.x * xv); y3 = fmaf(sv[q+3].x, c3.x, y3);
                sv[q+3].y = fmaf(sv[q+3].y, dcy, b3.y * xv); y3 = fmaf(sv[q+3].y, c3.y, y3);
                sv[q+3].z = fmaf(sv[q+3].z, dcy, b3.z * xv); y3 = fmaf(sv[q+3].z, c3.z, y3);
                sv[q+3].w = fmaf(sv[q+3].w, dcy, b3.w * xv); y3 = fmaf(sv[q+3].w, c3.w, y3);
            }
            float y = (y0 + y1) + (y2 + y3);
            yout[(base + l0 + j) * D_INNER + xcol + p] = fmaf(Dh, xv, y);
            if (p == 0) {
                cum *= dcy;
                cumout[cumbase + l0 + j] = cum;
            }
        }
        __syncthreads();                     // all done reading slot cur
        if (blk + 2 < NBLK) stage(cur, (blk + 2) * SBLK);
    }

    // write final local state: row p = 64 consecutive floats
    float* st = states +
        ((size_t)(((b * NHEADS + h) * NCHUNK) + c) * HEADDIM + p) * D_STATE;
    #pragma unroll
    for (int q = 0; q < 16; q++) *(float4*)(st + q * 4) = sv[q];
}

// ---------------- chunked scan: stage 2 (combine across chunks) ------------
__global__ __launch_bounds__(256) void scan_combine_kernel(
    float* __restrict__ states, const float* __restrict__ cum)
{
    const int h = blockIdx.x;
    const int b = blockIdx.y;
    const int tid = threadIdx.x;

    __shared__ float dprod[NCHUNK];
    if (tid < NCHUNK)
        dprod[tid] = cum[(size_t)(((b * NHEADS + h) * NCHUNK) + tid) * LCHUNK + LCHUNK - 1];
    __syncthreads();

    const size_t chunk_stride = (size_t)HEADDIM * D_STATE;
    float* base = states + (size_t)((b * NHEADS + h) * NCHUNK) * chunk_stride;

    float4 e[8];
    #pragma unroll
    for (int k = 0; k < 8; k++) e[k] = make_float4(0.f, 0.f, 0.f, 0.f);

    for (int c = 0; c < NCHUNK; c++) {
        float d = dprod[c];
        float4* p = (float4*)(base + c * chunk_stride);
        #pragma unroll
        for (int k = 0; k < 8; k++) {
            int idx = tid + k * 256;
            float4 sl = p[idx];
            p[idx] = e[k];
            e[k].x = fmaf(e[k].x, d, sl.x);
            e[k].y = fmaf(e[k].y, d, sl.y);
            e[k].z = fmaf(e[k].z, d, sl.z);
            e[k].w = fmaf(e[k].w, d, sl.w);
        }
    }
}

// ---------------- chunked scan: stage 3 (cross-chunk correction) -----------
__global__ __launch_bounds__(128) void scan_fix_kernel(
    const float* __restrict__ states, const float* __restrict__ cum,
    const float* __restrict__ xbc, float* __restrict__ yout)
{
    const int c = blockIdx.x;
    if (c == 0) return;
    const int h = blockIdx.y;
    const int b = blockIdx.z;
    const int p = threadIdx.x;

    float4 ent[16];
    const float* st = states +
        ((size_t)(((b * NHEADS + h) * NCHUNK) + c) * HEADDIM + p) * D_STATE;
    #pragma unroll
    for (int q = 0; q < 16; q++) ent[q] = *(const float4*)(st + q * 4);

    const size_t base = (size_t)b * SEQLEN + (size_t)c * LCHUNK;
    const size_t cumbase = (size_t)(((b * NHEADS + h) * NCHUNK) + c) * LCHUNK;
    const int ycol = h * HEADDIM + p;

    for (int l = 0; l < LCHUNK; l++) {
        const float* Cg = xbc + (base + l) * CONV_DIM + D_INNER + 64;
        float a0 = 0.f, a1 = 0.f, a2 = 0.f, a3 = 0.f;
        #pragma unroll
        for (int q = 0; q < 16; q += 4) {
            float4 c0 = __ldg((const float4*)(Cg + (q + 0) * 4));
            float4 c1 = __ldg((const float4*)(Cg + (q + 1) * 4));
            float4 c2 = __ldg((const float4*)(Cg + (q + 2) * 4));
            float4 c3 = __ldg((const float4*)(Cg + (q + 3) * 4));
            a0 = fmaf(ent[q+0].x, c0.x, a0); a0 = fmaf(ent[q+0].y, c0.y, a0);
            a0 = fmaf(ent[q+0].z, c0.z, a0); a0 = fmaf(ent[q+0].w, c0.w, a0);
            a1 = fmaf(ent[q+1].x, c1.x, a1); a1 = fmaf(ent[q+1].y, c1.y, a1);
            a1 = fmaf(ent[q+1].z, c1.z, a1); a1 = fmaf(ent[q+1].w, c1.w, a1);
            a2 = fmaf(ent[q+2].x, c2.x, a2); a2 = fmaf(ent[q+2].y, c2.y, a2);
            a2 = fmaf(ent[q+2].z, c2.z, a2); a2 = fmaf(ent[q+2].w, c2.w, a2);
            a3 = fmaf(ent[q+3].x, c3.x, a3); a3 = fmaf(ent[q+3].y, c3.y, a3);
            a3 = fmaf(ent[q+3].z, c3.z, a3); a3 = fmaf(ent[q+3].w, c3.w, a3);
        }
        float dot = (a0 + a1) + (a2 + a3);
        float cm = __ldg(cum + cumbase + l);
        float* yp = yout + (base + l) * D_INNER + ycol;
        *yp = fmaf(cm, dot, *yp);
    }
}

// ---------------- RMSNorm + gate, fused bf16 split output ------------------
__global__ __launch_bounds__(256) void rms_gate_kernel(
    const float* __restrict__ y, const float* __restrict__ zx,
    const float* __restrict__ rmsw,
    __nv_bfloat16* __restrict__ ygh, __nv_bfloat16* __restrict__ ygl)
{
    int r = blockIdx.x;
    const float*  yr = y  + (size_t)r * D_INNER;
    const float*  zr = zx + (size_t)r * D_IN_PROJ;
    const float4* y4 = (const float4*)yr;

    int tid = threadIdx.x;
    float ss = 0.f;
    #pragma unroll
    for (int i = 0; i < 2; i++) {
        float4 v = y4[tid + i * 256];
        ss += v.x*v.x + v.y*v.y + v.z*v.z + v.w*v.w;
    }
    #pragma unroll
    for (int o = 16; o > 0; o >>= 1) ss += __shfl_xor_sync(0xffffffffu, ss, o);
    __shared__ float red[8];
    if ((tid & 31) == 0) red[tid >> 5] = ss;
    __syncthreads();
    if (tid == 0) {
        float t = 0.f;
        #pragma unroll
        for (int i = 0; i < 8; i++) t += red[i];
        red[0] = rsqrtf(t * (1.f / D_INNER) + RMS_EPS);
    }
    __syncthreads();
    float rs = red[0];

    const float4* z4 = (const float4*)zr;
    const float4* w4 = (const float4*)rmsw;
    uint2* gh = (uint2*)(ygh + (size_t)r * D_INNER);
    uint2* gl = (uint2*)(ygl + (size_t)r * D_INNER);
    #pragma unroll
    for (int i = 0; i < 2; i++) {
        int c = tid + i * 256;
        float4 v = y4[c];
        float4 z = z4[c];
        float4 w = w4[c];
        float4 o;
        o.x = v.x * rs * w.x * (1.f / (1.f + expf(-z.x)));
        o.y = v.y * rs * w.y * (1.f / (1.f + expf(-z.y)));
        o.z = v.z * rs * w.z * (1.f / (1.f + expf(-z.z)));
        o.w = v.w * rs * w.w * (1.f / (1.f + expf(-z.w)));
        uint32_t h01 = pack_bf16(o.x, o.y);
        uint32_t h23 = pack_bf16(o.z, o.w);
        float h0 = __uint_as_float(h01 << 16);
        float h1 = __uint_as_float(h01 & 0xffff0000u);
        float h2 = __uint_as_float(h23 << 16);
        float h3 = __uint_as_float(h23 & 0xffff0000u);
        gh[c] = make_uint2(h01, h23);
        gl[c] = make_uint2(pack_bf16(o.x - h0, o.y - h1),
                           pack_bf16(o.z - h2, o.w - h3));
    }
}

// ---------------- launcher -------------------------------------------------
extern "C" void kernel_launch(void* const* d_in, const int* in_sizes, int n_in,
                              void* d_out, int out_size)
{
    const float* u        = (const float*)d_in[0];
    const float* in_proj  = (const float*)d_in[1];
    const float* conv_w   = (const float*)d_in[2];
    const float* conv_b   = (const float*)d_in[3];
    const float* dt_bias  = (const float*)d_in[4];
    const float* A_log    = (const float*)d_in[5];
    const float* Dv       = (const float*)d_in[6];
    const float* rms_w    = (const float*)d_in[7];
    const float* out_w    = (const float*)d_in[8];
    float* out = (float*)d_out;

    float *zx, *xbc, *dec, *y, *st, *cum;
    __nv_bfloat16 *uhi, *ulo, *w1hi, *w1lo, *w2hi, *w2lo, *yghi, *yglo;
    cudaGetSymbolAddress((void**)&zx,  g_zx);
    cudaGetSymbolAddress((void**)&xbc, g_xbc);
    cudaGetSymbolAddress((void**)&dec, g_dec);
    cudaGetSymbolAddress((void**)&y,   g_y);
    cudaGetSymbolAddress((void**)&st,  g_st);
    cudaGetSymbolAddress((void**)&cum, g_cum);
    cudaGetSymbolAddress((void**)&uhi,  g_uhi);
    cudaGetSymbolAddress((void**)&ulo,  g_ulo);
    cudaGetSymbolAddress((void**)&w1hi, g_w1hi);
    cudaGetSymbolAddress((void**)&w1lo, g_w1lo);
    cudaGetSymbolAddress((void**)&w2hi, g_w2hi);
    cudaGetSymbolAddress((void**)&w2lo, g_w2lo);
    cudaGetSymbolAddress((void**)&yghi, g_yghi);
    cudaGetSymbolAddress((void**)&yglo, g_yglo);

    cudaFuncSetAttribute(gemm_bf16x3,
        cudaFuncAttributeMaxDynamicSharedMemorySize, GB_SMEM_BYTES);

    // 0) split fp32 operands into bf16 hi/lo
    {
        int n4u = NROWS * D_MODEL / 4;
        split_kernel<<<(n4u + 255) / 256, 256>>>(u, uhi, ulo, n4u);
        int n4w1 = D_IN_PROJ * D_MODEL / 4;
        split_kernel<<<(n4w1 + 255) / 256, 256>>>(in_proj, w1hi, w1lo, n4w1);
        int n4w2 = D_MODEL * D_INNER / 4;
        split_kernel<<<(n4w2 + 255) / 256, 256>>>(out_w, w2hi, w2lo, n4w2);
    }
    // 1) in_proj GEMM
    {
        dim3 grid((D_IN_PROJ + GB_N - 1) / GB_N, NROWS / GB_M);
        gemm_bf16x3<<<grid, 256, GB_SMEM_BYTES>>>(uhi, ulo, w1hi, w1lo, zx,
                                                  NROWS, D_IN_PROJ, D_MODEL);
    }
    // 2) conv + silu
    {
        dim3 grid((CONV_DIM + 255) / 256, SEQLEN / 256, BATCH);
        conv_kernel<<<grid, 256>>>(zx, conv_w, conv_b, xbc);
    }
    // 3) decay precompute
    decay_kernel<<<(NROWS * NHEADS + 255) / 256, 256>>>(zx, dt_bias, A_log, dec);
    // 4) chunked SSM scan
    {
        dim3 grid(NCHUNK, NHEADS, BATCH);
        scan_local_kernel<<<grid, 128>>>(xbc, dec, Dv, y, st, cum);
    }
    {
        dim3 grid(NHEADS, BATCH);
        scan_combine_kernel<<<grid, 256>>>(st, cum);
    }
    {
        dim3 grid(NCHUNK, NHEADS, BATCH);
        scan_fix_kernel<<<grid, 128>>>(st, cum, xbc, y);
    }
    // 5) rmsnorm + gate (+ bf16 split)
    rms_gate_kernel<<<NROWS, 256>>>(y, zx, rms_w, yghi, yglo);
    // 6) out_proj GEMM
    {
        dim3 grid(D_MODEL / GB_N, NROWS / GB_M);
        gemm_bf16x3<<<grid, 256, GB_SMEM_BYTES>>>(yghi, yglo, w2hi, w2lo, out,
                                                  NROWS, D_MODEL, D_INNER);
    }
}

// round 8
// speedup vs baseline: 1.0282x; 1.0282x over previous
#include <cuda_runtime.h>
#include <cuda_bf16.h>
#include <cstdint>
#include <math.h>

// ---------------- problem constants ----------------
#define D_MODEL   1024
#define D_INNER   2048
#define D_STATE   64
#define HEADDIM   128
#define NHEADS    16
#define D_CONV    4
#define CONV_DIM  2176
#define D_IN_PROJ 4240
#define BATCH     2
#define SEQLEN    4096
#define NROWS     (BATCH*SEQLEN)  // 8192
#define RMS_EPS   1e-5f

#define LCHUNK    128
#define NCHUNK    (SEQLEN/LCHUNK)   // 32
#define SBLK      16                // staging block (steps)
#define NBLK      (LCHUNK/SBLK)     // 8

// ---------------- scratch ----------------
__device__ float g_zx [(size_t)NROWS * D_IN_PROJ];
__device__ float g_xbc[(size_t)NROWS * CONV_DIM];
__device__ float g_dec[(size_t)NROWS * NHEADS];
__device__ float g_y  [(size_t)NROWS * D_INNER];
__device__ float g_st [(size_t)BATCH * NHEADS * NCHUNK * HEADDIM * D_STATE];
__device__ float g_cum[(size_t)BATCH * NHEADS * NCHUNK * LCHUNK];
__device__ __nv_bfloat16 g_uhi [(size_t)NROWS * D_MODEL];
__device__ __nv_bfloat16 g_ulo [(size_t)NROWS * D_MODEL];
__device__ __nv_bfloat16 g_w1hi[(size_t)D_IN_PROJ * D_MODEL];
__device__ __nv_bfloat16 g_w1lo[(size_t)D_IN_PROJ * D_MODEL];
__device__ __nv_bfloat16 g_w2hi[(size_t)D_MODEL * D_INNER];
__device__ __nv_bfloat16 g_w2lo[(size_t)D_MODEL * D_INNER];
__device__ __nv_bfloat16 g_yghi[(size_t)NROWS * D_INNER];
__device__ __nv_bfloat16 g_yglo[(size_t)NROWS * D_INNER];

// ================= helpers =================
__device__ __forceinline__ uint32_t smem_to_u32(const void* p) {
    uint32_t a;
    asm("{ .reg .u64 t; cvta.to.shared.u64 t, %1; cvt.u32.u64 %0, t; }"
        : "=r"(a) : "l"(p));
    return a;
}
__device__ __forceinline__ uint32_t pack_bf16(float lo_elem, float hi_elem) {
    uint32_t r;
    asm("cvt.rn.bf16x2.f32 %0, %1, %2;" : "=r"(r) : "f"(hi_elem), "f"(lo_elem));
    return r;
}
__device__ __forceinline__ void mma_bf16(float* d, const uint32_t* a,
                                         const uint32_t* b) {
    asm volatile(
        "mma.sync.aligned.m16n8k16.row.col.f32.bf16.bf16.f32 "
        "{%0,%1,%2,%3},{%4,%5,%6,%7},{%8,%9},{%0,%1,%2,%3};"
        : "+f"(d[0]), "+f"(d[1]), "+f"(d[2]), "+f"(d[3])
        : "r"(a[0]), "r"(a[1]), "r"(a[2]), "r"(a[3]), "r"(b[0]), "r"(b[1]));
}
__device__ __forceinline__ void ldsm_x4(uint32_t& r0, uint32_t& r1,
                                        uint32_t& r2, uint32_t& r3,
                                        uint32_t addr) {
    asm volatile("ldmatrix.sync.aligned.m8n8.x4.shared.b16 {%0,%1,%2,%3}, [%4];"
                 : "=r"(r0), "=r"(r1), "=r"(r2), "=r"(r3) : "r"(addr));
}
// packed f32x2 ops (sm_100+ base feature)
#define FMA2(d, a, b, c) \
    asm("fma.rn.f32x2 %0, %1, %2, %3;" : "=l"(d) : "l"(a), "l"(b), "l"(c))
#define MUL2(d, a, b) \
    asm("mul.rn.f32x2 %0, %1, %2;" : "=l"(d) : "l"(a), "l"(b))
#define PACK2(d, s) \
    asm("mov.b64 %0, {%1, %1};" : "=l"(d) : "f"(s))
#define UNPACK2(lo, hi, v) \
    asm("mov.b64 {%0, %1}, %2;" : "=f"(lo), "=f"(hi) : "l"(v))

// ================= split kernel: fp32 -> bf16 hi + bf16 lo =================
__global__ __launch_bounds__(256) void split_kernel(
    const float* __restrict__ in, __nv_bfloat16* __restrict__ hi,
    __nv_bfloat16* __restrict__ lo, int n4)
{
    int i = blockIdx.x * 256 + threadIdx.x;
    if (i >= n4) return;
    float4 v = ((const float4*)in)[i];
    uint32_t h01 = pack_bf16(v.x, v.y);
    uint32_t h23 = pack_bf16(v.z, v.w);
    float h0 = __uint_as_float(h01 << 16);
    float h1 = __uint_as_float(h01 & 0xffff0000u);
    float h2 = __uint_as_float(h23 << 16);
    float h3 = __uint_as_float(h23 & 0xffff0000u);
    uint32_t l01 = pack_bf16(v.x - h0, v.y - h1);
    uint32_t l23 = pack_bf16(v.z - h2, v.w - h3);
    ((uint2*)hi)[i] = make_uint2(h01, h23);
    ((uint2*)lo)[i] = make_uint2(l01, l23);
}

// ================= GEMM (bf16x3, ldmatrix + 3-stage cp.async) ==============
#define GB_M 128
#define GB_N 128
#define GB_K 32
#define GB_STAGE 32768
#define GB_SMEM_BYTES (3 * GB_STAGE)   // 98304

__global__ __launch_bounds__(256, 2) void gemm_bf16x3(
    const __nv_bfloat16* __restrict__ Ahi, const __nv_bfloat16* __restrict__ Alo,
    const __nv_bfloat16* __restrict__ Bhi, const __nv_bfloat16* __restrict__ Blo,
    float* __restrict__ C, int M, int N, int K)
{
    extern __shared__ char smem[];
    const uint32_t sbase = smem_to_u32(smem);
    const int tid = threadIdx.x;
    const int bm  = blockIdx.y * GB_M;
    const int bn  = blockIdx.x * GB_N;
    const int nch = K / GB_K;

    const int warp = tid >> 5;
    const int lane = tid & 31;
    const int wm = warp >> 2;
    const int wn = warp & 3;
    const int lr = lane >> 2;
    const int lc = lane & 3;

    float acc[4][4][4];
    #pragma unroll
    for (int mt = 0; mt < 4; mt++)
        #pragma unroll
        for (int nt = 0; nt < 4; nt++)
            #pragma unroll
            for (int q = 0; q < 4; q++) acc[mt][nt][q] = 0.f;

    auto load_stage = [&](int buf, int kt) {
        #pragma unroll
        for (int i = 0; i < 8; i++) {
            int idx = tid + i * 256;
            int cq = idx & 3;
            int r  = (idx >> 2) & 127;
            int t  = idx >> 9;
            uint32_t so = sbase + (uint32_t)buf * GB_STAGE + (uint32_t)t * 8192 +
                          (uint32_t)r * 64 + (uint32_t)((cq ^ ((r >> 1) & 3)) * 16);
            const __nv_bfloat16* g;
            if (t == 0)      g = Ahi + (size_t)(bm + r) * K;
            else if (t == 1) g = Alo + (size_t)(bm + r) * K;
            else {
                int gn = bn + r; if (gn >= N) gn = N - 1;
                g = (t == 2 ? Bhi : Blo) + (size_t)gn * K;
            }
            g += kt + cq * 8;
            asm volatile("cp.async.cg.shared.global [%0], [%1], 16;"
                         :: "r"(so), "l"(g));
        }
        asm volatile("cp.async.commit_group;");
    };

    load_stage(0, 0);
    if (nch > 1) load_stage(1, GB_K);

    const int rowA = wm * 64 + ((lane >> 3) & 1) * 8 + (lane & 7);
    const int rowB = wn * 32 + ((lane >> 4) & 1) * 8 + (lane & 7);
    const int sel  = ((lane & 7) >> 1) & 3;
    const int cAq  = (lane >> 4) & 1;
    const int cBq  = (lane >> 3) & 1;

    for (int c = 0; c < nch; c++) {
        if (c == nch - 1) asm volatile("cp.async.wait_group 0;");
        else              asm volatile("cp.async.wait_group 1;");
        __syncthreads();
        if (c + 2 < nch) load_stage((c + 2) % 3, (c + 2) * GB_K);

        const uint32_t stg = sbase + (uint32_t)(c % 3) * GB_STAGE;
        const uint32_t baseAhi = stg + (uint32_t)rowA * 64;
        const uint32_t baseAlo = baseAhi + 8192;
        const uint32_t baseBhi = stg + 16384 + (uint32_t)rowB * 64;
        const uint32_t baseBlo = baseBhi + 8192;

        #pragma unroll
        for (int ks = 0; ks < 2; ks++) {
            const uint32_t cAo = (uint32_t)(((ks * 2 + cAq) ^ sel) * 16);
            const uint32_t cBo = (uint32_t)(((ks * 2 + cBq) ^ sel) * 16);

            uint32_t bh[4][2], bl[4][2];
            #pragma unroll
            for (int ntp = 0; ntp < 2; ntp++) {
                uint32_t r0, r1, r2, r3;
                ldsm_x4(r0, r1, r2, r3, baseBhi + ntp * 1024 + cBo);
                bh[ntp*2][0] = r0; bh[ntp*2][1] = r1;
                bh[ntp*2+1][0] = r2; bh[ntp*2+1][1] = r3;
                ldsm_x4(r0, r1, r2, r3, baseBlo + ntp * 1024 + cBo);
                bl[ntp*2][0] = r0; bl[ntp*2][1] = r1;
                bl[ntp*2+1][0] = r2; bl[ntp*2+1][1] = r3;
            }
            #pragma unroll
            for (int mt = 0; mt < 4; mt++) {
                uint32_t ah[4], al[4];
                ldsm_x4(ah[0], ah[1], ah[2], ah[3], baseAhi + mt * 1024 + cAo);
                ldsm_x4(al[0], al[1], al[2], al[3], baseAlo + mt * 1024 + cAo);
                #pragma unroll
                for (int nt = 0; nt < 4; nt++) {
                    mma_bf16(acc[mt][nt], ah, bh[nt]);
                    mma_bf16(acc[mt][nt], ah, bl[nt]);
                    mma_bf16(acc[mt][nt], al, bh[nt]);
                }
            }
        }
    }

    #pragma unroll
    for (int mt = 0; mt < 4; mt++) {
        int row = bm + wm * 64 + mt * 16 + lr;
        #pragma unroll
        for (int nt = 0; nt < 4; nt++) {
            int col = bn + wn * 32 + nt * 8 + lc * 2;
            if (col < N) {
                *(float2*)(C + (size_t)row * N + col) =
                    make_float2(acc[mt][nt][0], acc[mt][nt][1]);
                *(float2*)(C + (size_t)(row + 8) * N + col) =
                    make_float2(acc[mt][nt][2], acc[mt][nt][3]);
            }
        }
    }
}

// ---------------- depthwise causal conv (k=4) + bias + SiLU ----------------
__global__ __launch_bounds__(256) void conv_kernel(
    const float* __restrict__ zx, const float* __restrict__ cw,
    const float* __restrict__ cb, float* __restrict__ xbc)
{
    int c = blockIdx.x * 256 + threadIdx.x;
    if (c >= CONV_DIM) return;
    int strip = blockIdx.y;
    int b     = blockIdx.z;
    int l0    = strip * 256;

    float w0 = cw[c*4+0], w1 = cw[c*4+1], w2 = cw[c*4+2], w3 = cw[c*4+3];
    float bias = cb[c];

    size_t colbase = (size_t)D_INNER + c;
    size_t rb = (size_t)b * SEQLEN;

    float xm3 = (l0-3 >= 0) ? zx[(rb + l0-3) * D_IN_PROJ + colbase] : 0.f;
    float xm2 = (l0-2 >= 0) ? zx[(rb + l0-2) * D_IN_PROJ + colbase] : 0.f;
    float xm1 = (l0-1 >= 0) ? zx[(rb + l0-1) * D_IN_PROJ + colbase] : 0.f;

    for (int l = l0; l < l0 + 256; l++) {
        float xv = zx[(rb + l) * D_IN_PROJ + colbase];
        float a = bias;
        a = fmaf(w0, xm3, a);
        a = fmaf(w1, xm2, a);
        a = fmaf(w2, xm1, a);
        a = fmaf(w3, xv,  a);
        float sv = a / (1.f + expf(-a));
        xbc[(rb + l) * CONV_DIM + c] = sv;
        xm3 = xm2; xm2 = xm1; xm1 = xv;
    }
}

// ---------------- dt -> softplus -> decay ----------------------------------
__global__ __launch_bounds__(256) void decay_kernel(
    const float* __restrict__ zx, const float* __restrict__ dt_bias,
    const float* __restrict__ A_log, float* __restrict__ dec)
{
    int idx = blockIdx.x * 256 + threadIdx.x;
    if (idx >= NROWS * NHEADS) return;
    int r = idx >> 4;
    int h = idx & 15;
    float raw = zx[(size_t)r * D_IN_PROJ + (D_IN_PROJ - NHEADS) + h] + dt_bias[h];
    float sp  = (raw > 20.f) ? raw : log1pf(expf(raw));
    float A   = -expf(A_log[h]);
    dec[idx]  = expf(sp * A);
}

// ---------------- chunked scan: stage 1 (thread=p, f32x2 math) -------------
// grid (c=NCHUNK, h, b), 128 threads; thread owns full 64-wide state (32 b64).
__global__ __launch_bounds__(128) void scan_local_kernel(
    const float* __restrict__ xbc, const float* __restrict__ dec,
    const float* __restrict__ Dvec, float* __restrict__ yout,
    float* __restrict__ states, float* __restrict__ cumout)
{
    const int c = blockIdx.x;
    const int h = blockIdx.y;
    const int b = blockIdx.z;
    const int p = threadIdx.x;

    __shared__ __align__(16) float sx [2][SBLK][128];
    __shared__ __align__(16) float sBC[2][SBLK][128];
    __shared__ __align__(16) float sdec[2][SBLK];

    unsigned long long s2[32];
    #pragma unroll
    for (int q = 0; q < 32; q++) s2[q] = 0ull;

    const float Dh = Dvec[h];
    const size_t base = (size_t)b * SEQLEN + (size_t)c * LCHUNK;
    const int xcol = h * HEADDIM;
    const size_t cumbase = (size_t)(((b * NHEADS + h) * NCHUNK) + c) * LCHUNK;

    const uint32_t sx_a   = smem_to_u32(sx);
    const uint32_t sbc_a  = smem_to_u32(sBC);
    const uint32_t sdec_a = smem_to_u32(sdec);

    auto stage = [&](int buf, int l0) {
        #pragma unroll
        for (int i = 0; i < 8; i++) {
            int idx = p + i * 128;          // 0..1023
            int stp = idx >> 6;             // step 0..15
            int q   = idx & 63;
            size_t row = (base + l0 + stp) * CONV_DIM;
            const float* src;
            uint32_t dst;
            if (q < 32) {
                src = xbc + row + xcol + q * 4;
                dst = sx_a + (uint32_t)((buf * SBLK + stp) * 128 + q * 4) * 4;
            } else {
                src = xbc + row + D_INNER + (q - 32) * 4;
                dst = sbc_a + (uint32_t)((buf * SBLK + stp) * 128 + (q - 32) * 4) * 4;
            }
            asm volatile("cp.async.cg.shared.global [%0], [%1], 16;"
                         :: "r"(dst), "l"(src));
        }
        if (p < SBLK) {
            const float* src = dec + (base + l0 + p) * NHEADS + h;
            uint32_t dst = sdec_a + (uint32_t)(buf * SBLK + p) * 4;
            asm volatile("cp.async.ca.shared.global [%0], [%1], 4;"
                         :: "r"(dst), "l"(src));
        }
        asm volatile("cp.async.commit_group;");
    };

    stage(0, 0);
    stage(1, SBLK);

    float cum = 1.f;

    for (int blk = 0; blk < NBLK; blk++) {
        if (blk >= NBLK - 2) asm volatile("cp.async.wait_group 0;");
        else                 asm volatile("cp.async.wait_group 1;");
        __syncthreads();
        const int cur = blk & 1;
        const int l0 = blk * SBLK;

        #pragma unroll 4
        for (int j = 0; j < SBLK; j++) {
            const float dcy = sdec[cur][j];
            const float xv  = sx[cur][j][p];
            unsigned long long dpack, xpack;
            PACK2(dpack, dcy);
            PACK2(xpack, xv);
            const ulonglong2* B2 = (const ulonglong2*)&sBC[cur][j][0];
            const ulonglong2* C2 = (const ulonglong2*)&sBC[cur][j][64];
            unsigned long long ya = 0ull, yb = 0ull;
            #pragma unroll
            for (int q = 0; q < 16; q++) {
                ulonglong2 bv = B2[q];
                ulonglong2 cv = C2[q];
                unsigned long long t0, t1;
                MUL2(t0, bv.x, xpack);
                FMA2(s2[2*q],   s2[2*q],   dpack, t0);
                FMA2(ya, s2[2*q],   cv.x, ya);
                MUL2(t1, bv.y, xpack);
                FMA2(s2[2*q+1], s2[2*q+1], dpack, t1);
                FMA2(yb, s2[2*q+1], cv.y, yb);
            }
            float ya0, ya1, yb0, yb1;
            UNPACK2(ya0, ya1, ya);
            UNPACK2(yb0, yb1, yb);
            float y = (ya0 + ya1) + (yb0 + yb1);
            yout[(base + l0 + j) * D_INNER + xcol + p] = fmaf(Dh, xv, y);
            if (p == 0) {
                cum *= dcy;
                cumout[cumbase + l0 + j] = cum;
            }
        }
        __syncthreads();
        if (blk + 2 < NBLK) stage(cur, (blk + 2) * SBLK);
    }

    float* st = states +
        ((size_t)(((b * NHEADS + h) * NCHUNK) + c) * HEADDIM + p) * D_STATE;
    #pragma unroll
    for (int q = 0; q < 16; q++) {
        ulonglong2 v;
        v.x = s2[2*q];
        v.y = s2[2*q+1];
        *(ulonglong2*)(st + q * 4) = v;
    }
}

// ---------------- chunked scan: stage 2 (combine across chunks) ------------
__global__ __launch_bounds__(256) void scan_combine_kernel(
    float* __restrict__ states, const float* __restrict__ cum)
{
    const int h = blockIdx.x;
    const int b = blockIdx.y;
    const int tid = threadIdx.x;

    __shared__ float dprod[NCHUNK];
    if (tid < NCHUNK)
        dprod[tid] = cum[(size_t)(((b * NHEADS + h) * NCHUNK) + tid) * LCHUNK + LCHUNK - 1];
    __syncthreads();

    const size_t chunk_stride = (size_t)HEADDIM * D_STATE;
    float* base = states + (size_t)((b * NHEADS + h) * NCHUNK) * chunk_stride;

    float4 e[8];
    #pragma unroll
    for (int k = 0; k < 8; k++) e[k] = make_float4(0.f, 0.f, 0.f, 0.f);

    for (int c = 0; c < NCHUNK; c++) {
        float d = dprod[c];
        float4* p = (float4*)(base + c * chunk_stride);
        #pragma unroll
        for (int k = 0; k < 8; k++) {
            int idx = tid + k * 256;
            float4 sl = p[idx];
            p[idx] = e[k];
            e[k].x = fmaf(e[k].x, d, sl.x);
            e[k].y = fmaf(e[k].y, d, sl.y);
            e[k].z = fmaf(e[k].z, d, sl.z);
            e[k].w = fmaf(e[k].w, d, sl.w);
        }
    }
}

// ---------------- chunked scan: stage 3 (cross-chunk correction, f32x2) ----
__global__ __launch_bounds__(128) void scan_fix_kernel(
    const float* __restrict__ states, const float* __restrict__ cum,
    const float* __restrict__ xbc, float* __restrict__ yout)
{
    const int c = blockIdx.x;
    if (c == 0) return;
    const int h = blockIdx.y;
    const int b = blockIdx.z;
    const int p = threadIdx.x;

    ulonglong2 ent2[16];
    const float* st = states +
        ((size_t)(((b * NHEADS + h) * NCHUNK) + c) * HEADDIM + p) * D_STATE;
    #pragma unroll
    for (int q = 0; q < 16; q++) ent2[q] = *(const ulonglong2*)(st + q * 4);

    const size_t base = (size_t)b * SEQLEN + (size_t)c * LCHUNK;
    const size_t cumbase = (size_t)(((b * NHEADS + h) * NCHUNK) + c) * LCHUNK;
    const int ycol = h * HEADDIM + p;

    for (int l = 0; l < LCHUNK; l++) {
        const float* Cg = xbc + (base + l) * CONV_DIM + D_INNER + 64;
        unsigned long long accA = 0ull, accB = 0ull;
        #pragma unroll
        for (int q = 0; q < 16; q++) {
            ulonglong2 cv = __ldg((const ulonglong2*)(Cg + q * 4));
            FMA2(accA, ent2[q].x, cv.x, accA);
            FMA2(accB, ent2[q].y, cv.y, accB);
        }
        float a0, a1, b0, b1;
        UNPACK2(a0, a1, accA);
        UNPACK2(b0, b1, accB);
        float dot = (a0 + a1) + (b0 + b1);
        float cm = __ldg(cum + cumbase + l);
        float* yp = yout + (base + l) * D_INNER + ycol;
        *yp = fmaf(cm, dot, *yp);
    }
}

// ---------------- RMSNorm + gate, fused bf16 split output ------------------
__global__ __launch_bounds__(256) void rms_gate_kernel(
    const float* __restrict__ y, const float* __restrict__ zx,
    const float* __restrict__ rmsw,
    __nv_bfloat16* __restrict__ ygh, __nv_bfloat16* __restrict__ ygl)
{
    int r = blockIdx.x;
    const float*  yr = y  + (size_t)r * D_INNER;
    const float*  zr = zx + (size_t)r * D_IN_PROJ;
    const float4* y4 = (const float4*)yr;

    int tid = threadIdx.x;
    float ss = 0.f;
    #pragma unroll
    for (int i = 0; i < 2; i++) {
        float4 v = y4[tid + i * 256];
        ss += v.x*v.x + v.y*v.y + v.z*v.z + v.w*v.w;
    }
    #pragma unroll
    for (int o = 16; o > 0; o >>= 1) ss += __shfl_xor_sync(0xffffffffu, ss, o);
    __shared__ float red[8];
    if ((tid & 31) == 0) red[tid >> 5] = ss;
    __syncthreads();
    if (tid == 0) {
        float t = 0.f;
        #pragma unroll
        for (int i = 0; i < 8; i++) t += red[i];
        red[0] = rsqrtf(t * (1.f / D_INNER) + RMS_EPS);
    }
    __syncthreads();
    float rs = red[0];

    const float4* z4 = (const float4*)zr;
    const float4* w4 = (const float4*)rmsw;
    uint2* gh = (uint2*)(ygh + (size_t)r * D_INNER);
    uint2* gl = (uint2*)(ygl + (size_t)r * D_INNER);
    #pragma unroll
    for (int i = 0; i < 2; i++) {
        int c = tid + i * 256;
        float4 v = y4[c];
        float4 z = z4[c];
        float4 w = w4[c];
        float4 o;
        o.x = v.x * rs * w.x * (1.f / (1.f + expf(-z.x)));
        o.y = v.y * rs * w.y * (1.f / (1.f + expf(-z.y)));
        o.z = v.z * rs * w.z * (1.f / (1.f + expf(-z.z)));
        o.w = v.w * rs * w.w * (1.f / (1.f + expf(-z.w)));
        uint32_t h01 = pack_bf16(o.x, o.y);
        uint32_t h23 = pack_bf16(o.z, o.w);
        float h0 = __uint_as_float(h01 << 16);
        float h1 = __uint_as_float(h01 & 0xffff0000u);
        float h2 = __uint_as_float(h23 << 16);
        float h3 = __uint_as_float(h23 & 0xffff0000u);
        gh[c] = make_uint2(h01, h23);
        gl[c] = make_uint2(pack_bf16(o.x - h0, o.y - h1),
                           pack_bf16(o.z - h2, o.w - h3));
    }
}

// ---------------- launcher -------------------------------------------------
extern "C" void kernel_launch(void* const* d_in, const int* in_sizes, int n_in,
                              void* d_out, int out_size)
{
    const float* u        = (const float*)d_in[0];
    const float* in_proj  = (const float*)d_in[1];
    const float* conv_w   = (const float*)d_in[2];
    const float* conv_b   = (const float*)d_in[3];
    const float* dt_bias  = (const float*)d_in[4];
    const float* A_log    = (const float*)d_in[5];
    const float* Dv       = (const float*)d_in[6];
    const float* rms_w    = (const float*)d_in[7];
    const float* out_w    = (const float*)d_in[8];
    float* out = (float*)d_out;

    float *zx, *xbc, *dec, *y, *st, *cum;
    __nv_bfloat16 *uhi, *ulo, *w1hi, *w1lo, *w2hi, *w2lo, *yghi, *yglo;
    cudaGetSymbolAddress((void**)&zx,  g_zx);
    cudaGetSymbolAddress((void**)&xbc, g_xbc);
    cudaGetSymbolAddress((void**)&dec, g_dec);
    cudaGetSymbolAddress((void**)&y,   g_y);
    cudaGetSymbolAddress((void**)&st,  g_st);
    cudaGetSymbolAddress((void**)&cum, g_cum);
    cudaGetSymbolAddress((void**)&uhi,  g_uhi);
    cudaGetSymbolAddress((void**)&ulo,  g_ulo);
    cudaGetSymbolAddress((void**)&w1hi, g_w1hi);
    cudaGetSymbolAddress((void**)&w1lo, g_w1lo);
    cudaGetSymbolAddress((void**)&w2hi, g_w2hi);
    cudaGetSymbolAddress((void**)&w2lo, g_w2lo);
    cudaGetSymbolAddress((void**)&yghi, g_yghi);
    cudaGetSymbolAddress((void**)&yglo, g_yglo);

    cudaFuncSetAttribute(gemm_bf16x3,
        cudaFuncAttributeMaxDynamicSharedMemorySize, GB_SMEM_BYTES);

    // 0) split fp32 operands into bf16 hi/lo
    {
        int n4u = NROWS * D_MODEL / 4;
        split_kernel<<<(n4u + 255) / 256, 256>>>(u, uhi, ulo, n4u);
        int n4w1 = D_IN_PROJ * D_MODEL / 4;
        split_kernel<<<(n4w1 + 255) / 256, 256>>>(in_proj, w1hi, w1lo, n4w1);
        int n4w2 = D_MODEL * D_INNER / 4;
        split_kernel<<<(n4w2 + 255) / 256, 256>>>(out_w, w2hi, w2lo, n4w2);
    }
    // 1) in_proj GEMM
    {
        dim3 grid((D_IN_PROJ + GB_N - 1) / GB_N, NROWS / GB_M);
        gemm_bf16x3<<<grid, 256, GB_SMEM_BYTES>>>(uhi, ulo, w1hi, w1lo, zx,
                                                  NROWS, D_IN_PROJ, D_MODEL);
    }
    // 2) conv + silu
    {
        dim3 grid((CONV_DIM + 255) / 256, SEQLEN / 256, BATCH);
        conv_kernel<<<grid, 256>>>(zx, conv_w, conv_b, xbc);
    }
    // 3) decay precompute
    decay_kernel<<<(NROWS * NHEADS + 255) / 256, 256>>>(zx, dt_bias, A_log, dec);
    // 4) chunked SSM scan
    {
        dim3 grid(NCHUNK, NHEADS, BATCH);
        scan_local_kernel<<<grid, 128>>>(xbc, dec, Dv, y, st, cum);
    }
    {
        dim3 grid(NHEADS, BATCH);
        scan_combine_kernel<<<grid, 256>>>(st, cum);
    }
    {
        dim3 grid(NCHUNK, NHEADS, BATCH);
        scan_fix_kernel<<<grid, 128>>>(st, cum, xbc, y);
    }
    // 5) rmsnorm + gate (+ bf16 split)
    rms_gate_kernel<<<NROWS, 256>>>(y, zx, rms_w, yghi, yglo);
    // 6) out_proj GEMM
    {
        dim3 grid(D_MODEL / GB_N, NROWS / GB_M);
        gemm_bf16x3<<<grid, 256, GB_SMEM_BYTES>>>(yghi, yglo, w2hi, w2lo, out,
                                                  NROWS, D_MODEL, D_INNER);
    }
}

// round 9
// speedup vs baseline: 1.2388x; 1.2048x over previous
#include <cuda_runtime.h>
#include <cuda_bf16.h>
#include <cstdint>
#include <math.h>

// ---------------- problem constants ----------------
#define D_MODEL   1024
#define D_INNER   2048
#define D_STATE   64
#define HEADDIM   128
#define NHEADS    16
#define D_CONV    4
#define CONV_DIM  2176
#define D_IN_PROJ 4240
#define BATCH     2
#define SEQLEN    4096
#define NROWS     (BATCH*SEQLEN)  // 8192
#define RMS_EPS   1e-5f

#define LCHUNK    128
#define NCHUNK    (SEQLEN/LCHUNK)   // 32
#define SBLK      16                // staging block (steps)
#define NBLK      (LCHUNK/SBLK)     // 8

// ---------------- scratch ----------------
__device__ float g_zx [(size_t)NROWS * D_IN_PROJ];
__device__ float g_xbc[(size_t)NROWS * CONV_DIM];
__device__ float g_dec[(size_t)NROWS * NHEADS];
__device__ float g_y  [(size_t)NROWS * D_INNER];
__device__ float g_st [(size_t)BATCH * NHEADS * NCHUNK * HEADDIM * D_STATE];
__device__ float g_cum[(size_t)BATCH * NHEADS * NCHUNK * LCHUNK];
__device__ __nv_bfloat16 g_uhi [(size_t)NROWS * D_MODEL];
__device__ __nv_bfloat16 g_ulo [(size_t)NROWS * D_MODEL];
__device__ __nv_bfloat16 g_w1hi[(size_t)D_IN_PROJ * D_MODEL];
__device__ __nv_bfloat16 g_w1lo[(size_t)D_IN_PROJ * D_MODEL];
__device__ __nv_bfloat16 g_w2hi[(size_t)D_MODEL * D_INNER];
__device__ __nv_bfloat16 g_w2lo[(size_t)D_MODEL * D_INNER];
__device__ __nv_bfloat16 g_yghi[(size_t)NROWS * D_INNER];
__device__ __nv_bfloat16 g_yglo[(size_t)NROWS * D_INNER];

// ================= helpers =================
__device__ __forceinline__ uint32_t smem_to_u32(const void* p) {
    uint32_t a;
    asm("{ .reg .u64 t; cvta.to.shared.u64 t, %1; cvt.u32.u64 %0, t; }"
        : "=r"(a) : "l"(p));
    return a;
}
__device__ __forceinline__ uint32_t pack_bf16(float lo_elem, float hi_elem) {
    uint32_t r;
    asm("cvt.rn.bf16x2.f32 %0, %1, %2;" : "=r"(r) : "f"(hi_elem), "f"(lo_elem));
    return r;
}
__device__ __forceinline__ void mma_bf16(float* d, const uint32_t* a,
                                         const uint32_t* b) {
    asm volatile(
        "mma.sync.aligned.m16n8k16.row.col.f32.bf16.bf16.f32 "
        "{%0,%1,%2,%3},{%4,%5,%6,%7},{%8,%9},{%0,%1,%2,%3};"
        : "+f"(d[0]), "+f"(d[1]), "+f"(d[2]), "+f"(d[3])
        : "r"(a[0]), "r"(a[1]), "r"(a[2]), "r"(a[3]), "r"(b[0]), "r"(b[1]));
}
__device__ __forceinline__ void ldsm_x4(uint32_t& r0, uint32_t& r1,
                                        uint32_t& r2, uint32_t& r3,
                                        uint32_t addr) {
    asm volatile("ldmatrix.sync.aligned.m8n8.x4.shared.b16 {%0,%1,%2,%3}, [%4];"
                 : "=r"(r0), "=r"(r1), "=r"(r2), "=r"(r3) : "r"(addr));
}
// packed f32x2 ops (sm_100+ base feature)
#define FMA2(d, a, b, c) \
    asm("fma.rn.f32x2 %0, %1, %2, %3;" : "=l"(d) : "l"(a), "l"(b), "l"(c))
#define MUL2(d, a, b) \
    asm("mul.rn.f32x2 %0, %1, %2;" : "=l"(d) : "l"(a), "l"(b))
#define PACK2(d, s) \
    asm("mov.b64 %0, {%1, %1};" : "=l"(d) : "f"(s))
#define UNPACK2(lo, hi, v) \
    asm("mov.b64 {%0, %1}, %2;" : "=f"(lo), "=f"(hi) : "l"(v))

// ================= split kernel: fp32 -> bf16 hi + bf16 lo =================
__global__ __launch_bounds__(256) void split_kernel(
    const float* __restrict__ in, __nv_bfloat16* __restrict__ hi,
    __nv_bfloat16* __restrict__ lo, int n4)
{
    int i = blockIdx.x * 256 + threadIdx.x;
    if (i >= n4) return;
    float4 v = ((const float4*)in)[i];
    uint32_t h01 = pack_bf16(v.x, v.y);
    uint32_t h23 = pack_bf16(v.z, v.w);
    float h0 = __uint_as_float(h01 << 16);
    float h1 = __uint_as_float(h01 & 0xffff0000u);
    float h2 = __uint_as_float(h23 << 16);
    float h3 = __uint_as_float(h23 & 0xffff0000u);
    uint32_t l01 = pack_bf16(v.x - h0, v.y - h1);
    uint32_t l23 = pack_bf16(v.z - h2, v.w - h3);
    ((uint2*)hi)[i] = make_uint2(h01, h23);
    ((uint2*)lo)[i] = make_uint2(l01, l23);
}

// ================= GEMM (bf16x3, ldmatrix + 3-stage cp.async) ==============
#define GB_M 128
#define GB_N 128
#define GB_K 32
#define GB_STAGE 32768
#define GB_SMEM_BYTES (3 * GB_STAGE)   // 98304

__global__ __launch_bounds__(256, 2) void gemm_bf16x3(
    const __nv_bfloat16* __restrict__ Ahi, const __nv_bfloat16* __restrict__ Alo,
    const __nv_bfloat16* __restrict__ Bhi, const __nv_bfloat16* __restrict__ Blo,
    float* __restrict__ C, int M, int N, int K)
{
    extern __shared__ char smem[];
    const uint32_t sbase = smem_to_u32(smem);
    const int tid = threadIdx.x;
    const int bm  = blockIdx.y * GB_M;
    const int bn  = blockIdx.x * GB_N;
    const int nch = K / GB_K;

    const int warp = tid >> 5;
    const int lane = tid & 31;
    const int wm = warp >> 2;
    const int wn = warp & 3;
    const int lr = lane >> 2;
    const int lc = lane & 3;

    float acc[4][4][4];
    #pragma unroll
    for (int mt = 0; mt < 4; mt++)
        #pragma unroll
        for (int nt = 0; nt < 4; nt++)
            #pragma unroll
            for (int q = 0; q < 4; q++) acc[mt][nt][q] = 0.f;

    auto load_stage = [&](int buf, int kt) {
        #pragma unroll
        for (int i = 0; i < 8; i++) {
            int idx = tid + i * 256;
            int cq = idx & 3;
            int r  = (idx >> 2) & 127;
            int t  = idx >> 9;
            uint32_t so = sbase + (uint32_t)buf * GB_STAGE + (uint32_t)t * 8192 +
                          (uint32_t)r * 64 + (uint32_t)((cq ^ ((r >> 1) & 3)) * 16);
            const __nv_bfloat16* g;
            if (t == 0)      g = Ahi + (size_t)(bm + r) * K;
            else if (t == 1) g = Alo + (size_t)(bm + r) * K;
            else {
                int gn = bn + r; if (gn >= N) gn = N - 1;
                g = (t == 2 ? Bhi : Blo) + (size_t)gn * K;
            }
            g += kt + cq * 8;
            asm volatile("cp.async.cg.shared.global [%0], [%1], 16;"
                         :: "r"(so), "l"(g));
        }
        asm volatile("cp.async.commit_group;");
    };

    load_stage(0, 0);
    if (nch > 1) load_stage(1, GB_K);

    const int rowA = wm * 64 + ((lane >> 3) & 1) * 8 + (lane & 7);
    const int rowB = wn * 32 + ((lane >> 4) & 1) * 8 + (lane & 7);
    const int sel  = ((lane & 7) >> 1) & 3;
    const int cAq  = (lane >> 4) & 1;
    const int cBq  = (lane >> 3) & 1;

    for (int c = 0; c < nch; c++) {
        if (c == nch - 1) asm volatile("cp.async.wait_group 0;");
        else              asm volatile("cp.async.wait_group 1;");
        __syncthreads();
        if (c + 2 < nch) load_stage((c + 2) % 3, (c + 2) * GB_K);

        const uint32_t stg = sbase + (uint32_t)(c % 3) * GB_STAGE;
        const uint32_t baseAhi = stg + (uint32_t)rowA * 64;
        const uint32_t baseAlo = baseAhi + 8192;
        const uint32_t baseBhi = stg + 16384 + (uint32_t)rowB * 64;
        const uint32_t baseBlo = baseBhi + 8192;

        #pragma unroll
        for (int ks = 0; ks < 2; ks++) {
            const uint32_t cAo = (uint32_t)(((ks * 2 + cAq) ^ sel) * 16);
            const uint32_t cBo = (uint32_t)(((ks * 2 + cBq) ^ sel) * 16);

            uint32_t bh[4][2], bl[4][2];
            #pragma unroll
            for (int ntp = 0; ntp < 2; ntp++) {
                uint32_t r0, r1, r2, r3;
                ldsm_x4(r0, r1, r2, r3, baseBhi + ntp * 1024 + cBo);
                bh[ntp*2][0] = r0; bh[ntp*2][1] = r1;
                bh[ntp*2+1][0] = r2; bh[ntp*2+1][1] = r3;
                ldsm_x4(r0, r1, r2, r3, baseBlo + ntp * 1024 + cBo);
                bl[ntp*2][0] = r0; bl[ntp*2][1] = r1;
                bl[ntp*2+1][0] = r2; bl[ntp*2+1][1] = r3;
            }
            #pragma unroll
            for (int mt = 0; mt < 4; mt++) {
                uint32_t ah[4], al[4];
                ldsm_x4(ah[0], ah[1], ah[2], ah[3], baseAhi + mt * 1024 + cAo);
                ldsm_x4(al[0], al[1], al[2], al[3], baseAlo + mt * 1024 + cAo);
                #pragma unroll
                for (int nt = 0; nt < 4; nt++) {
                    mma_bf16(acc[mt][nt], ah, bh[nt]);
                    mma_bf16(acc[mt][nt], ah, bl[nt]);
                    mma_bf16(acc[mt][nt], al, bh[nt]);
                }
            }
        }
    }

    #pragma unroll
    for (int mt = 0; mt < 4; mt++) {
        int row = bm + wm * 64 + mt * 16 + lr;
        #pragma unroll
        for (int nt = 0; nt < 4; nt++) {
            int col = bn + wn * 32 + nt * 8 + lc * 2;
            if (col < N) {
                *(float2*)(C + (size_t)row * N + col) =
                    make_float2(acc[mt][nt][0], acc[mt][nt][1]);
                *(float2*)(C + (size_t)(row + 8) * N + col) =
                    make_float2(acc[mt][nt][2], acc[mt][nt][3]);
            }
        }
    }
}

// ---------------- depthwise causal conv (k=4) + bias + SiLU ----------------
__global__ __launch_bounds__(256) void conv_kernel(
    const float* __restrict__ zx, const float* __restrict__ cw,
    const float* __restrict__ cb, float* __restrict__ xbc)
{
    int c = blockIdx.x * 256 + threadIdx.x;
    if (c >= CONV_DIM) return;
    int strip = blockIdx.y;
    int b     = blockIdx.z;
    int l0    = strip * 256;

    float w0 = cw[c*4+0], w1 = cw[c*4+1], w2 = cw[c*4+2], w3 = cw[c*4+3];
    float bias = cb[c];

    size_t colbase = (size_t)D_INNER + c;
    size_t rb = (size_t)b * SEQLEN;

    float xm3 = (l0-3 >= 0) ? zx[(rb + l0-3) * D_IN_PROJ + colbase] : 0.f;
    float xm2 = (l0-2 >= 0) ? zx[(rb + l0-2) * D_IN_PROJ + colbase] : 0.f;
    float xm1 = (l0-1 >= 0) ? zx[(rb + l0-1) * D_IN_PROJ + colbase] : 0.f;

    for (int l = l0; l < l0 + 256; l++) {
        float xv = zx[(rb + l) * D_IN_PROJ + colbase];
        float a = bias;
        a = fmaf(w0, xm3, a);
        a = fmaf(w1, xm2, a);
        a = fmaf(w2, xm1, a);
        a = fmaf(w3, xv,  a);
        float sv = a / (1.f + expf(-a));
        xbc[(rb + l) * CONV_DIM + c] = sv;
        xm3 = xm2; xm2 = xm1; xm1 = xv;
    }
}

// ---------------- dt -> softplus -> decay ----------------------------------
__global__ __launch_bounds__(256) void decay_kernel(
    const float* __restrict__ zx, const float* __restrict__ dt_bias,
    const float* __restrict__ A_log, float* __restrict__ dec)
{
    int idx = blockIdx.x * 256 + threadIdx.x;
    if (idx >= NROWS * NHEADS) return;
    int r = idx >> 4;
    int h = idx & 15;
    float raw = zx[(size_t)r * D_IN_PROJ + (D_IN_PROJ - NHEADS) + h] + dt_bias[h];
    float sp  = (raw > 20.f) ? raw : log1pf(expf(raw));
    float A   = -expf(A_log[h]);
    dec[idx]  = expf(sp * A);
}

// ---------------- chunked scan: stage 1 (thread=p, f32x2 math) -------------
__global__ __launch_bounds__(128) void scan_local_kernel(
    const float* __restrict__ xbc, const float* __restrict__ dec,
    const float* __restrict__ Dvec, float* __restrict__ yout,
    float* __restrict__ states, float* __restrict__ cumout)
{
    const int c = blockIdx.x;
    const int h = blockIdx.y;
    const int b = blockIdx.z;
    const int p = threadIdx.x;

    __shared__ __align__(16) float sx [2][SBLK][128];
    __shared__ __align__(16) float sBC[2][SBLK][128];
    __shared__ __align__(16) float sdec[2][SBLK];

    unsigned long long s2[32];
    #pragma unroll
    for (int q = 0; q < 32; q++) s2[q] = 0ull;

    const float Dh = Dvec[h];
    const size_t base = (size_t)b * SEQLEN + (size_t)c * LCHUNK;
    const int xcol = h * HEADDIM;
    const size_t cumbase = (size_t)(((b * NHEADS + h) * NCHUNK) + c) * LCHUNK;

    const uint32_t sx_a   = smem_to_u32(sx);
    const uint32_t sbc_a  = smem_to_u32(sBC);
    const uint32_t sdec_a = smem_to_u32(sdec);

    auto stage = [&](int buf, int l0) {
        #pragma unroll
        for (int i = 0; i < 8; i++) {
            int idx = p + i * 128;
            int stp = idx >> 6;
            int q   = idx & 63;
            size_t row = (base + l0 + stp) * CONV_DIM;
            const float* src;
            uint32_t dst;
            if (q < 32) {
                src = xbc + row + xcol + q * 4;
                dst = sx_a + (uint32_t)((buf * SBLK + stp) * 128 + q * 4) * 4;
            } else {
                src = xbc + row + D_INNER + (q - 32) * 4;
                dst = sbc_a + (uint32_t)((buf * SBLK + stp) * 128 + (q - 32) * 4) * 4;
            }
            asm volatile("cp.async.cg.shared.global [%0], [%1], 16;"
                         :: "r"(dst), "l"(src));
        }
        if (p < SBLK) {
            const float* src = dec + (base + l0 + p) * NHEADS + h;
            uint32_t dst = sdec_a + (uint32_t)(buf * SBLK + p) * 4;
            asm volatile("cp.async.ca.shared.global [%0], [%1], 4;"
                         :: "r"(dst), "l"(src));
        }
        asm volatile("cp.async.commit_group;");
    };

    stage(0, 0);
    stage(1, SBLK);

    float cum = 1.f;

    for (int blk = 0; blk < NBLK; blk++) {
        if (blk >= NBLK - 2) asm volatile("cp.async.wait_group 0;");
        else                 asm volatile("cp.async.wait_group 1;");
        __syncthreads();
        const int cur = blk & 1;
        const int l0 = blk * SBLK;

        #pragma unroll 4
        for (int j = 0; j < SBLK; j++) {
            const float dcy = sdec[cur][j];
            const float xv  = sx[cur][j][p];
            unsigned long long dpack, xpack;
            PACK2(dpack, dcy);
            PACK2(xpack, xv);
            const ulonglong2* B2 = (const ulonglong2*)&sBC[cur][j][0];
            const ulonglong2* C2 = (const ulonglong2*)&sBC[cur][j][64];
            unsigned long long ya = 0ull, yb = 0ull;
            #pragma unroll
            for (int q = 0; q < 16; q++) {
                ulonglong2 bv = B2[q];
                ulonglong2 cv = C2[q];
                unsigned long long t0, t1;
                MUL2(t0, bv.x, xpack);
                FMA2(s2[2*q],   s2[2*q],   dpack, t0);
                FMA2(ya, s2[2*q],   cv.x, ya);
                MUL2(t1, bv.y, xpack);
                FMA2(s2[2*q+1], s2[2*q+1], dpack, t1);
                FMA2(yb, s2[2*q+1], cv.y, yb);
            }
            float ya0, ya1, yb0, yb1;
            UNPACK2(ya0, ya1, ya);
            UNPACK2(yb0, yb1, yb);
            float y = (ya0 + ya1) + (yb0 + yb1);
            yout[(base + l0 + j) * D_INNER + xcol + p] = fmaf(Dh, xv, y);
            if (p == 0) {
                cum *= dcy;
                cumout[cumbase + l0 + j] = cum;
            }
        }
        __syncthreads();
        if (blk + 2 < NBLK) stage(cur, (blk + 2) * SBLK);
    }

    float* st = states +
        ((size_t)(((b * NHEADS + h) * NCHUNK) + c) * HEADDIM + p) * D_STATE;
    #pragma unroll
    for (int q = 0; q < 16; q++) {
        ulonglong2 v;
        v.x = s2[2*q];
        v.y = s2[2*q+1];
        *(ulonglong2*)(st + q * 4) = v;
    }
}

// ---------------- chunked scan: stage 2 (combine across chunks) ------------
__global__ __launch_bounds__(256) void scan_combine_kernel(
    float* __restrict__ states, const float* __restrict__ cum)
{
    const int h = blockIdx.x;
    const int b = blockIdx.y;
    const int tid = threadIdx.x;

    __shared__ float dprod[NCHUNK];
    if (tid < NCHUNK)
        dprod[tid] = cum[(size_t)(((b * NHEADS + h) * NCHUNK) + tid) * LCHUNK + LCHUNK - 1];
    __syncthreads();

    const size_t chunk_stride = (size_t)HEADDIM * D_STATE;
    float* base = states + (size_t)((b * NHEADS + h) * NCHUNK) * chunk_stride;

    float4 e[8];
    #pragma unroll
    for (int k = 0; k < 8; k++) e[k] = make_float4(0.f, 0.f, 0.f, 0.f);

    for (int c = 0; c < NCHUNK; c++) {
        float d = dprod[c];
        float4* p = (float4*)(base + c * chunk_stride);
        #pragma unroll
        for (int k = 0; k < 8; k++) {
            int idx = tid + k * 256;
            float4 sl = p[idx];
            p[idx] = e[k];
            e[k].x = fmaf(e[k].x, d, sl.x);
            e[k].y = fmaf(e[k].y, d, sl.y);
            e[k].z = fmaf(e[k].z, d, sl.z);
            e[k].w = fmaf(e[k].w, d, sl.w);
        }
    }
}

// ---------------- chunked scan: stage 3 (smem-staged, f32x2) ---------------
// grid (c=NCHUNK, h, b), 128 threads. C rows + cum staged via cp.async;
// inner loop is broadcast LDS.128 instead of redundant per-thread LDG.
__global__ __launch_bounds__(128) void scan_fix_kernel(
    const float* __restrict__ states, const float* __restrict__ cum,
    const float* __restrict__ xbc, float* __restrict__ yout)
{
    const int c = blockIdx.x;
    if (c == 0) return;
    const int h = blockIdx.y;
    const int b = blockIdx.z;
    const int p = threadIdx.x;

    __shared__ __align__(16) float sC  [2][SBLK][64];
    __shared__ __align__(16) float scum[2][SBLK];

    ulonglong2 ent2[16];
    const float* st = states +
        ((size_t)(((b * NHEADS + h) * NCHUNK) + c) * HEADDIM + p) * D_STATE;
    #pragma unroll
    for (int q = 0; q < 16; q++) ent2[q] = *(const ulonglong2*)(st + q * 4);

    const size_t base = (size_t)b * SEQLEN + (size_t)c * LCHUNK;
    const size_t cumbase = (size_t)(((b * NHEADS + h) * NCHUNK) + c) * LCHUNK;
    const int ycol = h * HEADDIM + p;

    const uint32_t sC_a   = smem_to_u32(sC);
    const uint32_t scum_a = smem_to_u32(scum);

    // stage SBLK C rows (16x64 floats = 256 float4) + SBLK cum values
    auto stage = [&](int buf, int l0) {
        #pragma unroll
        for (int i = 0; i < 2; i++) {
            int idx = p + i * 128;          // 0..255
            int stp = idx >> 4;             // step 0..15
            int q   = idx & 15;             // float4 within 64-float row
            const float* src = xbc + (base + l0 + stp) * CONV_DIM + D_INNER + 64 + q * 4;
            uint32_t dst = sC_a + (uint32_t)((buf * SBLK + stp) * 64 + q * 4) * 4;
            asm volatile("cp.async.cg.shared.global [%0], [%1], 16;"
                         :: "r"(dst), "l"(src));
        }
        if (p < SBLK) {
            const float* src = cum + cumbase + l0 + p;
            uint32_t dst = scum_a + (uint32_t)(buf * SBLK + p) * 4;
            asm volatile("cp.async.ca.shared.global [%0], [%1], 4;"
                         :: "r"(dst), "l"(src));
        }
        asm volatile("cp.async.commit_group;");
    };

    stage(0, 0);
    stage(1, SBLK);

    for (int blk = 0; blk < NBLK; blk++) {
        if (blk >= NBLK - 2) asm volatile("cp.async.wait_group 0;");
        else                 asm volatile("cp.async.wait_group 1;");
        __syncthreads();
        const int cur = blk & 1;
        const int l0 = blk * SBLK;

        #pragma unroll 4
        for (int j = 0; j < SBLK; j++) {
            const ulonglong2* C2 = (const ulonglong2*)&sC[cur][j][0];
            unsigned long long accA = 0ull, accB = 0ull;
            #pragma unroll
            for (int q = 0; q < 16; q++) {
                ulonglong2 cv = C2[q];
                FMA2(accA, ent2[q].x, cv.x, accA);
                FMA2(accB, ent2[q].y, cv.y, accB);
            }
            float a0, a1, b0, b1;
            UNPACK2(a0, a1, accA);
            UNPACK2(b0, b1, accB);
            float dot = (a0 + a1) + (b0 + b1);
            float cm = scum[cur][j];
            float* yp = yout + (base + l0 + j) * D_INNER + ycol;
            *yp = fmaf(cm, dot, *yp);
        }
        __syncthreads();
        if (blk + 2 < NBLK) stage(cur, (blk + 2) * SBLK);
    }
}

// ---------------- RMSNorm + gate, fused bf16 split output ------------------
__global__ __launch_bounds__(256) void rms_gate_kernel(
    const float* __restrict__ y, const float* __restrict__ zx,
    const float* __restrict__ rmsw,
    __nv_bfloat16* __restrict__ ygh, __nv_bfloat16* __restrict__ ygl)
{
    int r = blockIdx.x;
    const float*  yr = y  + (size_t)r * D_INNER;
    const float*  zr = zx + (size_t)r * D_IN_PROJ;
    const float4* y4 = (const float4*)yr;

    int tid = threadIdx.x;
    float ss = 0.f;
    #pragma unroll
    for (int i = 0; i < 2; i++) {
        float4 v = y4[tid + i * 256];
        ss += v.x*v.x + v.y*v.y + v.z*v.z + v.w*v.w;
    }
    #pragma unroll
    for (int o = 16; o > 0; o >>= 1) ss += __shfl_xor_sync(0xffffffffu, ss, o);
    __shared__ float red[8];
    if ((tid & 31) == 0) red[tid >> 5] = ss;
    __syncthreads();
    if (tid == 0) {
        float t = 0.f;
        #pragma unroll
        for (int i = 0; i < 8; i++) t += red[i];
        red[0] = rsqrtf(t * (1.f / D_INNER) + RMS_EPS);
    }
    __syncthreads();
    float rs = red[0];

    const float4* z4 = (const float4*)zr;
    const float4* w4 = (const float4*)rmsw;
    uint2* gh = (uint2*)(ygh + (size_t)r * D_INNER);
    uint2* gl = (uint2*)(ygl + (size_t)r * D_INNER);
    #pragma unroll
    for (int i = 0; i < 2; i++) {
        int c = tid + i * 256;
        float4 v = y4[c];
        float4 z = z4[c];
        float4 w = w4[c];
        float4 o;
        o.x = v.x * rs * w.x * (1.f / (1.f + expf(-z.x)));
        o.y = v.y * rs * w.y * (1.f / (1.f + expf(-z.y)));
        o.z = v.z * rs * w.z * (1.f / (1.f + expf(-z.z)));
        o.w = v.w * rs * w.w * (1.f / (1.f + expf(-z.w)));
        uint32_t h01 = pack_bf16(o.x, o.y);
        uint32_t h23 = pack_bf16(o.z, o.w);
        float h0 = __uint_as_float(h01 << 16);
        float h1 = __uint_as_float(h01 & 0xffff0000u);
        float h2 = __uint_as_float(h23 << 16);
        float h3 = __uint_as_float(h23 & 0xffff0000u);
        gh[c] = make_uint2(h01, h23);
        gl[c] = make_uint2(pack_bf16(o.x - h0, o.y - h1),
                           pack_bf16(o.z - h2, o.w - h3));
    }
}

// ---------------- launcher -------------------------------------------------
extern "C" void kernel_launch(void* const* d_in, const int* in_sizes, int n_in,
                              void* d_out, int out_size)
{
    const float* u        = (const float*)d_in[0];
    const float* in_proj  = (const float*)d_in[1];
    const float* conv_w   = (const float*)d_in[2];
    const float* conv_b   = (const float*)d_in[3];
    const float* dt_bias  = (const float*)d_in[4];
    const float* A_log    = (const float*)d_in[5];
    const float* Dv       = (const float*)d_in[6];
    const float* rms_w    = (const float*)d_in[7];
    const float* out_w    = (const float*)d_in[8];
    float* out = (float*)d_out;

    float *zx, *xbc, *dec, *y, *st, *cum;
    __nv_bfloat16 *uhi, *ulo, *w1hi, *w1lo, *w2hi, *w2lo, *yghi, *yglo;
    cudaGetSymbolAddress((void**)&zx,  g_zx);
    cudaGetSymbolAddress((void**)&xbc, g_xbc);
    cudaGetSymbolAddress((void**)&dec, g_dec);
    cudaGetSymbolAddress((void**)&y,   g_y);
    cudaGetSymbolAddress((void**)&st,  g_st);
    cudaGetSymbolAddress((void**)&cum, g_cum);
    cudaGetSymbolAddress((void**)&uhi,  g_uhi);
    cudaGetSymbolAddress((void**)&ulo,  g_ulo);
    cudaGetSymbolAddress((void**)&w1hi, g_w1hi);
    cudaGetSymbolAddress((void**)&w1lo, g_w1lo);
    cudaGetSymbolAddress((void**)&w2hi, g_w2hi);
    cudaGetSymbolAddress((void**)&w2lo, g_w2lo);
    cudaGetSymbolAddress((void**)&yghi, g_yghi);
    cudaGetSymbolAddress((void**)&yglo, g_yglo);

    cudaFuncSetAttribute(gemm_bf16x3,
        cudaFuncAttributeMaxDynamicSharedMemorySize, GB_SMEM_BYTES);

    // 0) split fp32 operands into bf16 hi/lo
    {
        int n4u = NROWS * D_MODEL / 4;
        split_kernel<<<(n4u + 255) / 256, 256>>>(u, uhi, ulo, n4u);
        int n4w1 = D_IN_PROJ * D_MODEL / 4;
        split_kernel<<<(n4w1 + 255) / 256, 256>>>(in_proj, w1hi, w1lo, n4w1);
        int n4w2 = D_MODEL * D_INNER / 4;
        split_kernel<<<(n4w2 + 255) / 256, 256>>>(out_w, w2hi, w2lo, n4w2);
    }
    // 1) in_proj GEMM
    {
        dim3 grid((D_IN_PROJ + GB_N - 1) / GB_N, NROWS / GB_M);
        gemm_bf16x3<<<grid, 256, GB_SMEM_BYTES>>>(uhi, ulo, w1hi, w1lo, zx,
                                                  NROWS, D_IN_PROJ, D_MODEL);
    }
    // 2) conv + silu
    {
        dim3 grid((CONV_DIM + 255) / 256, SEQLEN / 256, BATCH);
        conv_kernel<<<grid, 256>>>(zx, conv_w, conv_b, xbc);
    }
    // 3) decay precompute
    decay_kernel<<<(NROWS * NHEADS + 255) / 256, 256>>>(zx, dt_bias, A_log, dec);
    // 4) chunked SSM scan
    {
        dim3 grid(NCHUNK, NHEADS, BATCH);
        scan_local_kernel<<<grid, 128>>>(xbc, dec, Dv, y, st, cum);
    }
    {
        dim3 grid(NHEADS, BATCH);
        scan_combine_kernel<<<grid, 256>>>(st, cum);
    }
    {
        dim3 grid(NCHUNK, NHEADS, BATCH);
        scan_fix_kernel<<<grid, 128>>>(st, cum, xbc, y);
    }
    // 5) rmsnorm + gate (+ bf16 split)
    rms_gate_kernel<<<NROWS, 256>>>(y, zx, rms_w, yghi, yglo);
    // 6) out_proj GEMM
    {
        dim3 grid(D_MODEL / GB_N, NROWS / GB_M);
        gemm_bf16x3<<<grid, 256, GB_SMEM_BYTES>>>(yghi, yglo, w2hi, w2lo, out,
                                                  NROWS, D_MODEL, D_INNER);
    }
}

// round 10
// speedup vs baseline: 1.3025x; 1.0515x over previous
#include <cuda_runtime.h>
#include <cuda_bf16.h>
#include <cstdint>
#include <math.h>

// ---------------- problem constants ----------------
#define D_MODEL   1024
#define D_INNER   2048
#define D_STATE   64
#define HEADDIM   128
#define NHEADS    16
#define D_CONV    4
#define CONV_DIM  2176
#define D_IN_PROJ 4240
#define BATCH     2
#define SEQLEN    4096
#define NROWS     (BATCH*SEQLEN)  // 8192
#define RMS_EPS   1e-5f

#define LCHUNK    128
#define NCHUNK    (SEQLEN/LCHUNK)   // 32
#define SBLK      16                // staging block (steps)
#define NBLK      (LCHUNK/SBLK)     // 8

// ---------------- scratch ----------------
__device__ float g_zx [(size_t)NROWS * D_IN_PROJ];
__device__ float g_xbc[(size_t)NROWS * CONV_DIM];
__device__ float g_dec[(size_t)NROWS * NHEADS];
__device__ float g_y  [(size_t)NROWS * D_INNER];
__device__ float g_st [(size_t)BATCH * NHEADS * NCHUNK * HEADDIM * D_STATE];
__device__ float g_cum[(size_t)BATCH * NHEADS * NCHUNK * LCHUNK];
__device__ __nv_bfloat16 g_uhi [(size_t)NROWS * D_MODEL];
__device__ __nv_bfloat16 g_ulo [(size_t)NROWS * D_MODEL];
__device__ __nv_bfloat16 g_w1hi[(size_t)D_IN_PROJ * D_MODEL];
__device__ __nv_bfloat16 g_w1lo[(size_t)D_IN_PROJ * D_MODEL];
__device__ __nv_bfloat16 g_w2hi[(size_t)D_MODEL * D_INNER];
__device__ __nv_bfloat16 g_w2lo[(size_t)D_MODEL * D_INNER];
__device__ __nv_bfloat16 g_yghi[(size_t)NROWS * D_INNER];
__device__ __nv_bfloat16 g_yglo[(size_t)NROWS * D_INNER];

// ================= helpers =================
__device__ __forceinline__ uint32_t smem_to_u32(const void* p) {
    uint32_t a;
    asm("{ .reg .u64 t; cvta.to.shared.u64 t, %1; cvt.u32.u64 %0, t; }"
        : "=r"(a) : "l"(p));
    return a;
}
__device__ __forceinline__ uint32_t pack_bf16(float lo_elem, float hi_elem) {
    uint32_t r;
    asm("cvt.rn.bf16x2.f32 %0, %1, %2;" : "=r"(r) : "f"(hi_elem), "f"(lo_elem));
    return r;
}
__device__ __forceinline__ void mma_bf16(float* d, const uint32_t* a,
                                         const uint32_t* b) {
    asm volatile(
        "mma.sync.aligned.m16n8k16.row.col.f32.bf16.bf16.f32 "
        "{%0,%1,%2,%3},{%4,%5,%6,%7},{%8,%9},{%0,%1,%2,%3};"
        : "+f"(d[0]), "+f"(d[1]), "+f"(d[2]), "+f"(d[3])
        : "r"(a[0]), "r"(a[1]), "r"(a[2]), "r"(a[3]), "r"(b[0]), "r"(b[1]));
}
__device__ __forceinline__ void ldsm_x4(uint32_t& r0, uint32_t& r1,
                                        uint32_t& r2, uint32_t& r3,
                                        uint32_t addr) {
    asm volatile("ldmatrix.sync.aligned.m8n8.x4.shared.b16 {%0,%1,%2,%3}, [%4];"
                 : "=r"(r0), "=r"(r1), "=r"(r2), "=r"(r3) : "r"(addr));
}
// packed f32x2 ops (sm_100+ base feature)
#define FMA2(d, a, b, c) \
    asm("fma.rn.f32x2 %0, %1, %2, %3;" : "=l"(d) : "l"(a), "l"(b), "l"(c))
#define MUL2(d, a, b) \
    asm("mul.rn.f32x2 %0, %1, %2;" : "=l"(d) : "l"(a), "l"(b))
#define PACK2(d, s) \
    asm("mov.b64 %0, {%1, %1};" : "=l"(d) : "f"(s))
#define UNPACK2(lo, hi, v) \
    asm("mov.b64 {%0, %1}, %2;" : "=f"(lo), "=f"(hi) : "l"(v))

__device__ __forceinline__ float fast_sigmoid(float x) {
    return __fdividef(1.f, 1.f + __expf(-x));
}

// ================= split kernel: fp32 -> bf16 hi + bf16 lo =================
__global__ __launch_bounds__(256) void split_kernel(
    const float* __restrict__ in, __nv_bfloat16* __restrict__ hi,
    __nv_bfloat16* __restrict__ lo, int n4)
{
    int i = blockIdx.x * 256 + threadIdx.x;
    if (i >= n4) return;
    float4 v = ((const float4*)in)[i];
    uint32_t h01 = pack_bf16(v.x, v.y);
    uint32_t h23 = pack_bf16(v.z, v.w);
    float h0 = __uint_as_float(h01 << 16);
    float h1 = __uint_as_float(h01 & 0xffff0000u);
    float h2 = __uint_as_float(h23 << 16);
    float h3 = __uint_as_float(h23 & 0xffff0000u);
    uint32_t l01 = pack_bf16(v.x - h0, v.y - h1);
    uint32_t l23 = pack_bf16(v.z - h2, v.w - h3);
    ((uint2*)hi)[i] = make_uint2(h01, h23);
    ((uint2*)lo)[i] = make_uint2(l01, l23);
}

// ================= GEMM (bf16x3, ldmatrix + 3-stage cp.async) ==============
#define GB_M 128
#define GB_N 128
#define GB_K 32
#define GB_STAGE 32768
#define GB_SMEM_BYTES (3 * GB_STAGE)   // 98304

__global__ __launch_bounds__(256, 2) void gemm_bf16x3(
    const __nv_bfloat16* __restrict__ Ahi, const __nv_bfloat16* __restrict__ Alo,
    const __nv_bfloat16* __restrict__ Bhi, const __nv_bfloat16* __restrict__ Blo,
    float* __restrict__ C, int M, int N, int K)
{
    extern __shared__ char smem[];
    const uint32_t sbase = smem_to_u32(smem);
    const int tid = threadIdx.x;
    const int bm  = blockIdx.y * GB_M;
    const int bn  = blockIdx.x * GB_N;
    const int nch = K / GB_K;

    const int warp = tid >> 5;
    const int lane = tid & 31;
    const int wm = warp >> 2;
    const int wn = warp & 3;
    const int lr = lane >> 2;
    const int lc = lane & 3;

    float acc[4][4][4];
    #pragma unroll
    for (int mt = 0; mt < 4; mt++)
        #pragma unroll
        for (int nt = 0; nt < 4; nt++)
            #pragma unroll
            for (int q = 0; q < 4; q++) acc[mt][nt][q] = 0.f;

    auto load_stage = [&](int buf, int kt) {
        #pragma unroll
        for (int i = 0; i < 8; i++) {
            int idx = tid + i * 256;
            int cq = idx & 3;
            int r  = (idx >> 2) & 127;
            int t  = idx >> 9;
            uint32_t so = sbase + (uint32_t)buf * GB_STAGE + (uint32_t)t * 8192 +
                          (uint32_t)r * 64 + (uint32_t)((cq ^ ((r >> 1) & 3)) * 16);
            const __nv_bfloat16* g;
            if (t == 0)      g = Ahi + (size_t)(bm + r) * K;
            else if (t == 1) g = Alo + (size_t)(bm + r) * K;
            else {
                int gn = bn + r; if (gn >= N) gn = N - 1;
                g = (t == 2 ? Bhi : Blo) + (size_t)gn * K;
            }
            g += kt + cq * 8;
            asm volatile("cp.async.cg.shared.global [%0], [%1], 16;"
                         :: "r"(so), "l"(g));
        }
        asm volatile("cp.async.commit_group;");
    };

    load_stage(0, 0);
    if (nch > 1) load_stage(1, GB_K);

    const int rowA = wm * 64 + ((lane >> 3) & 1) * 8 + (lane & 7);
    const int rowB = wn * 32 + ((lane >> 4) & 1) * 8 + (lane & 7);
    const int sel  = ((lane & 7) >> 1) & 3;
    const int cAq  = (lane >> 4) & 1;
    const int cBq  = (lane >> 3) & 1;

    for (int c = 0; c < nch; c++) {
        if (c == nch - 1) asm volatile("cp.async.wait_group 0;");
        else              asm volatile("cp.async.wait_group 1;");
        __syncthreads();
        if (c + 2 < nch) load_stage((c + 2) % 3, (c + 2) * GB_K);

        const uint32_t stg = sbase + (uint32_t)(c % 3) * GB_STAGE;
        const uint32_t baseAhi = stg + (uint32_t)rowA * 64;
        const uint32_t baseAlo = baseAhi + 8192;
        const uint32_t baseBhi = stg + 16384 + (uint32_t)rowB * 64;
        const uint32_t baseBlo = baseBhi + 8192;

        #pragma unroll
        for (int ks = 0; ks < 2; ks++) {
            const uint32_t cAo = (uint32_t)(((ks * 2 + cAq) ^ sel) * 16);
            const uint32_t cBo = (uint32_t)(((ks * 2 + cBq) ^ sel) * 16);

            uint32_t bh[4][2], bl[4][2];
            #pragma unroll
            for (int ntp = 0; ntp < 2; ntp++) {
                uint32_t r0, r1, r2, r3;
                ldsm_x4(r0, r1, r2, r3, baseBhi + ntp * 1024 + cBo);
                bh[ntp*2][0] = r0; bh[ntp*2][1] = r1;
                bh[ntp*2+1][0] = r2; bh[ntp*2+1][1] = r3;
                ldsm_x4(r0, r1, r2, r3, baseBlo + ntp * 1024 + cBo);
                bl[ntp*2][0] = r0; bl[ntp*2][1] = r1;
                bl[ntp*2+1][0] = r2; bl[ntp*2+1][1] = r3;
            }
            #pragma unroll
            for (int mt = 0; mt < 4; mt++) {
                uint32_t ah[4], al[4];
                ldsm_x4(ah[0], ah[1], ah[2], ah[3], baseAhi + mt * 1024 + cAo);
                ldsm_x4(al[0], al[1], al[2], al[3], baseAlo + mt * 1024 + cAo);
                #pragma unroll
                for (int nt = 0; nt < 4; nt++) {
                    mma_bf16(acc[mt][nt], ah, bh[nt]);
                    mma_bf16(acc[mt][nt], ah, bl[nt]);
                    mma_bf16(acc[mt][nt], al, bh[nt]);
                }
            }
        }
    }

    #pragma unroll
    for (int mt = 0; mt < 4; mt++) {
        int row = bm + wm * 64 + mt * 16 + lr;
        #pragma unroll
        for (int nt = 0; nt < 4; nt++) {
            int col = bn + wn * 32 + nt * 8 + lc * 2;
            if (col < N) {
                *(float2*)(C + (size_t)row * N + col) =
                    make_float2(acc[mt][nt][0], acc[mt][nt][1]);
                *(float2*)(C + (size_t)(row + 8) * N + col) =
                    make_float2(acc[mt][nt][2], acc[mt][nt][3]);
            }
        }
    }
}

// ---------------- depthwise causal conv (k=4) + bias + SiLU ----------------
__global__ __launch_bounds__(256) void conv_kernel(
    const float* __restrict__ zx, const float* __restrict__ cw,
    const float* __restrict__ cb, float* __restrict__ xbc)
{
    int c = blockIdx.x * 256 + threadIdx.x;
    if (c >= CONV_DIM) return;
    int strip = blockIdx.y;
    int b     = blockIdx.z;
    int l0    = strip * 256;

    float w0 = cw[c*4+0], w1 = cw[c*4+1], w2 = cw[c*4+2], w3 = cw[c*4+3];
    float bias = cb[c];

    size_t colbase = (size_t)D_INNER + c;
    size_t rb = (size_t)b * SEQLEN;

    float xm3 = (l0-3 >= 0) ? zx[(rb + l0-3) * D_IN_PROJ + colbase] : 0.f;
    float xm2 = (l0-2 >= 0) ? zx[(rb + l0-2) * D_IN_PROJ + colbase] : 0.f;
    float xm1 = (l0-1 >= 0) ? zx[(rb + l0-1) * D_IN_PROJ + colbase] : 0.f;

    for (int l = l0; l < l0 + 256; l++) {
        float xv = zx[(rb + l) * D_IN_PROJ + colbase];
        float a = bias;
        a = fmaf(w0, xm3, a);
        a = fmaf(w1, xm2, a);
        a = fmaf(w2, xm1, a);
        a = fmaf(w3, xv,  a);
        float sv = a * fast_sigmoid(a);
        xbc[(rb + l) * CONV_DIM + c] = sv;
        xm3 = xm2; xm2 = xm1; xm1 = xv;
    }
}

// ---------------- dt -> softplus -> decay ----------------------------------
__global__ __launch_bounds__(256) void decay_kernel(
    const float* __restrict__ zx, const float* __restrict__ dt_bias,
    const float* __restrict__ A_log, float* __restrict__ dec)
{
    int idx = blockIdx.x * 256 + threadIdx.x;
    if (idx >= NROWS * NHEADS) return;
    int r = idx >> 4;
    int h = idx & 15;
    float raw = zx[(size_t)r * D_IN_PROJ + (D_IN_PROJ - NHEADS) + h] + dt_bias[h];
    float sp  = (raw > 20.f) ? raw : log1pf(expf(raw));
    float A   = -expf(A_log[h]);
    dec[idx]  = expf(sp * A);
}

// ---------------- chunked scan: stage 1 (thread=p, f32x2 math) -------------
__global__ __launch_bounds__(128) void scan_local_kernel(
    const float* __restrict__ xbc, const float* __restrict__ dec,
    const float* __restrict__ Dvec, float* __restrict__ yout,
    float* __restrict__ states, float* __restrict__ cumout)
{
    const int c = blockIdx.x;
    const int h = blockIdx.y;
    const int b = blockIdx.z;
    const int p = threadIdx.x;

    __shared__ __align__(16) float sx [2][SBLK][128];
    __shared__ __align__(16) float sBC[2][SBLK][128];
    __shared__ __align__(16) float sdec[2][SBLK];

    unsigned long long s2[32];
    #pragma unroll
    for (int q = 0; q < 32; q++) s2[q] = 0ull;

    const float Dh = Dvec[h];
    const size_t base = (size_t)b * SEQLEN + (size_t)c * LCHUNK;
    const int xcol = h * HEADDIM;
    const size_t cumbase = (size_t)(((b * NHEADS + h) * NCHUNK) + c) * LCHUNK;

    const uint32_t sx_a   = smem_to_u32(sx);
    const uint32_t sbc_a  = smem_to_u32(sBC);
    const uint32_t sdec_a = smem_to_u32(sdec);

    auto stage = [&](int buf, int l0) {
        #pragma unroll
        for (int i = 0; i < 8; i++) {
            int idx = p + i * 128;
            int stp = idx >> 6;
            int q   = idx & 63;
            size_t row = (base + l0 + stp) * CONV_DIM;
            const float* src;
            uint32_t dst;
            if (q < 32) {
                src = xbc + row + xcol + q * 4;
                dst = sx_a + (uint32_t)((buf * SBLK + stp) * 128 + q * 4) * 4;
            } else {
                src = xbc + row + D_INNER + (q - 32) * 4;
                dst = sbc_a + (uint32_t)((buf * SBLK + stp) * 128 + (q - 32) * 4) * 4;
            }
            asm volatile("cp.async.cg.shared.global [%0], [%1], 16;"
                         :: "r"(dst), "l"(src));
        }
        if (p < SBLK) {
            const float* src = dec + (base + l0 + p) * NHEADS + h;
            uint32_t dst = sdec_a + (uint32_t)(buf * SBLK + p) * 4;
            asm volatile("cp.async.ca.shared.global [%0], [%1], 4;"
                         :: "r"(dst), "l"(src));
        }
        asm volatile("cp.async.commit_group;");
    };

    stage(0, 0);
    stage(1, SBLK);

    float cum = 1.f;

    for (int blk = 0; blk < NBLK; blk++) {
        if (blk >= NBLK - 2) asm volatile("cp.async.wait_group 0;");
        else                 asm volatile("cp.async.wait_group 1;");
        __syncthreads();
        const int cur = blk & 1;
        const int l0 = blk * SBLK;

        #pragma unroll 4
        for (int j = 0; j < SBLK; j++) {
            const float dcy = sdec[cur][j];
            const float xv  = sx[cur][j][p];
            unsigned long long dpack, xpack;
            PACK2(dpack, dcy);
            PACK2(xpack, xv);
            const ulonglong2* B2 = (const ulonglong2*)&sBC[cur][j][0];
            const ulonglong2* C2 = (const ulonglong2*)&sBC[cur][j][64];
            unsigned long long ya0 = 0ull, ya1 = 0ull, ya2 = 0ull, ya3 = 0ull;
            unsigned long long yb0 = 0ull, yb1 = 0ull, yb2 = 0ull, yb3 = 0ull;
            #pragma unroll
            for (int q = 0; q < 16; q += 4) {
                ulonglong2 bv0 = B2[q],   bv1 = B2[q+1];
                ulonglong2 bv2 = B2[q+2], bv3 = B2[q+3];
                ulonglong2 cv0 = C2[q],   cv1 = C2[q+1];
                ulonglong2 cv2 = C2[q+2], cv3 = C2[q+3];
                unsigned long long t;
                MUL2(t, bv0.x, xpack); FMA2(s2[2*q],   s2[2*q],   dpack, t);
                FMA2(ya0, s2[2*q],   cv0.x, ya0);
                MUL2(t, bv0.y, xpack); FMA2(s2[2*q+1], s2[2*q+1], dpack, t);
                FMA2(yb0, s2[2*q+1], cv0.y, yb0);
                MUL2(t, bv1.x, xpack); FMA2(s2[2*q+2], s2[2*q+2], dpack, t);
                FMA2(ya1, s2[2*q+2], cv1.x, ya1);
                MUL2(t, bv1.y, xpack); FMA2(s2[2*q+3], s2[2*q+3], dpack, t);
                FMA2(yb1, s2[2*q+3], cv1.y, yb1);
                MUL2(t, bv2.x, xpack); FMA2(s2[2*q+4], s2[2*q+4], dpack, t);
                FMA2(ya2, s2[2*q+4], cv2.x, ya2);
                MUL2(t, bv2.y, xpack); FMA2(s2[2*q+5], s2[2*q+5], dpack, t);
                FMA2(yb2, s2[2*q+5], cv2.y, yb2);
                MUL2(t, bv3.x, xpack); FMA2(s2[2*q+6], s2[2*q+6], dpack, t);
                FMA2(ya3, s2[2*q+6], cv3.x, ya3);
                MUL2(t, bv3.y, xpack); FMA2(s2[2*q+7], s2[2*q+7], dpack, t);
                FMA2(yb3, s2[2*q+7], cv3.y, yb3);
            }
            float a0, a1, b0, b1, acc = 0.f;
            UNPACK2(a0, a1, ya0); acc += a0 + a1;
            UNPACK2(a0, a1, ya1); acc += a0 + a1;
            UNPACK2(a0, a1, ya2); acc += a0 + a1;
            UNPACK2(a0, a1, ya3); acc += a0 + a1;
            UNPACK2(b0, b1, yb0); acc += b0 + b1;
            UNPACK2(b0, b1, yb1); acc += b0 + b1;
            UNPACK2(b0, b1, yb2); acc += b0 + b1;
            UNPACK2(b0, b1, yb3); acc += b0 + b1;
            yout[(base + l0 + j) * D_INNER + xcol + p] = fmaf(Dh, xv, acc);
            if (p == 0) {
                cum *= dcy;
                cumout[cumbase + l0 + j] = cum;
            }
        }
        __syncthreads();
        if (blk + 2 < NBLK) stage(cur, (blk + 2) * SBLK);
    }

    float* st = states +
        ((size_t)(((b * NHEADS + h) * NCHUNK) + c) * HEADDIM + p) * D_STATE;
    #pragma unroll
    for (int q = 0; q < 16; q++) {
        ulonglong2 v;
        v.x = s2[2*q];
        v.y = s2[2*q+1];
        *(ulonglong2*)(st + q * 4) = v;
    }
}

// ---------------- chunked scan: stage 2 (combine across chunks) ------------
__global__ __launch_bounds__(256) void scan_combine_kernel(
    float* __restrict__ states, const float* __restrict__ cum)
{
    const int h = blockIdx.x;
    const int b = blockIdx.y;
    const int tid = threadIdx.x;

    __shared__ float dprod[NCHUNK];
    if (tid < NCHUNK)
        dprod[tid] = cum[(size_t)(((b * NHEADS + h) * NCHUNK) + tid) * LCHUNK + LCHUNK - 1];
    __syncthreads();

    const size_t chunk_stride = (size_t)HEADDIM * D_STATE;
    float* base = states + (size_t)((b * NHEADS + h) * NCHUNK) * chunk_stride;

    float4 e[8];
    #pragma unroll
    for (int k = 0; k < 8; k++) e[k] = make_float4(0.f, 0.f, 0.f, 0.f);

    for (int c = 0; c < NCHUNK; c++) {
        float d = dprod[c];
        float4* p = (float4*)(base + c * chunk_stride);
        #pragma unroll
        for (int k = 0; k < 8; k++) {
            int idx = tid + k * 256;
            float4 sl = p[idx];
            p[idx] = e[k];
            e[k].x = fmaf(e[k].x, d, sl.x);
            e[k].y = fmaf(e[k].y, d, sl.y);
            e[k].z = fmaf(e[k].z, d, sl.z);
            e[k].w = fmaf(e[k].w, d, sl.w);
        }
    }
}

// ---------------- chunked scan: stage 3 (smem-staged, f32x2) ---------------
__global__ __launch_bounds__(128) void scan_fix_kernel(
    const float* __restrict__ states, const float* __restrict__ cum,
    const float* __restrict__ xbc, float* __restrict__ yout)
{
    const int c = blockIdx.x;
    if (c == 0) return;
    const int h = blockIdx.y;
    const int b = blockIdx.z;
    const int p = threadIdx.x;

    __shared__ __align__(16) float sC  [2][SBLK][64];
    __shared__ __align__(16) float scum[2][SBLK];

    ulonglong2 ent2[16];
    const float* st = states +
        ((size_t)(((b * NHEADS + h) * NCHUNK) + c) * HEADDIM + p) * D_STATE;
    #pragma unroll
    for (int q = 0; q < 16; q++) ent2[q] = *(const ulonglong2*)(st + q * 4);

    const size_t base = (size_t)b * SEQLEN + (size_t)c * LCHUNK;
    const size_t cumbase = (size_t)(((b * NHEADS + h) * NCHUNK) + c) * LCHUNK;
    const int ycol = h * HEADDIM + p;

    const uint32_t sC_a   = smem_to_u32(sC);
    const uint32_t scum_a = smem_to_u32(scum);

    auto stage = [&](int buf, int l0) {
        #pragma unroll
        for (int i = 0; i < 2; i++) {
            int idx = p + i * 128;
            int stp = idx >> 4;
            int q   = idx & 15;
            const float* src = xbc + (base + l0 + stp) * CONV_DIM + D_INNER + 64 + q * 4;
            uint32_t dst = sC_a + (uint32_t)((buf * SBLK + stp) * 64 + q * 4) * 4;
            asm volatile("cp.async.cg.shared.global [%0], [%1], 16;"
                         :: "r"(dst), "l"(src));
        }
        if (p < SBLK) {
            const float* src = cum + cumbase + l0 + p;
            uint32_t dst = scum_a + (uint32_t)(buf * SBLK + p) * 4;
            asm volatile("cp.async.ca.shared.global [%0], [%1], 4;"
                         :: "r"(dst), "l"(src));
        }
        asm volatile("cp.async.commit_group;");
    };

    stage(0, 0);
    stage(1, SBLK);

    for (int blk = 0; blk < NBLK; blk++) {
        if (blk >= NBLK - 2) asm volatile("cp.async.wait_group 0;");
        else                 asm volatile("cp.async.wait_group 1;");
        __syncthreads();
        const int cur = blk & 1;
        const int l0 = blk * SBLK;

        #pragma unroll 4
        for (int j = 0; j < SBLK; j++) {
            const ulonglong2* C2 = (const ulonglong2*)&sC[cur][j][0];
            unsigned long long a0 = 0ull, a1 = 0ull, b0 = 0ull, b1 = 0ull;
            #pragma unroll
            for (int q = 0; q < 16; q += 2) {
                ulonglong2 cv0 = C2[q];
                ulonglong2 cv1 = C2[q+1];
                FMA2(a0, ent2[q].x,   cv0.x, a0);
                FMA2(b0, ent2[q].y,   cv0.y, b0);
                FMA2(a1, ent2[q+1].x, cv1.x, a1);
                FMA2(b1, ent2[q+1].y, cv1.y, b1);
            }
            float p0, p1, dot = 0.f;
            UNPACK2(p0, p1, a0); dot += p0 + p1;
            UNPACK2(p0, p1, a1); dot += p0 + p1;
            UNPACK2(p0, p1, b0); dot += p0 + p1;
            UNPACK2(p0, p1, b1); dot += p0 + p1;
            float cm = scum[cur][j];
            float* yp = yout + (base + l0 + j) * D_INNER + ycol;
            *yp = fmaf(cm, dot, *yp);
        }
        __syncthreads();
        if (blk + 2 < NBLK) stage(cur, (blk + 2) * SBLK);
    }
}

// ---------------- RMSNorm + gate, fused bf16 split output ------------------
__global__ __launch_bounds__(256) void rms_gate_kernel(
    const float* __restrict__ y, const float* __restrict__ zx,
    const float* __restrict__ rmsw,
    __nv_bfloat16* __restrict__ ygh, __nv_bfloat16* __restrict__ ygl)
{
    int r = blockIdx.x;
    const float*  yr = y  + (size_t)r * D_INNER;
    const float*  zr = zx + (size_t)r * D_IN_PROJ;
    const float4* y4 = (const float4*)yr;

    int tid = threadIdx.x;
    float ss = 0.f;
    #pragma unroll
    for (int i = 0; i < 2; i++) {
        float4 v = y4[tid + i * 256];
        ss += v.x*v.x + v.y*v.y + v.z*v.z + v.w*v.w;
    }
    #pragma unroll
    for (int o = 16; o > 0; o >>= 1) ss += __shfl_xor_sync(0xffffffffu, ss, o);
    __shared__ float red[8];
    if ((tid & 31) == 0) red[tid >> 5] = ss;
    __syncthreads();
    if (tid == 0) {
        float t = 0.f;
        #pragma unroll
        for (int i = 0; i < 8; i++) t += red[i];
        red[0] = rsqrtf(t * (1.f / D_INNER) + RMS_EPS);
    }
    __syncthreads();
    float rs = red[0];

    const float4* z4 = (const float4*)zr;
    const float4* w4 = (const float4*)rmsw;
    uint2* gh = (uint2*)(ygh + (size_t)r * D_INNER);
    uint2* gl = (uint2*)(ygl + (size_t)r * D_INNER);
    #pragma unroll
    for (int i = 0; i < 2; i++) {
        int c = tid + i * 256;
        float4 v = y4[c];
        float4 z = z4[c];
        float4 w = w4[c];
        float4 o;
        o.x = v.x * rs * w.x * fast_sigmoid(z.x);
        o.y = v.y * rs * w.y * fast_sigmoid(z.y);
        o.z = v.z * rs * w.z * fast_sigmoid(z.z);
        o.w = v.w * rs * w.w * fast_sigmoid(z.w);
        uint32_t h01 = pack_bf16(o.x, o.y);
        uint32_t h23 = pack_bf16(o.z, o.w);
        float h0 = __uint_as_float(h01 << 16);
        float h1 = __uint_as_float(h01 & 0xffff0000u);
        float h2 = __uint_as_float(h23 << 16);
        float h3 = __uint_as_float(h23 & 0xffff0000u);
        gh[c] = make_uint2(h01, h23);
        gl[c] = make_uint2(pack_bf16(o.x - h0, o.y - h1),
                           pack_bf16(o.z - h2, o.w - h3));
    }
}

// ---------------- launcher -------------------------------------------------
extern "C" void kernel_launch(void* const* d_in, const int* in_sizes, int n_in,
                              void* d_out, int out_size)
{
    const float* u        = (const float*)d_in[0];
    const float* in_proj  = (const float*)d_in[1];
    const float* conv_w   = (const float*)d_in[2];
    const float* conv_b   = (const float*)d_in[3];
    const float* dt_bias  = (const float*)d_in[4];
    const float* A_log    = (const float*)d_in[5];
    const float* Dv       = (const float*)d_in[6];
    const float* rms_w    = (const float*)d_in[7];
    const float* out_w    = (const float*)d_in[8];
    float* out = (float*)d_out;

    float *zx, *xbc, *dec, *y, *st, *cum;
    __nv_bfloat16 *uhi, *ulo, *w1hi, *w1lo, *w2hi, *w2lo, *yghi, *yglo;
    cudaGetSymbolAddress((void**)&zx,  g_zx);
    cudaGetSymbolAddress((void**)&xbc, g_xbc);
    cudaGetSymbolAddress((void**)&dec, g_dec);
    cudaGetSymbolAddress((void**)&y,   g_y);
    cudaGetSymbolAddress((void**)&st,  g_st);
    cudaGetSymbolAddress((void**)&cum, g_cum);
    cudaGetSymbolAddress((void**)&uhi,  g_uhi);
    cudaGetSymbolAddress((void**)&ulo,  g_ulo);
    cudaGetSymbolAddress((void**)&w1hi, g_w1hi);
    cudaGetSymbolAddress((void**)&w1lo, g_w1lo);
    cudaGetSymbolAddress((void**)&w2hi, g_w2hi);
    cudaGetSymbolAddress((void**)&w2lo, g_w2lo);
    cudaGetSymbolAddress((void**)&yghi, g_yghi);
    cudaGetSymbolAddress((void**)&yglo, g_yglo);

    cudaFuncSetAttribute(gemm_bf16x3,
        cudaFuncAttributeMaxDynamicSharedMemorySize, GB_SMEM_BYTES);

    // 0) split fp32 operands into bf16 hi/lo
    {
        int n4u = NROWS * D_MODEL / 4;
        split_kernel<<<(n4u + 255) / 256, 256>>>(u, uhi, ulo, n4u);
        int n4w1 = D_IN_PROJ * D_MODEL / 4;
        split_kernel<<<(n4w1 + 255) / 256, 256>>>(in_proj, w1hi, w1lo, n4w1);
        int n4w2 = D_MODEL * D_INNER / 4;
        split_kernel<<<(n4w2 + 255) / 256, 256>>>(out_w, w2hi, w2lo, n4w2);
    }
    // 1) in_proj GEMM
    {
        dim3 grid((D_IN_PROJ + GB_N - 1) / GB_N, NROWS / GB_M);
        gemm_bf16x3<<<grid, 256, GB_SMEM_BYTES>>>(uhi, ulo, w1hi, w1lo, zx,
                                                  NROWS, D_IN_PROJ, D_MODEL);
    }
    // 2) conv + silu
    {
        dim3 grid((CONV_DIM + 255) / 256, SEQLEN / 256, BATCH);
        conv_kernel<<<grid, 256>>>(zx, conv_w, conv_b, xbc);
    }
    // 3) decay precompute
    decay_kernel<<<(NROWS * NHEADS + 255) / 256, 256>>>(zx, dt_bias, A_log, dec);
    // 4) chunked SSM scan
    {
        dim3 grid(NCHUNK, NHEADS, BATCH);
        scan_local_kernel<<<grid, 128>>>(xbc, dec, Dv, y, st, cum);
    }
    {
        dim3 grid(NHEADS, BATCH);
        scan_combine_kernel<<<grid, 256>>>(st, cum);
    }
    {
        dim3 grid(NCHUNK, NHEADS, BATCH);
        scan_fix_kernel<<<grid, 128>>>(st, cum, xbc, y);
    }
    // 5) rmsnorm + gate (+ bf16 split)
    rms_gate_kernel<<<NROWS, 256>>>(y, zx, rms_w, yghi, yglo);
    // 6) out_proj GEMM
    {
        dim3 grid(D_MODEL / GB_N, NROWS / GB_M);
        gemm_bf16x3<<<grid, 256, GB_SMEM_BYTES>>>(yghi, yglo, w2hi, w2lo, out,
                                                  NROWS, D_MODEL, D_INNER);
    }
}

// round 11
// speedup vs baseline: 1.3092x; 1.0051x over previous
#include <cuda_runtime.h>
#include <cuda_bf16.h>
#include <cstdint>
#include <math.h>

// ---------------- problem constants ----------------
#define D_MODEL   1024
#define D_INNER   2048
#define D_STATE   64
#define HEADDIM   128
#define NHEADS    16
#define D_CONV    4
#define CONV_DIM  2176
#define D_IN_PROJ 4240
#define BATCH     2
#define SEQLEN    4096
#define NROWS     (BATCH*SEQLEN)  // 8192
#define RMS_EPS   1e-5f

#define LCHUNK    256
#define NCHUNK    (SEQLEN/LCHUNK)   // 16
#define SBLK      16                // staging block (steps)
#define NBLK      (LCHUNK/SBLK)     // 16

// ---------------- scratch ----------------
__device__ float g_zx [(size_t)NROWS * D_IN_PROJ];
__device__ float g_xbc[(size_t)NROWS * CONV_DIM];
__device__ float g_dec[(size_t)NROWS * NHEADS];
__device__ float g_y  [(size_t)NROWS * D_INNER];
__device__ float g_st [(size_t)BATCH * NHEADS * NCHUNK * HEADDIM * D_STATE];
__device__ float g_cum[(size_t)BATCH * NHEADS * NCHUNK * LCHUNK];
__device__ __nv_bfloat16 g_uhi [(size_t)NROWS * D_MODEL];
__device__ __nv_bfloat16 g_ulo [(size_t)NROWS * D_MODEL];
__device__ __nv_bfloat16 g_w1hi[(size_t)D_IN_PROJ * D_MODEL];
__device__ __nv_bfloat16 g_w1lo[(size_t)D_IN_PROJ * D_MODEL];
__device__ __nv_bfloat16 g_w2hi[(size_t)D_MODEL * D_INNER];
__device__ __nv_bfloat16 g_w2lo[(size_t)D_MODEL * D_INNER];
__device__ __nv_bfloat16 g_yghi[(size_t)NROWS * D_INNER];
__device__ __nv_bfloat16 g_yglo[(size_t)NROWS * D_INNER];

// ================= helpers =================
__device__ __forceinline__ uint32_t smem_to_u32(const void* p) {
    uint32_t a;
    asm("{ .reg .u64 t; cvta.to.shared.u64 t, %1; cvt.u32.u64 %0, t; }"
        : "=r"(a) : "l"(p));
    return a;
}
__device__ __forceinline__ uint32_t pack_bf16(float lo_elem, float hi_elem) {
    uint32_t r;
    asm("cvt.rn.bf16x2.f32 %0, %1, %2;" : "=r"(r) : "f"(hi_elem), "f"(lo_elem));
    return r;
}
__device__ __forceinline__ void mma_bf16(float* d, const uint32_t* a,
                                         const uint32_t* b) {
    asm volatile(
        "mma.sync.aligned.m16n8k16.row.col.f32.bf16.bf16.f32 "
        "{%0,%1,%2,%3},{%4,%5,%6,%7},{%8,%9},{%0,%1,%2,%3};"
        : "+f"(d[0]), "+f"(d[1]), "+f"(d[2]), "+f"(d[3])
        : "r"(a[0]), "r"(a[1]), "r"(a[2]), "r"(a[3]), "r"(b[0]), "r"(b[1]));
}
__device__ __forceinline__ void ldsm_x4(uint32_t& r0, uint32_t& r1,
                                        uint32_t& r2, uint32_t& r3,
                                        uint32_t addr) {
    asm volatile("ldmatrix.sync.aligned.m8n8.x4.shared.b16 {%0,%1,%2,%3}, [%4];"
                 : "=r"(r0), "=r"(r1), "=r"(r2), "=r"(r3) : "r"(addr));
}
// packed f32x2 ops (sm_100+ base feature)
#define FMA2(d, a, b, c) \
    asm("fma.rn.f32x2 %0, %1, %2, %3;" : "=l"(d) : "l"(a), "l"(b), "l"(c))
#define MUL2(d, a, b) \
    asm("mul.rn.f32x2 %0, %1, %2;" : "=l"(d) : "l"(a), "l"(b))
#define PACK2(d, s) \
    asm("mov.b64 %0, {%1, %1};" : "=l"(d) : "f"(s))
#define UNPACK2(lo, hi, v) \
    asm("mov.b64 {%0, %1}, %2;" : "=f"(lo), "=f"(hi) : "l"(v))

__device__ __forceinline__ float fast_sigmoid(float x) {
    return __fdividef(1.f, 1.f + __expf(-x));
}

// ================= split kernel: fp32 -> bf16 hi + bf16 lo =================
__global__ __launch_bounds__(256) void split_kernel(
    const float* __restrict__ in, __nv_bfloat16* __restrict__ hi,
    __nv_bfloat16* __restrict__ lo, int n4)
{
    int i = blockIdx.x * 256 + threadIdx.x;
    if (i >= n4) return;
    float4 v = ((const float4*)in)[i];
    uint32_t h01 = pack_bf16(v.x, v.y);
    uint32_t h23 = pack_bf16(v.z, v.w);
    float h0 = __uint_as_float(h01 << 16);
    float h1 = __uint_as_float(h01 & 0xffff0000u);
    float h2 = __uint_as_float(h23 << 16);
    float h3 = __uint_as_float(h23 & 0xffff0000u);
    uint32_t l01 = pack_bf16(v.x - h0, v.y - h1);
    uint32_t l23 = pack_bf16(v.z - h2, v.w - h3);
    ((uint2*)hi)[i] = make_uint2(h01, h23);
    ((uint2*)lo)[i] = make_uint2(l01, l23);
}

// ================= GEMM (bf16x3, ldmatrix + 3-stage cp.async) ==============
#define GB_M 128
#define GB_N 128
#define GB_K 32
#define GB_STAGE 32768
#define GB_SMEM_BYTES (3 * GB_STAGE)   // 98304

__global__ __launch_bounds__(256, 2) void gemm_bf16x3(
    const __nv_bfloat16* __restrict__ Ahi, const __nv_bfloat16* __restrict__ Alo,
    const __nv_bfloat16* __restrict__ Bhi, const __nv_bfloat16* __restrict__ Blo,
    float* __restrict__ C, int M, int N, int K)
{
    extern __shared__ char smem[];
    const uint32_t sbase = smem_to_u32(smem);
    const int tid = threadIdx.x;
    const int bm  = blockIdx.y * GB_M;
    const int bn  = blockIdx.x * GB_N;
    const int nch = K / GB_K;

    const int warp = tid >> 5;
    const int lane = tid & 31;
    const int wm = warp >> 2;
    const int wn = warp & 3;
    const int lr = lane >> 2;
    const int lc = lane & 3;

    float acc[4][4][4];
    #pragma unroll
    for (int mt = 0; mt < 4; mt++)
        #pragma unroll
        for (int nt = 0; nt < 4; nt++)
            #pragma unroll
            for (int q = 0; q < 4; q++) acc[mt][nt][q] = 0.f;

    auto load_stage = [&](int buf, int kt) {
        #pragma unroll
        for (int i = 0; i < 8; i++) {
            int idx = tid + i * 256;
            int cq = idx & 3;
            int r  = (idx >> 2) & 127;
            int t  = idx >> 9;
            uint32_t so = sbase + (uint32_t)buf * GB_STAGE + (uint32_t)t * 8192 +
                          (uint32_t)r * 64 + (uint32_t)((cq ^ ((r >> 1) & 3)) * 16);
            const __nv_bfloat16* g;
            if (t == 0)      g = Ahi + (size_t)(bm + r) * K;
            else if (t == 1) g = Alo + (size_t)(bm + r) * K;
            else {
                int gn = bn + r; if (gn >= N) gn = N - 1;
                g = (t == 2 ? Bhi : Blo) + (size_t)gn * K;
            }
            g += kt + cq * 8;
            asm volatile("cp.async.cg.shared.global [%0], [%1], 16;"
                         :: "r"(so), "l"(g));
        }
        asm volatile("cp.async.commit_group;");
    };

    load_stage(0, 0);
    if (nch > 1) load_stage(1, GB_K);

    const int rowA = wm * 64 + ((lane >> 3) & 1) * 8 + (lane & 7);
    const int rowB = wn * 32 + ((lane >> 4) & 1) * 8 + (lane & 7);
    const int sel  = ((lane & 7) >> 1) & 3;
    const int cAq  = (lane >> 4) & 1;
    const int cBq  = (lane >> 3) & 1;

    for (int c = 0; c < nch; c++) {
        if (c == nch - 1) asm volatile("cp.async.wait_group 0;");
        else              asm volatile("cp.async.wait_group 1;");
        __syncthreads();
        if (c + 2 < nch) load_stage((c + 2) % 3, (c + 2) * GB_K);

        const uint32_t stg = sbase + (uint32_t)(c % 3) * GB_STAGE;
        const uint32_t baseAhi = stg + (uint32_t)rowA * 64;
        const uint32_t baseAlo = baseAhi + 8192;
        const uint32_t baseBhi = stg + 16384 + (uint32_t)rowB * 64;
        const uint32_t baseBlo = baseBhi + 8192;

        #pragma unroll
        for (int ks = 0; ks < 2; ks++) {
            const uint32_t cAo = (uint32_t)(((ks * 2 + cAq) ^ sel) * 16);
            const uint32_t cBo = (uint32_t)(((ks * 2 + cBq) ^ sel) * 16);

            uint32_t bh[4][2], bl[4][2];
            #pragma unroll
            for (int ntp = 0; ntp < 2; ntp++) {
                uint32_t r0, r1, r2, r3;
                ldsm_x4(r0, r1, r2, r3, baseBhi + ntp * 1024 + cBo);
                bh[ntp*2][0] = r0; bh[ntp*2][1] = r1;
                bh[ntp*2+1][0] = r2; bh[ntp*2+1][1] = r3;
                ldsm_x4(r0, r1, r2, r3, baseBlo + ntp * 1024 + cBo);
                bl[ntp*2][0] = r0; bl[ntp*2][1] = r1;
                bl[ntp*2+1][0] = r2; bl[ntp*2+1][1] = r3;
            }
            #pragma unroll
            for (int mt = 0; mt < 4; mt++) {
                uint32_t ah[4], al[4];
                ldsm_x4(ah[0], ah[1], ah[2], ah[3], baseAhi + mt * 1024 + cAo);
                ldsm_x4(al[0], al[1], al[2], al[3], baseAlo + mt * 1024 + cAo);
                #pragma unroll
                for (int nt = 0; nt < 4; nt++) {
                    mma_bf16(acc[mt][nt], ah, bh[nt]);
                    mma_bf16(acc[mt][nt], ah, bl[nt]);
                    mma_bf16(acc[mt][nt], al, bh[nt]);
                }
            }
        }
    }

    #pragma unroll
    for (int mt = 0; mt < 4; mt++) {
        int row = bm + wm * 64 + mt * 16 + lr;
        #pragma unroll
        for (int nt = 0; nt < 4; nt++) {
            int col = bn + wn * 32 + nt * 8 + lc * 2;
            if (col < N) {
                *(float2*)(C + (size_t)row * N + col) =
                    make_float2(acc[mt][nt][0], acc[mt][nt][1]);
                *(float2*)(C + (size_t)(row + 8) * N + col) =
                    make_float2(acc[mt][nt][2], acc[mt][nt][3]);
            }
        }
    }
}

// ---------------- depthwise causal conv (k=4) + bias + SiLU ----------------
__global__ __launch_bounds__(256) void conv_kernel(
    const float* __restrict__ zx, const float* __restrict__ cw,
    const float* __restrict__ cb, float* __restrict__ xbc)
{
    int c = blockIdx.x * 256 + threadIdx.x;
    if (c >= CONV_DIM) return;
    int strip = blockIdx.y;
    int b     = blockIdx.z;
    int l0    = strip * 256;

    float w0 = cw[c*4+0], w1 = cw[c*4+1], w2 = cw[c*4+2], w3 = cw[c*4+3];
    float bias = cb[c];

    size_t colbase = (size_t)D_INNER + c;
    size_t rb = (size_t)b * SEQLEN;

    float xm3 = (l0-3 >= 0) ? zx[(rb + l0-3) * D_IN_PROJ + colbase] : 0.f;
    float xm2 = (l0-2 >= 0) ? zx[(rb + l0-2) * D_IN_PROJ + colbase] : 0.f;
    float xm1 = (l0-1 >= 0) ? zx[(rb + l0-1) * D_IN_PROJ + colbase] : 0.f;

    for (int l = l0; l < l0 + 256; l++) {
        float xv = zx[(rb + l) * D_IN_PROJ + colbase];
        float a = bias;
        a = fmaf(w0, xm3, a);
        a = fmaf(w1, xm2, a);
        a = fmaf(w2, xm1, a);
        a = fmaf(w3, xv,  a);
        float sv = a * fast_sigmoid(a);
        xbc[(rb + l) * CONV_DIM + c] = sv;
        xm3 = xm2; xm2 = xm1; xm1 = xv;
    }
}

// ---------------- dt -> softplus -> decay ----------------------------------
__global__ __launch_bounds__(256) void decay_kernel(
    const float* __restrict__ zx, const float* __restrict__ dt_bias,
    const float* __restrict__ A_log, float* __restrict__ dec)
{
    int idx = blockIdx.x * 256 + threadIdx.x;
    if (idx >= NROWS * NHEADS) return;
    int r = idx >> 4;
    int h = idx & 15;
    float raw = zx[(size_t)r * D_IN_PROJ + (D_IN_PROJ - NHEADS) + h] + dt_bias[h];
    float sp  = (raw > 20.f) ? raw : log1pf(expf(raw));
    float A   = -expf(A_log[h]);
    dec[idx]  = expf(sp * A);
}

// ---------------- chunked scan: stage 1 (thread=p, f32x2 math) -------------
// grid (c=NCHUNK, h, b) = 512 blocks (single wave), 128 threads.
__global__ __launch_bounds__(128) void scan_local_kernel(
    const float* __restrict__ xbc, const float* __restrict__ dec,
    const float* __restrict__ Dvec, float* __restrict__ yout,
    float* __restrict__ states, float* __restrict__ cumout)
{
    const int c = blockIdx.x;
    const int h = blockIdx.y;
    const int b = blockIdx.z;
    const int p = threadIdx.x;

    __shared__ __align__(16) float sx [2][SBLK][128];
    __shared__ __align__(16) float sBC[2][SBLK][128];
    __shared__ __align__(16) float sdec[2][SBLK];

    unsigned long long s2[32];
    #pragma unroll
    for (int q = 0; q < 32; q++) s2[q] = 0ull;

    const float Dh = Dvec[h];
    const size_t base = (size_t)b * SEQLEN + (size_t)c * LCHUNK;
    const int xcol = h * HEADDIM;
    const size_t cumbase = (size_t)(((b * NHEADS + h) * NCHUNK) + c) * LCHUNK;

    const uint32_t sx_a   = smem_to_u32(sx);
    const uint32_t sbc_a  = smem_to_u32(sBC);
    const uint32_t sdec_a = smem_to_u32(sdec);

    auto stage = [&](int buf, int l0) {
        #pragma unroll
        for (int i = 0; i < 8; i++) {
            int idx = p + i * 128;
            int stp = idx >> 6;
            int q   = idx & 63;
            size_t row = (base + l0 + stp) * CONV_DIM;
            const float* src;
            uint32_t dst;
            if (q < 32) {
                src = xbc + row + xcol + q * 4;
                dst = sx_a + (uint32_t)((buf * SBLK + stp) * 128 + q * 4) * 4;
            } else {
                src = xbc + row + D_INNER + (q - 32) * 4;
                dst = sbc_a + (uint32_t)((buf * SBLK + stp) * 128 + (q - 32) * 4) * 4;
            }
            asm volatile("cp.async.cg.shared.global [%0], [%1], 16;"
                         :: "r"(dst), "l"(src));
        }
        if (p < SBLK) {
            const float* src = dec + (base + l0 + p) * NHEADS + h;
            uint32_t dst = sdec_a + (uint32_t)(buf * SBLK + p) * 4;
            asm volatile("cp.async.ca.shared.global [%0], [%1], 4;"
                         :: "r"(dst), "l"(src));
        }
        asm volatile("cp.async.commit_group;");
    };

    stage(0, 0);
    stage(1, SBLK);

    float cum = 1.f;

    for (int blk = 0; blk < NBLK; blk++) {
        if (blk >= NBLK - 2) asm volatile("cp.async.wait_group 0;");
        else                 asm volatile("cp.async.wait_group 1;");
        __syncthreads();
        const int cur = blk & 1;
        const int l0 = blk * SBLK;

        #pragma unroll 4
        for (int j = 0; j < SBLK; j++) {
            const float dcy = sdec[cur][j];
            const float xv  = sx[cur][j][p];
            unsigned long long dpack, xpack;
            PACK2(dpack, dcy);
            PACK2(xpack, xv);
            const ulonglong2* B2 = (const ulonglong2*)&sBC[cur][j][0];
            const ulonglong2* C2 = (const ulonglong2*)&sBC[cur][j][64];
            unsigned long long ya0 = 0ull, ya1 = 0ull, ya2 = 0ull, ya3 = 0ull;
            unsigned long long yb0 = 0ull, yb1 = 0ull, yb2 = 0ull, yb3 = 0ull;
            #pragma unroll
            for (int q = 0; q < 16; q += 4) {
                ulonglong2 bv0 = B2[q],   bv1 = B2[q+1];
                ulonglong2 bv2 = B2[q+2], bv3 = B2[q+3];
                ulonglong2 cv0 = C2[q],   cv1 = C2[q+1];
                ulonglong2 cv2 = C2[q+2], cv3 = C2[q+3];
                unsigned long long t;
                MUL2(t, bv0.x, xpack); FMA2(s2[2*q],   s2[2*q],   dpack, t);
                FMA2(ya0, s2[2*q],   cv0.x, ya0);
                MUL2(t, bv0.y, xpack); FMA2(s2[2*q+1], s2[2*q+1], dpack, t);
                FMA2(yb0, s2[2*q+1], cv0.y, yb0);
                MUL2(t, bv1.x, xpack); FMA2(s2[2*q+2], s2[2*q+2], dpack, t);
                FMA2(ya1, s2[2*q+2], cv1.x, ya1);
                MUL2(t, bv1.y, xpack); FMA2(s2[2*q+3], s2[2*q+3], dpack, t);
                FMA2(yb1, s2[2*q+3], cv1.y, yb1);
                MUL2(t, bv2.x, xpack); FMA2(s2[2*q+4], s2[2*q+4], dpack, t);
                FMA2(ya2, s2[2*q+4], cv2.x, ya2);
                MUL2(t, bv2.y, xpack); FMA2(s2[2*q+5], s2[2*q+5], dpack, t);
                FMA2(yb2, s2[2*q+5], cv2.y, yb2);
                MUL2(t, bv3.x, xpack); FMA2(s2[2*q+6], s2[2*q+6], dpack, t);
                FMA2(ya3, s2[2*q+6], cv3.x, ya3);
                MUL2(t, bv3.y, xpack); FMA2(s2[2*q+7], s2[2*q+7], dpack, t);
                FMA2(yb3, s2[2*q+7], cv3.y, yb3);
            }
            float a0, a1, b0, b1, acc = 0.f;
            UNPACK2(a0, a1, ya0); acc += a0 + a1;
            UNPACK2(a0, a1, ya1); acc += a0 + a1;
            UNPACK2(a0, a1, ya2); acc += a0 + a1;
            UNPACK2(a0, a1, ya3); acc += a0 + a1;
            UNPACK2(b0, b1, yb0); acc += b0 + b1;
            UNPACK2(b0, b1, yb1); acc += b0 + b1;
            UNPACK2(b0, b1, yb2); acc += b0 + b1;
            UNPACK2(b0, b1, yb3); acc += b0 + b1;
            yout[(base + l0 + j) * D_INNER + xcol + p] = fmaf(Dh, xv, acc);
            if (p == 0) {
                cum *= dcy;
                cumout[cumbase + l0 + j] = cum;
            }
        }
        __syncthreads();
        if (blk + 2 < NBLK) stage(cur, (blk + 2) * SBLK);
    }

    float* st = states +
        ((size_t)(((b * NHEADS + h) * NCHUNK) + c) * HEADDIM + p) * D_STATE;
    #pragma unroll
    for (int q = 0; q < 16; q++) {
        ulonglong2 v;
        v.x = s2[2*q];
        v.y = s2[2*q+1];
        *(ulonglong2*)(st + q * 4) = v;
    }
}

// ---------------- chunked scan: stage 2 (combine, p-sliced) ----------------
// grid (h=16, b=2, slice=8), 256 threads; each block owns 1024 floats of the
// 8192-float state stride and walks chunks serially (in-place -> S_entry).
__global__ __launch_bounds__(256) void scan_combine_kernel(
    float* __restrict__ states, const float* __restrict__ cum)
{
    const int h   = blockIdx.x;
    const int b   = blockIdx.y;
    const int sl  = blockIdx.z;        // 0..7
    const int tid = threadIdx.x;

    __shared__ float dprod[NCHUNK];
    if (tid < NCHUNK)
        dprod[tid] = cum[(size_t)(((b * NHEADS + h) * NCHUNK) + tid) * LCHUNK + LCHUNK - 1];
    __syncthreads();

    const size_t chunk_stride = (size_t)HEADDIM * D_STATE;        // 8192 floats
    float* base = states + (size_t)((b * NHEADS + h) * NCHUNK) * chunk_stride
                         + (size_t)sl * 1024;

    float4 e = make_float4(0.f, 0.f, 0.f, 0.f);
    const int idx = tid;               // 256 float4 = 1024 floats

    for (int c = 0; c < NCHUNK; c++) {
        float d = dprod[c];
        float4* p = (float4*)(base + c * chunk_stride);
        float4 s = p[idx];
        p[idx] = e;
        e.x = fmaf(e.x, d, s.x);
        e.y = fmaf(e.y, d, s.y);
        e.z = fmaf(e.z, d, s.z);
        e.w = fmaf(e.w, d, s.w);
    }
}

// ---------------- chunked scan: stage 3 (smem-staged, f32x2) ---------------
__global__ __launch_bounds__(128) void scan_fix_kernel(
    const float* __restrict__ states, const float* __restrict__ cum,
    const float* __restrict__ xbc, float* __restrict__ yout)
{
    const int c = blockIdx.x;
    if (c == 0) return;
    const int h = blockIdx.y;
    const int b = blockIdx.z;
    const int p = threadIdx.x;

    __shared__ __align__(16) float sC  [2][SBLK][64];
    __shared__ __align__(16) float scum[2][SBLK];

    ulonglong2 ent2[16];
    const float* st = states +
        ((size_t)(((b * NHEADS + h) * NCHUNK) + c) * HEADDIM + p) * D_STATE;
    #pragma unroll
    for (int q = 0; q < 16; q++) ent2[q] = *(const ulonglong2*)(st + q * 4);

    const size_t base = (size_t)b * SEQLEN + (size_t)c * LCHUNK;
    const size_t cumbase = (size_t)(((b * NHEADS + h) * NCHUNK) + c) * LCHUNK;
    const int ycol = h * HEADDIM + p;

    const uint32_t sC_a   = smem_to_u32(sC);
    const uint32_t scum_a = smem_to_u32(scum);

    auto stage = [&](int buf, int l0) {
        #pragma unroll
        for (int i = 0; i < 2; i++) {
            int idx = p + i * 128;
            int stp = idx >> 4;
            int q   = idx & 15;
            const float* src = xbc + (base + l0 + stp) * CONV_DIM + D_INNER + 64 + q * 4;
            uint32_t dst = sC_a + (uint32_t)((buf * SBLK + stp) * 64 + q * 4) * 4;
            asm volatile("cp.async.cg.shared.global [%0], [%1], 16;"
                         :: "r"(dst), "l"(src));
        }
        if (p < SBLK) {
            const float* src = cum + cumbase + l0 + p;
            uint32_t dst = scum_a + (uint32_t)(buf * SBLK + p) * 4;
            asm volatile("cp.async.ca.shared.global [%0], [%1], 4;"
                         :: "r"(dst), "l"(src));
        }
        asm volatile("cp.async.commit_group;");
    };

    stage(0, 0);
    stage(1, SBLK);

    for (int blk = 0; blk < NBLK; blk++) {
        if (blk >= NBLK - 2) asm volatile("cp.async.wait_group 0;");
        else                 asm volatile("cp.async.wait_group 1;");
        __syncthreads();
        const int cur = blk & 1;
        const int l0 = blk * SBLK;

        #pragma unroll 4
        for (int j = 0; j < SBLK; j++) {
            const ulonglong2* C2 = (const ulonglong2*)&sC[cur][j][0];
            unsigned long long a0 = 0ull, a1 = 0ull, b0 = 0ull, b1 = 0ull;
            #pragma unroll
            for (int q = 0; q < 16; q += 2) {
                ulonglong2 cv0 = C2[q];
                ulonglong2 cv1 = C2[q+1];
                FMA2(a0, ent2[q].x,   cv0.x, a0);
                FMA2(b0, ent2[q].y,   cv0.y, b0);
                FMA2(a1, ent2[q+1].x, cv1.x, a1);
                FMA2(b1, ent2[q+1].y, cv1.y, b1);
            }
            float p0, p1, dot = 0.f;
            UNPACK2(p0, p1, a0); dot += p0 + p1;
            UNPACK2(p0, p1, a1); dot += p0 + p1;
            UNPACK2(p0, p1, b0); dot += p0 + p1;
            UNPACK2(p0, p1, b1); dot += p0 + p1;
            float cm = scum[cur][j];
            float* yp = yout + (base + l0 + j) * D_INNER + ycol;
            *yp = fmaf(cm, dot, *yp);
        }
        __syncthreads();
        if (blk + 2 < NBLK) stage(cur, (blk + 2) * SBLK);
    }
}

// ---------------- RMSNorm + gate, fused bf16 split output ------------------
__global__ __launch_bounds__(256) void rms_gate_kernel(
    const float* __restrict__ y, const float* __restrict__ zx,
    const float* __restrict__ rmsw,
    __nv_bfloat16* __restrict__ ygh, __nv_bfloat16* __restrict__ ygl)
{
    int r = blockIdx.x;
    const float*  yr = y  + (size_t)r * D_INNER;
    const float*  zr = zx + (size_t)r * D_IN_PROJ;
    const float4* y4 = (const float4*)yr;

    int tid = threadIdx.x;
    float ss = 0.f;
    #pragma unroll
    for (int i = 0; i < 2; i++) {
        float4 v = y4[tid + i * 256];
        ss += v.x*v.x + v.y*v.y + v.z*v.z + v.w*v.w;
    }
    #pragma unroll
    for (int o = 16; o > 0; o >>= 1) ss += __shfl_xor_sync(0xffffffffu, ss, o);
    __shared__ float red[8];
    if ((tid & 31) == 0) red[tid >> 5] = ss;
    __syncthreads();
    if (tid == 0) {
        float t = 0.f;
        #pragma unroll
        for (int i = 0; i < 8; i++) t += red[i];
        red[0] = rsqrtf(t * (1.f / D_INNER) + RMS_EPS);
    }
    __syncthreads();
    float rs = red[0];

    const float4* z4 = (const float4*)zr;
    const float4* w4 = (const float4*)rmsw;
    uint2* gh = (uint2*)(ygh + (size_t)r * D_INNER);
    uint2* gl = (uint2*)(ygl + (size_t)r * D_INNER);
    #pragma unroll
    for (int i = 0; i < 2; i++) {
        int c = tid + i * 256;
        float4 v = y4[c];
        float4 z = z4[c];
        float4 w = w4[c];
        float4 o;
        o.x = v.x * rs * w.x * fast_sigmoid(z.x);
        o.y = v.y * rs * w.y * fast_sigmoid(z.y);
        o.z = v.z * rs * w.z * fast_sigmoid(z.z);
        o.w = v.w * rs * w.w * fast_sigmoid(z.w);
        uint32_t h01 = pack_bf16(o.x, o.y);
        uint32_t h23 = pack_bf16(o.z, o.w);
        float h0 = __uint_as_float(h01 << 16);
        float h1 = __uint_as_float(h01 & 0xffff0000u);
        float h2 = __uint_as_float(h23 << 16);
        float h3 = __uint_as_float(h23 & 0xffff0000u);
        gh[c] = make_uint2(h01, h23);
        gl[c] = make_uint2(pack_bf16(o.x - h0, o.y - h1),
                           pack_bf16(o.z - h2, o.w - h3));
    }
}

// ---------------- launcher -------------------------------------------------
extern "C" void kernel_launch(void* const* d_in, const int* in_sizes, int n_in,
                              void* d_out, int out_size)
{
    const float* u        = (const float*)d_in[0];
    const float* in_proj  = (const float*)d_in[1];
    const float* conv_w   = (const float*)d_in[2];
    const float* conv_b   = (const float*)d_in[3];
    const float* dt_bias  = (const float*)d_in[4];
    const float* A_log    = (const float*)d_in[5];
    const float* Dv       = (const float*)d_in[6];
    const float* rms_w    = (const float*)d_in[7];
    const float* out_w    = (const float*)d_in[8];
    float* out = (float*)d_out;

    float *zx, *xbc, *dec, *y, *st, *cum;
    __nv_bfloat16 *uhi, *ulo, *w1hi, *w1lo, *w2hi, *w2lo, *yghi, *yglo;
    cudaGetSymbolAddress((void**)&zx,  g_zx);
    cudaGetSymbolAddress((void**)&xbc, g_xbc);
    cudaGetSymbolAddress((void**)&dec, g_dec);
    cudaGetSymbolAddress((void**)&y,   g_y);
    cudaGetSymbolAddress((void**)&st,  g_st);
    cudaGetSymbolAddress((void**)&cum, g_cum);
    cudaGetSymbolAddress((void**)&uhi,  g_uhi);
    cudaGetSymbolAddress((void**)&ulo,  g_ulo);
    cudaGetSymbolAddress((void**)&w1hi, g_w1hi);
    cudaGetSymbolAddress((void**)&w1lo, g_w1lo);
    cudaGetSymbolAddress((void**)&w2hi, g_w2hi);
    cudaGetSymbolAddress((void**)&w2lo, g_w2lo);
    cudaGetSymbolAddress((void**)&yghi, g_yghi);
    cudaGetSymbolAddress((void**)&yglo, g_yglo);

    cudaFuncSetAttribute(gemm_bf16x3,
        cudaFuncAttributeMaxDynamicSharedMemorySize, GB_SMEM_BYTES);

    // 0) split fp32 operands into bf16 hi/lo
    {
        int n4u = NROWS * D_MODEL / 4;
        split_kernel<<<(n4u + 255) / 256, 256>>>(u, uhi, ulo, n4u);
        int n4w1 = D_IN_PROJ * D_MODEL / 4;
        split_kernel<<<(n4w1 + 255) / 256, 256>>>(in_proj, w1hi, w1lo, n4w1);
        int n4w2 = D_MODEL * D_INNER / 4;
        split_kernel<<<(n4w2 + 255) / 256, 256>>>(out_w, w2hi, w2lo, n4w2);
    }
    // 1) in_proj GEMM
    {
        dim3 grid((D_IN_PROJ + GB_N - 1) / GB_N, NROWS / GB_M);
        gemm_bf16x3<<<grid, 256, GB_SMEM_BYTES>>>(uhi, ulo, w1hi, w1lo, zx,
                                                  NROWS, D_IN_PROJ, D_MODEL);
    }
    // 2) conv + silu
    {
        dim3 grid((CONV_DIM + 255) / 256, SEQLEN / 256, BATCH);
        conv_kernel<<<grid, 256>>>(zx, conv_w, conv_b, xbc);
    }
    // 3) decay precompute
    decay_kernel<<<(NROWS * NHEADS + 255) / 256, 256>>>(zx, dt_bias, A_log, dec);
    // 4) chunked SSM scan
    {
        dim3 grid(NCHUNK, NHEADS, BATCH);
        scan_local_kernel<<<grid, 128>>>(xbc, dec, Dv, y, st, cum);
    }
    {
        dim3 grid(NHEADS, BATCH, 8);
        scan_combine_kernel<<<grid, 256>>>(st, cum);
    }
    {
        dim3 grid(NCHUNK, NHEADS, BATCH);
        scan_fix_kernel<<<grid, 128>>>(st, cum, xbc, y);
    }
    // 5) rmsnorm + gate (+ bf16 split)
    rms_gate_kernel<<<NROWS, 256>>>(y, zx, rms_w, yghi, yglo);
    // 6) out_proj GEMM
    {
        dim3 grid(D_MODEL / GB_N, NROWS / GB_M);
        gemm_bf16x3<<<grid, 256, GB_SMEM_BYTES>>>(yghi, yglo, w2hi, w2lo, out,
                                                  NROWS, D_MODEL, D_INNER);
    }
}

// round 12
// speedup vs baseline: 1.3255x; 1.0124x over previous
#include <cuda_runtime.h>
#include <cuda_bf16.h>
#include <cstdint>
#include <math.h>

// ---------------- problem constants ----------------
#define D_MODEL   1024
#define D_INNER   2048
#define D_STATE   64
#define HEADDIM   128
#define NHEADS    16
#define D_CONV    4
#define CONV_DIM  2176
#define D_IN_PROJ 4240
#define BATCH     2
#define SEQLEN    4096
#define NROWS     (BATCH*SEQLEN)  // 8192
#define RMS_EPS   1e-5f

#define LCHUNK    256
#define NCHUNK    (SEQLEN/LCHUNK)   // 16
#define SBLK      16                // staging block (steps)
#define NBLK      (LCHUNK/SBLK)     // 16

// ---------------- scratch ----------------
__device__ float g_zx [(size_t)NROWS * D_IN_PROJ];
__device__ float g_xbc[(size_t)NROWS * CONV_DIM];
__device__ float g_dec[(size_t)NROWS * NHEADS];
__device__ float g_y  [(size_t)NROWS * D_INNER];
__device__ float g_st [(size_t)BATCH * NHEADS * NCHUNK * HEADDIM * D_STATE];
__device__ float g_cum[(size_t)BATCH * NHEADS * NCHUNK * LCHUNK];
__device__ __nv_bfloat16 g_uhi [(size_t)NROWS * D_MODEL];
__device__ __nv_bfloat16 g_ulo [(size_t)NROWS * D_MODEL];
__device__ __nv_bfloat16 g_w1hi[(size_t)D_IN_PROJ * D_MODEL];
__device__ __nv_bfloat16 g_w1lo[(size_t)D_IN_PROJ * D_MODEL];
__device__ __nv_bfloat16 g_w2hi[(size_t)D_MODEL * D_INNER];
__device__ __nv_bfloat16 g_w2lo[(size_t)D_MODEL * D_INNER];
__device__ __nv_bfloat16 g_yghi[(size_t)NROWS * D_INNER];
__device__ __nv_bfloat16 g_yglo[(size_t)NROWS * D_INNER];

// ================= helpers =================
__device__ __forceinline__ uint32_t smem_to_u32(const void* p) {
    uint32_t a;
    asm("{ .reg .u64 t; cvta.to.shared.u64 t, %1; cvt.u32.u64 %0, t; }"
        : "=r"(a) : "l"(p));
    return a;
}
__device__ __forceinline__ uint32_t pack_bf16(float lo_elem, float hi_elem) {
    uint32_t r;
    asm("cvt.rn.bf16x2.f32 %0, %1, %2;" : "=r"(r) : "f"(hi_elem), "f"(lo_elem));
    return r;
}
__device__ __forceinline__ void mma_bf16(float* d, const uint32_t* a,
                                         const uint32_t* b) {
    asm volatile(
        "mma.sync.aligned.m16n8k16.row.col.f32.bf16.bf16.f32 "
        "{%0,%1,%2,%3},{%4,%5,%6,%7},{%8,%9},{%0,%1,%2,%3};"
        : "+f"(d[0]), "+f"(d[1]), "+f"(d[2]), "+f"(d[3])
        : "r"(a[0]), "r"(a[1]), "r"(a[2]), "r"(a[3]), "r"(b[0]), "r"(b[1]));
}
__device__ __forceinline__ void ldsm_x4(uint32_t& r0, uint32_t& r1,
                                        uint32_t& r2, uint32_t& r3,
                                        uint32_t addr) {
    asm volatile("ldmatrix.sync.aligned.m8n8.x4.shared.b16 {%0,%1,%2,%3}, [%4];"
                 : "=r"(r0), "=r"(r1), "=r"(r2), "=r"(r3) : "r"(addr));
}
// packed f32x2 ops (sm_100+ base feature)
#define FMA2(d, a, b, c) \
    asm("fma.rn.f32x2 %0, %1, %2, %3;" : "=l"(d) : "l"(a), "l"(b), "l"(c))
#define MUL2(d, a, b) \
    asm("mul.rn.f32x2 %0, %1, %2;" : "=l"(d) : "l"(a), "l"(b))
#define PACK2(d, s) \
    asm("mov.b64 %0, {%1, %1};" : "=l"(d) : "f"(s))
#define UNPACK2(lo, hi, v) \
    asm("mov.b64 {%0, %1}, %2;" : "=f"(lo), "=f"(hi) : "l"(v))

__device__ __forceinline__ float fast_sigmoid(float x) {
    return __fdividef(1.f, 1.f + __expf(-x));
}

// ================= split kernel: fp32 -> bf16 hi + bf16 lo =================
__global__ __launch_bounds__(256) void split_kernel(
    const float* __restrict__ in, __nv_bfloat16* __restrict__ hi,
    __nv_bfloat16* __restrict__ lo, int n4)
{
    int i = blockIdx.x * 256 + threadIdx.x;
    if (i >= n4) return;
    float4 v = ((const float4*)in)[i];
    uint32_t h01 = pack_bf16(v.x, v.y);
    uint32_t h23 = pack_bf16(v.z, v.w);
    float h0 = __uint_as_float(h01 << 16);
    float h1 = __uint_as_float(h01 & 0xffff0000u);
    float h2 = __uint_as_float(h23 << 16);
    float h3 = __uint_as_float(h23 & 0xffff0000u);
    uint32_t l01 = pack_bf16(v.x - h0, v.y - h1);
    uint32_t l23 = pack_bf16(v.z - h2, v.w - h3);
    ((uint2*)hi)[i] = make_uint2(h01, h23);
    ((uint2*)lo)[i] = make_uint2(l01, l23);
}

// ================= GEMM (bf16x3, ldmatrix + 3-stage cp.async) ==============
#define GB_M 128
#define GB_N 128
#define GB_K 32
#define GB_STAGE 32768
#define GB_SMEM_BYTES (3 * GB_STAGE)   // 98304

__global__ __launch_bounds__(256, 2) void gemm_bf16x3(
    const __nv_bfloat16* __restrict__ Ahi, const __nv_bfloat16* __restrict__ Alo,
    const __nv_bfloat16* __restrict__ Bhi, const __nv_bfloat16* __restrict__ Blo,
    float* __restrict__ C, int M, int N, int K, int ldc)
{
    extern __shared__ char smem[];
    const uint32_t sbase = smem_to_u32(smem);
    const int tid = threadIdx.x;
    const int bm  = blockIdx.y * GB_M;
    const int bn  = blockIdx.x * GB_N;
    const int nch = K / GB_K;

    const int warp = tid >> 5;
    const int lane = tid & 31;
    const int wm = warp >> 2;
    const int wn = warp & 3;
    const int lr = lane >> 2;
    const int lc = lane & 3;

    float acc[4][4][4];
    #pragma unroll
    for (int mt = 0; mt < 4; mt++)
        #pragma unroll
        for (int nt = 0; nt < 4; nt++)
            #pragma unroll
            for (int q = 0; q < 4; q++) acc[mt][nt][q] = 0.f;

    auto load_stage = [&](int buf, int kt) {
        #pragma unroll
        for (int i = 0; i < 8; i++) {
            int idx = tid + i * 256;
            int cq = idx & 3;
            int r  = (idx >> 2) & 127;
            int t  = idx >> 9;
            uint32_t so = sbase + (uint32_t)buf * GB_STAGE + (uint32_t)t * 8192 +
                          (uint32_t)r * 64 + (uint32_t)((cq ^ ((r >> 1) & 3)) * 16);
            const __nv_bfloat16* g;
            if (t == 0)      g = Ahi + (size_t)(bm + r) * K;
            else if (t == 1) g = Alo + (size_t)(bm + r) * K;
            else {
                int gn = bn + r; if (gn >= N) gn = N - 1;
                g = (t == 2 ? Bhi : Blo) + (size_t)gn * K;
            }
            g += kt + cq * 8;
            asm volatile("cp.async.cg.shared.global [%0], [%1], 16;"
                         :: "r"(so), "l"(g));
        }
        asm volatile("cp.async.commit_group;");
    };

    load_stage(0, 0);
    if (nch > 1) load_stage(1, GB_K);

    const int rowA = wm * 64 + ((lane >> 3) & 1) * 8 + (lane & 7);
    const int rowB = wn * 32 + ((lane >> 4) & 1) * 8 + (lane & 7);
    const int sel  = ((lane & 7) >> 1) & 3;
    const int cAq  = (lane >> 4) & 1;
    const int cBq  = (lane >> 3) & 1;

    for (int c = 0; c < nch; c++) {
        if (c == nch - 1) asm volatile("cp.async.wait_group 0;");
        else              asm volatile("cp.async.wait_group 1;");
        __syncthreads();
        if (c + 2 < nch) load_stage((c + 2) % 3, (c + 2) * GB_K);

        const uint32_t stg = sbase + (uint32_t)(c % 3) * GB_STAGE;
        const uint32_t baseAhi = stg + (uint32_t)rowA * 64;
        const uint32_t baseAlo = baseAhi + 8192;
        const uint32_t baseBhi = stg + 16384 + (uint32_t)rowB * 64;
        const uint32_t baseBlo = baseBhi + 8192;

        #pragma unroll
        for (int ks = 0; ks < 2; ks++) {
            const uint32_t cAo = (uint32_t)(((ks * 2 + cAq) ^ sel) * 16);
            const uint32_t cBo = (uint32_t)(((ks * 2 + cBq) ^ sel) * 16);

            uint32_t bh[4][2], bl[4][2];
            #pragma unroll
            for (int ntp = 0; ntp < 2; ntp++) {
                uint32_t r0, r1, r2, r3;
                ldsm_x4(r0, r1, r2, r3, baseBhi + ntp * 1024 + cBo);
                bh[ntp*2][0] = r0; bh[ntp*2][1] = r1;
                bh[ntp*2+1][0] = r2; bh[ntp*2+1][1] = r3;
                ldsm_x4(r0, r1, r2, r3, baseBlo + ntp * 1024 + cBo);
                bl[ntp*2][0] = r0; bl[ntp*2][1] = r1;
                bl[ntp*2+1][0] = r2; bl[ntp*2+1][1] = r3;
            }
            #pragma unroll
            for (int mt = 0; mt < 4; mt++) {
                uint32_t ah[4], al[4];
                ldsm_x4(ah[0], ah[1], ah[2], ah[3], baseAhi + mt * 1024 + cAo);
                ldsm_x4(al[0], al[1], al[2], al[3], baseAlo + mt * 1024 + cAo);
                #pragma unroll
                for (int nt = 0; nt < 4; nt++) {
                    mma_bf16(acc[mt][nt], ah, bh[nt]);
                    mma_bf16(acc[mt][nt], ah, bl[nt]);
                    mma_bf16(acc[mt][nt], al, bh[nt]);
                }
            }
        }
    }

    #pragma unroll
    for (int mt = 0; mt < 4; mt++) {
        int row = bm + wm * 64 + mt * 16 + lr;
        #pragma unroll
        for (int nt = 0; nt < 4; nt++) {
            int col = bn + wn * 32 + nt * 8 + lc * 2;
            if (col + 1 < N) {
                *(float2*)(C + (size_t)row * ldc + col) =
                    make_float2(acc[mt][nt][0], acc[mt][nt][1]);
                *(float2*)(C + (size_t)(row + 8) * ldc + col) =
                    make_float2(acc[mt][nt][2], acc[mt][nt][3]);
            }
        }
    }
}

// ---------------- depthwise causal conv (k=4) + bias + SiLU ----------------
__global__ __launch_bounds__(256) void conv_kernel(
    const float* __restrict__ zx, const float* __restrict__ cw,
    const float* __restrict__ cb, float* __restrict__ xbc)
{
    int c = blockIdx.x * 256 + threadIdx.x;
    if (c >= CONV_DIM) return;
    int strip = blockIdx.y;
    int b     = blockIdx.z;
    int l0    = strip * 256;

    float w0 = cw[c*4+0], w1 = cw[c*4+1], w2 = cw[c*4+2], w3 = cw[c*4+3];
    float bias = cb[c];

    size_t colbase = (size_t)D_INNER + c;
    size_t rb = (size_t)b * SEQLEN;

    float xm3 = (l0-3 >= 0) ? zx[(rb + l0-3) * D_IN_PROJ + colbase] : 0.f;
    float xm2 = (l0-2 >= 0) ? zx[(rb + l0-2) * D_IN_PROJ + colbase] : 0.f;
    float xm1 = (l0-1 >= 0) ? zx[(rb + l0-1) * D_IN_PROJ + colbase] : 0.f;

    for (int l = l0; l < l0 + 256; l++) {
        float xv = zx[(rb + l) * D_IN_PROJ + colbase];
        float a = bias;
        a = fmaf(w0, xm3, a);
        a = fmaf(w1, xm2, a);
        a = fmaf(w2, xm1, a);
        a = fmaf(w3, xv,  a);
        float sv = a * fast_sigmoid(a);
        xbc[(rb + l) * CONV_DIM + c] = sv;
        xm3 = xm2; xm2 = xm1; xm1 = xv;
    }
}

// ---------------- dt -> softplus -> decay ----------------------------------
__global__ __launch_bounds__(256) void decay_kernel(
    const float* __restrict__ zx, const float* __restrict__ dt_bias,
    const float* __restrict__ A_log, float* __restrict__ dec)
{
    int idx = blockIdx.x * 256 + threadIdx.x;
    if (idx >= NROWS * NHEADS) return;
    int r = idx >> 4;
    int h = idx & 15;
    float raw = zx[(size_t)r * D_IN_PROJ + (D_IN_PROJ - NHEADS) + h] + dt_bias[h];
    float sp  = (raw > 20.f) ? raw : log1pf(expf(raw));
    float A   = -expf(A_log[h]);
    dec[idx]  = expf(sp * A);
}

// ---------------- chunked scan: stage 1 (thread=p, f32x2 math) -------------
__global__ __launch_bounds__(128) void scan_local_kernel(
    const float* __restrict__ xbc, const float* __restrict__ dec,
    const float* __restrict__ Dvec, float* __restrict__ yout,
    float* __restrict__ states, float* __restrict__ cumout)
{
    const int c = blockIdx.x;
    const int h = blockIdx.y;
    const int b = blockIdx.z;
    const int p = threadIdx.x;

    __shared__ __align__(16) float sx [2][SBLK][128];
    __shared__ __align__(16) float sBC[2][SBLK][128];
    __shared__ __align__(16) float sdec[2][SBLK];

    unsigned long long s2[32];
    #pragma unroll
    for (int q = 0; q < 32; q++) s2[q] = 0ull;

    const float Dh = Dvec[h];
    const size_t base = (size_t)b * SEQLEN + (size_t)c * LCHUNK;
    const int xcol = h * HEADDIM;
    const size_t cumbase = (size_t)(((b * NHEADS + h) * NCHUNK) + c) * LCHUNK;

    const uint32_t sx_a   = smem_to_u32(sx);
    const uint32_t sbc_a  = smem_to_u32(sBC);
    const uint32_t sdec_a = smem_to_u32(sdec);

    auto stage = [&](int buf, int l0) {
        #pragma unroll
        for (int i = 0; i < 8; i++) {
            int idx = p + i * 128;
            int stp = idx >> 6;
            int q   = idx & 63;
            size_t row = (base + l0 + stp) * CONV_DIM;
            const float* src;
            uint32_t dst;
            if (q < 32) {
                src = xbc + row + xcol + q * 4;
                dst = sx_a + (uint32_t)((buf * SBLK + stp) * 128 + q * 4) * 4;
            } else {
                src = xbc + row + D_INNER + (q - 32) * 4;
                dst = sbc_a + (uint32_t)((buf * SBLK + stp) * 128 + (q - 32) * 4) * 4;
            }
            asm volatile("cp.async.cg.shared.global [%0], [%1], 16;"
                         :: "r"(dst), "l"(src));
        }
        if (p < SBLK) {
            const float* src = dec + (base + l0 + p) * NHEADS + h;
            uint32_t dst = sdec_a + (uint32_t)(buf * SBLK + p) * 4;
            asm volatile("cp.async.ca.shared.global [%0], [%1], 4;"
                         :: "r"(dst), "l"(src));
        }
        asm volatile("cp.async.commit_group;");
    };

    stage(0, 0);
    stage(1, SBLK);

    float cum = 1.f;

    for (int blk = 0; blk < NBLK; blk++) {
        if (blk >= NBLK - 2) asm volatile("cp.async.wait_group 0;");
        else                 asm volatile("cp.async.wait_group 1;");
        __syncthreads();
        const int cur = blk & 1;
        const int l0 = blk * SBLK;

        #pragma unroll 4
        for (int j = 0; j < SBLK; j++) {
            const float dcy = sdec[cur][j];
            const float xv  = sx[cur][j][p];
            unsigned long long dpack, xpack;
            PACK2(dpack, dcy);
            PACK2(xpack, xv);
            const ulonglong2* B2 = (const ulonglong2*)&sBC[cur][j][0];
            const ulonglong2* C2 = (const ulonglong2*)&sBC[cur][j][64];
            unsigned long long ya0 = 0ull, ya1 = 0ull, ya2 = 0ull, ya3 = 0ull;
            unsigned long long yb0 = 0ull, yb1 = 0ull, yb2 = 0ull, yb3 = 0ull;
            #pragma unroll
            for (int q = 0; q < 16; q += 4) {
                ulonglong2 bv0 = B2[q],   bv1 = B2[q+1];
                ulonglong2 bv2 = B2[q+2], bv3 = B2[q+3];
                ulonglong2 cv0 = C2[q],   cv1 = C2[q+1];
                ulonglong2 cv2 = C2[q+2], cv3 = C2[q+3];
                unsigned long long t;
                MUL2(t, bv0.x, xpack); FMA2(s2[2*q],   s2[2*q],   dpack, t);
                FMA2(ya0, s2[2*q],   cv0.x, ya0);
                MUL2(t, bv0.y, xpack); FMA2(s2[2*q+1], s2[2*q+1], dpack, t);
                FMA2(yb0, s2[2*q+1], cv0.y, yb0);
                MUL2(t, bv1.x, xpack); FMA2(s2[2*q+2], s2[2*q+2], dpack, t);
                FMA2(ya1, s2[2*q+2], cv1.x, ya1);
                MUL2(t, bv1.y, xpack); FMA2(s2[2*q+3], s2[2*q+3], dpack, t);
                FMA2(yb1, s2[2*q+3], cv1.y, yb1);
                MUL2(t, bv2.x, xpack); FMA2(s2[2*q+4], s2[2*q+4], dpack, t);
                FMA2(ya2, s2[2*q+4], cv2.x, ya2);
                MUL2(t, bv2.y, xpack); FMA2(s2[2*q+5], s2[2*q+5], dpack, t);
                FMA2(yb2, s2[2*q+5], cv2.y, yb2);
                MUL2(t, bv3.x, xpack); FMA2(s2[2*q+6], s2[2*q+6], dpack, t);
                FMA2(ya3, s2[2*q+6], cv3.x, ya3);
                MUL2(t, bv3.y, xpack); FMA2(s2[2*q+7], s2[2*q+7], dpack, t);
                FMA2(yb3, s2[2*q+7], cv3.y, yb3);
            }
            float a0, a1, b0, b1, acc = 0.f;
            UNPACK2(a0, a1, ya0); acc += a0 + a1;
            UNPACK2(a0, a1, ya1); acc += a0 + a1;
            UNPACK2(a0, a1, ya2); acc += a0 + a1;
            UNPACK2(a0, a1, ya3); acc += a0 + a1;
            UNPACK2(b0, b1, yb0); acc += b0 + b1;
            UNPACK2(b0, b1, yb1); acc += b0 + b1;
            UNPACK2(b0, b1, yb2); acc += b0 + b1;
            UNPACK2(b0, b1, yb3); acc += b0 + b1;
            yout[(base + l0 + j) * D_INNER + xcol + p] = fmaf(Dh, xv, acc);
            if (p == 0) {
                cum *= dcy;
                cumout[cumbase + l0 + j] = cum;
            }
        }
        __syncthreads();
        if (blk + 2 < NBLK) stage(cur, (blk + 2) * SBLK);
    }

    float* st = states +
        ((size_t)(((b * NHEADS + h) * NCHUNK) + c) * HEADDIM + p) * D_STATE;
    #pragma unroll
    for (int q = 0; q < 16; q++) {
        ulonglong2 v;
        v.x = s2[2*q];
        v.y = s2[2*q+1];
        *(ulonglong2*)(st + q * 4) = v;
    }
}

// ---------------- chunked scan: stage 2 (combine, p-sliced) ----------------
__global__ __launch_bounds__(256) void scan_combine_kernel(
    float* __restrict__ states, const float* __restrict__ cum)
{
    const int h   = blockIdx.x;
    const int b   = blockIdx.y;
    const int sl  = blockIdx.z;        // 0..7
    const int tid = threadIdx.x;

    __shared__ float dprod[NCHUNK];
    if (tid < NCHUNK)
        dprod[tid] = cum[(size_t)(((b * NHEADS + h) * NCHUNK) + tid) * LCHUNK + LCHUNK - 1];
    __syncthreads();

    const size_t chunk_stride = (size_t)HEADDIM * D_STATE;        // 8192 floats
    float* base = states + (size_t)((b * NHEADS + h) * NCHUNK) * chunk_stride
                         + (size_t)sl * 1024;

    float4 e = make_float4(0.f, 0.f, 0.f, 0.f);
    const int idx = tid;               // 256 float4 = 1024 floats

    for (int c = 0; c < NCHUNK; c++) {
        float d = dprod[c];
        float4* p = (float4*)(base + c * chunk_stride);
        float4 s = p[idx];
        p[idx] = e;
        e.x = fmaf(e.x, d, s.x);
        e.y = fmaf(e.y, d, s.y);
        e.z = fmaf(e.z, d, s.z);
        e.w = fmaf(e.w, d, s.w);
    }
}

// ---------------- chunked scan: stage 3 (smem-staged, f32x2) ---------------
__global__ __launch_bounds__(128) void scan_fix_kernel(
    const float* __restrict__ states, const float* __restrict__ cum,
    const float* __restrict__ xbc, float* __restrict__ yout)
{
    const int c = blockIdx.x;
    if (c == 0) return;
    const int h = blockIdx.y;
    const int b = blockIdx.z;
    const int p = threadIdx.x;

    __shared__ __align__(16) float sC  [2][SBLK][64];
    __shared__ __align__(16) float scum[2][SBLK];

    ulonglong2 ent2[16];
    const float* st = states +
        ((size_t)(((b * NHEADS + h) * NCHUNK) + c) * HEADDIM + p) * D_STATE;
    #pragma unroll
    for (int q = 0; q < 16; q++) ent2[q] = *(const ulonglong2*)(st + q * 4);

    const size_t base = (size_t)b * SEQLEN + (size_t)c * LCHUNK;
    const size_t cumbase = (size_t)(((b * NHEADS + h) * NCHUNK) + c) * LCHUNK;
    const int ycol = h * HEADDIM + p;

    const uint32_t sC_a   = smem_to_u32(sC);
    const uint32_t scum_a = smem_to_u32(scum);

    auto stage = [&](int buf, int l0) {
        #pragma unroll
        for (int i = 0; i < 2; i++) {
            int idx = p + i * 128;
            int stp = idx >> 4;
            int q   = idx & 15;
            const float* src = xbc + (base + l0 + stp) * CONV_DIM + D_INNER + 64 + q * 4;
            uint32_t dst = sC_a + (uint32_t)((buf * SBLK + stp) * 64 + q * 4) * 4;
            asm volatile("cp.async.cg.shared.global [%0], [%1], 16;"
                         :: "r"(dst), "l"(src));
        }
        if (p < SBLK) {
            const float* src = cum + cumbase + l0 + p;
            uint32_t dst = scum_a + (uint32_t)(buf * SBLK + p) * 4;
            asm volatile("cp.async.ca.shared.global [%0], [%1], 4;"
                         :: "r"(dst), "l"(src));
        }
        asm volatile("cp.async.commit_group;");
    };

    stage(0, 0);
    stage(1, SBLK);

    for (int blk = 0; blk < NBLK; blk++) {
        if (blk >= NBLK - 2) asm volatile("cp.async.wait_group 0;");
        else                 asm volatile("cp.async.wait_group 1;");
        __syncthreads();
        const int cur = blk & 1;
        const int l0 = blk * SBLK;

        #pragma unroll 4
        for (int j = 0; j < SBLK; j++) {
            const ulonglong2* C2 = (const ulonglong2*)&sC[cur][j][0];
            unsigned long long a0 = 0ull, a1 = 0ull, b0 = 0ull, b1 = 0ull;
            #pragma unroll
            for (int q = 0; q < 16; q += 2) {
                ulonglong2 cv0 = C2[q];
                ulonglong2 cv1 = C2[q+1];
                FMA2(a0, ent2[q].x,   cv0.x, a0);
                FMA2(b0, ent2[q].y,   cv0.y, b0);
                FMA2(a1, ent2[q+1].x, cv1.x, a1);
                FMA2(b1, ent2[q+1].y, cv1.y, b1);
            }
            float p0, p1, dot = 0.f;
            UNPACK2(p0, p1, a0); dot += p0 + p1;
            UNPACK2(p0, p1, a1); dot += p0 + p1;
            UNPACK2(p0, p1, b0); dot += p0 + p1;
            UNPACK2(p0, p1, b1); dot += p0 + p1;
            float cm = scum[cur][j];
            float* yp = yout + (base + l0 + j) * D_INNER + ycol;
            *yp = fmaf(cm, dot, *yp);
        }
        __syncthreads();
        if (blk + 2 < NBLK) stage(cur, (blk + 2) * SBLK);
    }
}

// ---------------- RMSNorm + gate, fused bf16 split output ------------------
__global__ __launch_bounds__(256) void rms_gate_kernel(
    const float* __restrict__ y, const float* __restrict__ zx,
    const float* __restrict__ rmsw,
    __nv_bfloat16* __restrict__ ygh, __nv_bfloat16* __restrict__ ygl)
{
    int r = blockIdx.x;
    const float*  yr = y  + (size_t)r * D_INNER;
    const float*  zr = zx + (size_t)r * D_IN_PROJ;
    const float4* y4 = (const float4*)yr;

    int tid = threadIdx.x;
    float ss = 0.f;
    #pragma unroll
    for (int i = 0; i < 2; i++) {
        float4 v = y4[tid + i * 256];
        ss += v.x*v.x + v.y*v.y + v.z*v.z + v.w*v.w;
    }
    #pragma unroll
    for (int o = 16; o > 0; o >>= 1) ss += __shfl_xor_sync(0xffffffffu, ss, o);
    __shared__ float red[8];
    if ((tid & 31) == 0) red[tid >> 5] = ss;
    __syncthreads();
    if (tid == 0) {
        float t = 0.f;
        #pragma unroll
        for (int i = 0; i < 8; i++) t += red[i];
        red[0] = rsqrtf(t * (1.f / D_INNER) + RMS_EPS);
    }
    __syncthreads();
    float rs = red[0];

    const float4* z4 = (const float4*)zr;
    const float4* w4 = (const float4*)rmsw;
    uint2* gh = (uint2*)(ygh + (size_t)r * D_INNER);
    uint2* gl = (uint2*)(ygl + (size_t)r * D_INNER);
    #pragma unroll
    for (int i = 0; i < 2; i++) {
        int c = tid + i * 256;
        float4 v = y4[c];
        float4 z = z4[c];
        float4 w = w4[c];
        float4 o;
        o.x = v.x * rs * w.x * fast_sigmoid(z.x);
        o.y = v.y * rs * w.y * fast_sigmoid(z.y);
        o.z = v.z * rs * w.z * fast_sigmoid(z.z);
        o.w = v.w * rs * w.w * fast_sigmoid(z.w);
        uint32_t h01 = pack_bf16(o.x, o.y);
        uint32_t h23 = pack_bf16(o.z, o.w);
        float h0 = __uint_as_float(h01 << 16);
        float h1 = __uint_as_float(h01 & 0xffff0000u);
        float h2 = __uint_as_float(h23 << 16);
        float h3 = __uint_as_float(h23 & 0xffff0000u);
        gh[c] = make_uint2(h01, h23);
        gl[c] = make_uint2(pack_bf16(o.x - h0, o.y - h1),
                           pack_bf16(o.z - h2, o.w - h3));
    }
}

// ---------------- launcher -------------------------------------------------
extern "C" void kernel_launch(void* const* d_in, const int* in_sizes, int n_in,
                              void* d_out, int out_size)
{
    const float* u        = (const float*)d_in[0];
    const float* in_proj  = (const float*)d_in[1];
    const float* conv_w   = (const float*)d_in[2];
    const float* conv_b   = (const float*)d_in[3];
    const float* dt_bias  = (const float*)d_in[4];
    const float* A_log    = (const float*)d_in[5];
    const float* Dv       = (const float*)d_in[6];
    const float* rms_w    = (const float*)d_in[7];
    const float* out_w    = (const float*)d_in[8];
    float* out = (float*)d_out;

    float *zx, *xbc, *dec, *y, *st, *cum;
    __nv_bfloat16 *uhi, *ulo, *w1hi, *w1lo, *w2hi, *w2lo, *yghi, *yglo;
    cudaGetSymbolAddress((void**)&zx,  g_zx);
    cudaGetSymbolAddress((void**)&xbc, g_xbc);
    cudaGetSymbolAddress((void**)&dec, g_dec);
    cudaGetSymbolAddress((void**)&y,   g_y);
    cudaGetSymbolAddress((void**)&st,  g_st);
    cudaGetSymbolAddress((void**)&cum, g_cum);
    cudaGetSymbolAddress((void**)&uhi,  g_uhi);
    cudaGetSymbolAddress((void**)&ulo,  g_ulo);
    cudaGetSymbolAddress((void**)&w1hi, g_w1hi);
    cudaGetSymbolAddress((void**)&w1lo, g_w1lo);
    cudaGetSymbolAddress((void**)&w2hi, g_w2hi);
    cudaGetSymbolAddress((void**)&w2lo, g_w2lo);
    cudaGetSymbolAddress((void**)&yghi, g_yghi);
    cudaGetSymbolAddress((void**)&yglo, g_yglo);

    cudaFuncSetAttribute(gemm_bf16x3,
        cudaFuncAttributeMaxDynamicSharedMemorySize, GB_SMEM_BYTES);

    // lazy side-stream + events (created on first, non-captured, call)
    static cudaStream_t s1 = nullptr;
    static cudaEvent_t evFork = nullptr, evJoin = nullptr;
    if (!s1) {
        cudaStreamCreateWithFlags(&s1, cudaStreamNonBlocking);
        cudaEventCreateWithFlags(&evFork, cudaEventDisableTiming);
        cudaEventCreateWithFlags(&evJoin, cudaEventDisableTiming);
    }

    // 0) split fp32 operands into bf16 hi/lo
    {
        int n4u = NROWS * D_MODEL / 4;
        split_kernel<<<(n4u + 255) / 256, 256>>>(u, uhi, ulo, n4u);
        int n4w1 = D_IN_PROJ * D_MODEL / 4;
        split_kernel<<<(n4w1 + 255) / 256, 256>>>(in_proj, w1hi, w1lo, n4w1);
        int n4w2 = D_MODEL * D_INNER / 4;
        split_kernel<<<(n4w2 + 255) / 256, 256>>>(out_w, w2hi, w2lo, n4w2);
    }
    // 1a) in_proj GEMM, xBC+dt columns (2048..4239) — scan stack depends on this
    {
        const int Nxbc = D_IN_PROJ - D_INNER;   // 2192
        dim3 grid((Nxbc + GB_N - 1) / GB_N, NROWS / GB_M);
        gemm_bf16x3<<<grid, 256, GB_SMEM_BYTES>>>(
            uhi, ulo,
            w1hi + (size_t)D_INNER * D_MODEL, w1lo + (size_t)D_INNER * D_MODEL,
            zx + D_INNER, NROWS, Nxbc, D_MODEL, D_IN_PROJ);
    }
    // fork: 1b) z columns (0..2047) run concurrently with the scan stack
    cudaEventRecord(evFork, 0);
    cudaStreamWaitEvent(s1, evFork, 0);
    {
        dim3 grid(D_INNER / GB_N, NROWS / GB_M);
        gemm_bf16x3<<<grid, 256, GB_SMEM_BYTES, s1>>>(
            uhi, ulo, w1hi, w1lo, zx, NROWS, D_INNER, D_MODEL, D_IN_PROJ);
    }
    cudaEventRecord(evJoin, s1);

    // 2) conv + silu (main stream, overlapped with GEMM1b)
    {
        dim3 grid((CONV_DIM + 255) / 256, SEQLEN / 256, BATCH);
        conv_kernel<<<grid, 256>>>(zx, conv_w, conv_b, xbc);
    }
    // 3) decay precompute
    decay_kernel<<<(NROWS * NHEADS + 255) / 256, 256>>>(zx, dt_bias, A_log, dec);
    // 4) chunked SSM scan
    {
        dim3 grid(NCHUNK, NHEADS, BATCH);
        scan_local_kernel<<<grid, 128>>>(xbc, dec, Dv, y, st, cum);
    }
    {
        dim3 grid(NHEADS, BATCH, 8);
        scan_combine_kernel<<<grid, 256>>>(st, cum);
    }
    {
        dim3 grid(NCHUNK, NHEADS, BATCH);
        scan_fix_kernel<<<grid, 128>>>(st, cum, xbc, y);
    }
    // join: z columns must be ready for rms_gate
    cudaStreamWaitEvent(0, evJoin, 0);
    // 5) rmsnorm + gate (+ bf16 split)
    rms_gate_kernel<<<NROWS, 256>>>(y, zx, rms_w, yghi, yglo);
    // 6) out_proj GEMM
    {
        dim3 grid(D_MODEL / GB_N, NROWS / GB_M);
        gemm_bf16x3<<<grid, 256, GB_SMEM_BYTES>>>(yghi, yglo, w2hi, w2lo, out,
                                                  NROWS, D_MODEL, D_INNER, D_MODEL);
    }
}

// round 13
// speedup vs baseline: 1.3636x; 1.0288x over previous
#include <cuda_runtime.h>
#include <cuda_bf16.h>
#include <cstdint>
#include <math.h>

// ---------------- problem constants ----------------
#define D_MODEL   1024
#define D_INNER   2048
#define D_STATE   64
#define HEADDIM   128
#define NHEADS    16
#define D_CONV    4
#define CONV_DIM  2176
#define D_IN_PROJ 4240
#define BATCH     2
#define SEQLEN    4096
#define NROWS     (BATCH*SEQLEN)  // 8192
#define RMS_EPS   1e-5f

#define LCHUNK    128
#define NCHUNK    (SEQLEN/LCHUNK)   // 32
#define SBLK      16
#define NBLK      (LCHUNK/SBLK)     // 8

// ---------------- scratch ----------------
__device__ float g_zx  [(size_t)NROWS * D_IN_PROJ];
__device__ float g_xbc [(size_t)NROWS * CONV_DIM];
__device__ float g_ldec[(size_t)NROWS * NHEADS];      // log-decay
__device__ float g_y   [(size_t)NROWS * D_INNER];
__device__ float g_st  [(size_t)BATCH * NHEADS * NCHUNK * HEADDIM * D_STATE];
__device__ float g_cum [(size_t)BATCH * NHEADS * NCHUNK * LCHUNK];
__device__ __nv_bfloat16 g_uhi [(size_t)NROWS * D_MODEL];
__device__ __nv_bfloat16 g_ulo [(size_t)NROWS * D_MODEL];
__device__ __nv_bfloat16 g_w1hi[(size_t)D_IN_PROJ * D_MODEL];
__device__ __nv_bfloat16 g_w1lo[(size_t)D_IN_PROJ * D_MODEL];
__device__ __nv_bfloat16 g_w2hi[(size_t)D_MODEL * D_INNER];
__device__ __nv_bfloat16 g_w2lo[(size_t)D_MODEL * D_INNER];
__device__ __nv_bfloat16 g_yghi[(size_t)NROWS * D_INNER];
__device__ __nv_bfloat16 g_yglo[(size_t)NROWS * D_INNER];

// ================= helpers =================
__device__ __forceinline__ uint32_t smem_to_u32(const void* p) {
    uint32_t a;
    asm("{ .reg .u64 t; cvta.to.shared.u64 t, %1; cvt.u32.u64 %0, t; }"
        : "=r"(a) : "l"(p));
    return a;
}
__device__ __forceinline__ uint32_t pack_bf16(float lo_elem, float hi_elem) {
    uint32_t r;
    asm("cvt.rn.bf16x2.f32 %0, %1, %2;" : "=r"(r) : "f"(hi_elem), "f"(lo_elem));
    return r;
}
__device__ __forceinline__ void mma_bf16(float* d, const uint32_t* a,
                                         const uint32_t* b) {
    asm volatile(
        "mma.sync.aligned.m16n8k16.row.col.f32.bf16.bf16.f32 "
        "{%0,%1,%2,%3},{%4,%5,%6,%7},{%8,%9},{%0,%1,%2,%3};"
        : "+f"(d[0]), "+f"(d[1]), "+f"(d[2]), "+f"(d[3])
        : "r"(a[0]), "r"(a[1]), "r"(a[2]), "r"(a[3]), "r"(b[0]), "r"(b[1]));
}
__device__ __forceinline__ void ldsm_x4(uint32_t& r0, uint32_t& r1,
                                        uint32_t& r2, uint32_t& r3,
                                        uint32_t addr) {
    asm volatile("ldmatrix.sync.aligned.m8n8.x4.shared.b16 {%0,%1,%2,%3}, [%4];"
                 : "=r"(r0), "=r"(r1), "=r"(r2), "=r"(r3) : "r"(addr));
}
#define FMA2(d, a, b, c) \
    asm("fma.rn.f32x2 %0, %1, %2, %3;" : "=l"(d) : "l"(a), "l"(b), "l"(c))
#define UNPACK2(lo, hi, v) \
    asm("mov.b64 {%0, %1}, %2;" : "=f"(lo), "=f"(hi) : "l"(v))

__device__ __forceinline__ float fast_sigmoid(float x) {
    return __fdividef(1.f, 1.f + __expf(-x));
}
// split float pair -> bf16 hi-pack + lo-pack
__device__ __forceinline__ void split2(float a, float b, uint32_t& hp, uint32_t& lp) {
    hp = pack_bf16(a, b);
    float h0 = __uint_as_float(hp << 16);
    float h1 = __uint_as_float(hp & 0xffff0000u);
    lp = pack_bf16(a - h0, b - h1);
}
// swizzled addressing: 128B rows (64 bf16), col2 = uint32 index 0..31
__device__ __forceinline__ uint32_t a128(uint32_t base, int row, int col2) {
    return base + (uint32_t)(row * 128 + ((((col2 >> 2) ^ row) & 7) * 16) + (col2 & 3) * 4);
}
// swizzled addressing: 256B rows (128 bf16), col2 0..63
__device__ __forceinline__ uint32_t a256(uint32_t base, int row, int col2) {
    int cq = col2 >> 2;
    int ph = (((cq & 7) ^ (row & 7)) | (cq & 8));
    return base + (uint32_t)(row * 256 + ph * 16 + (col2 & 3) * 4);
}

// ================= split kernel: fp32 -> bf16 hi + bf16 lo =================
__global__ __launch_bounds__(256) void split_kernel(
    const float* __restrict__ in, __nv_bfloat16* __restrict__ hi,
    __nv_bfloat16* __restrict__ lo, int n4)
{
    int i = blockIdx.x * 256 + threadIdx.x;
    if (i >= n4) return;
    float4 v = ((const float4*)in)[i];
    uint32_t h01, l01, h23, l23;
    split2(v.x, v.y, h01, l01);
    split2(v.z, v.w, h23, l23);
    ((uint2*)hi)[i] = make_uint2(h01, h23);
    ((uint2*)lo)[i] = make_uint2(l01, l23);
}

// ================= GEMM (bf16x3, ldmatrix + 3-stage cp.async) ==============
#define GB_M 128
#define GB_N 128
#define GB_K 32
#define GB_STAGE 32768
#define GB_SMEM_BYTES (3 * GB_STAGE)

__global__ __launch_bounds__(256, 2) void gemm_bf16x3(
    const __nv_bfloat16* __restrict__ Ahi, const __nv_bfloat16* __restrict__ Alo,
    const __nv_bfloat16* __restrict__ Bhi, const __nv_bfloat16* __restrict__ Blo,
    float* __restrict__ C, int M, int N, int K, int ldc)
{
    extern __shared__ char smem[];
    const uint32_t sbase = smem_to_u32(smem);
    const int tid = threadIdx.x;
    const int bm  = blockIdx.y * GB_M;
    const int bn  = blockIdx.x * GB_N;
    const int nch = K / GB_K;

    const int warp = tid >> 5;
    const int lane = tid & 31;
    const int wm = warp >> 2;
    const int wn = warp & 3;
    const int lr = lane >> 2;
    const int lc = lane & 3;

    float acc[4][4][4];
    #pragma unroll
    for (int mt = 0; mt < 4; mt++)
        #pragma unroll
        for (int nt = 0; nt < 4; nt++)
            #pragma unroll
            for (int q = 0; q < 4; q++) acc[mt][nt][q] = 0.f;

    auto load_stage = [&](int buf, int kt) {
        #pragma unroll
        for (int i = 0; i < 8; i++) {
            int idx = tid + i * 256;
            int cq = idx & 3;
            int r  = (idx >> 2) & 127;
            int t  = idx >> 9;
            uint32_t so = sbase + (uint32_t)buf * GB_STAGE + (uint32_t)t * 8192 +
                          (uint32_t)r * 64 + (uint32_t)((cq ^ ((r >> 1) & 3)) * 16);
            const __nv_bfloat16* g;
            if (t == 0)      g = Ahi + (size_t)(bm + r) * K;
            else if (t == 1) g = Alo + (size_t)(bm + r) * K;
            else {
                int gn = bn + r; if (gn >= N) gn = N - 1;
                g = (t == 2 ? Bhi : Blo) + (size_t)gn * K;
            }
            g += kt + cq * 8;
            asm volatile("cp.async.cg.shared.global [%0], [%1], 16;"
                         :: "r"(so), "l"(g));
        }
        asm volatile("cp.async.commit_group;");
    };

    load_stage(0, 0);
    if (nch > 1) load_stage(1, GB_K);

    const int rowA = wm * 64 + ((lane >> 3) & 1) * 8 + (lane & 7);
    const int rowB = wn * 32 + ((lane >> 4) & 1) * 8 + (lane & 7);
    const int sel  = ((lane & 7) >> 1) & 3;
    const int cAq  = (lane >> 4) & 1;
    const int cBq  = (lane >> 3) & 1;

    for (int c = 0; c < nch; c++) {
        if (c == nch - 1) asm volatile("cp.async.wait_group 0;");
        else              asm volatile("cp.async.wait_group 1;");
        __syncthreads();
        if (c + 2 < nch) load_stage((c + 2) % 3, (c + 2) * GB_K);

        const uint32_t stg = sbase + (uint32_t)(c % 3) * GB_STAGE;
        const uint32_t baseAhi = stg + (uint32_t)rowA * 64;
        const uint32_t baseAlo = baseAhi + 8192;
        const uint32_t baseBhi = stg + 16384 + (uint32_t)rowB * 64;
        const uint32_t baseBlo = baseBhi + 8192;

        #pragma unroll
        for (int ks = 0; ks < 2; ks++) {
            const uint32_t cAo = (uint32_t)(((ks * 2 + cAq) ^ sel) * 16);
            const uint32_t cBo = (uint32_t)(((ks * 2 + cBq) ^ sel) * 16);

            uint32_t bh[4][2], bl[4][2];
            #pragma unroll
            for (int ntp = 0; ntp < 2; ntp++) {
                uint32_t r0, r1, r2, r3;
                ldsm_x4(r0, r1, r2, r3, baseBhi + ntp * 1024 + cBo);
                bh[ntp*2][0] = r0; bh[ntp*2][1] = r1;
                bh[ntp*2+1][0] = r2; bh[ntp*2+1][1] = r3;
                ldsm_x4(r0, r1, r2, r3, baseBlo + ntp * 1024 + cBo);
                bl[ntp*2][0] = r0; bl[ntp*2][1] = r1;
                bl[ntp*2+1][0] = r2; bl[ntp*2+1][1] = r3;
            }
            #pragma unroll
            for (int mt = 0; mt < 4; mt++) {
                uint32_t ah[4], al[4];
                ldsm_x4(ah[0], ah[1], ah[2], ah[3], baseAhi + mt * 1024 + cAo);
                ldsm_x4(al[0], al[1], al[2], al[3], baseAlo + mt * 1024 + cAo);
                #pragma unroll
                for (int nt = 0; nt < 4; nt++) {
                    mma_bf16(acc[mt][nt], ah, bh[nt]);
                    mma_bf16(acc[mt][nt], ah, bl[nt]);
                    mma_bf16(acc[mt][nt], al, bh[nt]);
                }
            }
        }
    }

    #pragma unroll
    for (int mt = 0; mt < 4; mt++) {
        int row = bm + wm * 64 + mt * 16 + lr;
        #pragma unroll
        for (int nt = 0; nt < 4; nt++) {
            int col = bn + wn * 32 + nt * 8 + lc * 2;
            if (col + 1 < N) {
                *(float2*)(C + (size_t)row * ldc + col) =
                    make_float2(acc[mt][nt][0], acc[mt][nt][1]);
                *(float2*)(C + (size_t)(row + 8) * ldc + col) =
                    make_float2(acc[mt][nt][2], acc[mt][nt][3]);
            }
        }
    }
}

// ---------------- depthwise causal conv (k=4) + bias + SiLU ----------------
__global__ __launch_bounds__(256) void conv_kernel(
    const float* __restrict__ zx, const float* __restrict__ cw,
    const float* __restrict__ cb, float* __restrict__ xbc)
{
    int c = blockIdx.x * 256 + threadIdx.x;
    if (c >= CONV_DIM) return;
    int strip = blockIdx.y;
    int b     = blockIdx.z;
    int l0    = strip * 256;

    float w0 = cw[c*4+0], w1 = cw[c*4+1], w2 = cw[c*4+2], w3 = cw[c*4+3];
    float bias = cb[c];

    size_t colbase = (size_t)D_INNER + c;
    size_t rb = (size_t)b * SEQLEN;

    float xm3 = (l0-3 >= 0) ? zx[(rb + l0-3) * D_IN_PROJ + colbase] : 0.f;
    float xm2 = (l0-2 >= 0) ? zx[(rb + l0-2) * D_IN_PROJ + colbase] : 0.f;
    float xm1 = (l0-1 >= 0) ? zx[(rb + l0-1) * D_IN_PROJ + colbase] : 0.f;

    for (int l = l0; l < l0 + 256; l++) {
        float xv = zx[(rb + l) * D_IN_PROJ + colbase];
        float a = bias;
        a = fmaf(w0, xm3, a);
        a = fmaf(w1, xm2, a);
        a = fmaf(w2, xm1, a);
        a = fmaf(w3, xv,  a);
        float sv = a * fast_sigmoid(a);
        xbc[(rb + l) * CONV_DIM + c] = sv;
        xm3 = xm2; xm2 = xm1; xm1 = xv;
    }
}

// ---------------- dt -> softplus -> LOG decay ------------------------------
__global__ __launch_bounds__(256) void decay_kernel(
    const float* __restrict__ zx, const float* __restrict__ dt_bias,
    const float* __restrict__ A_log, float* __restrict__ ldec)
{
    int idx = blockIdx.x * 256 + threadIdx.x;
    if (idx >= NROWS * NHEADS) return;
    int r = idx >> 4;
    int h = idx & 15;
    float raw = zx[(size_t)r * D_IN_PROJ + (D_IN_PROJ - NHEADS) + h] + dt_bias[h];
    float sp  = (raw > 20.f) ? raw : log1pf(expf(raw));
    float A   = -expf(A_log[h]);
    ldec[idx] = sp * A;            // log of decay (<= 0)
}

// ================= chunked matmul scan (intra-chunk) ======================
// One CTA per (chunk, head, batch). 256 threads, 8 warps.
// Computes: G = (C·B^T) ∘ exp(L_l - L_s) ∘ [s<=l];  Y = G@X + D*x;
//           S_end = X^T @ (W∘B),  W_s = exp(L_last - L_s);  cum_l = exp(L_l).
#define SC_XTH 0u
#define SC_XTL 32768u
#define SC_GA  65536u           // phase1: CH, CL(+16K), BH(+32K), BL(+48K); phase2: GH, GL(+32K)
#define SC_WBH 131072u
#define SC_WBL 147456u
#define SC_L   163840u
#define SC_STG 164352u
#define SC_SMEM 168576u

__global__ __launch_bounds__(256, 1) void scan_matmul_kernel(
    const float* __restrict__ xbc, const float* __restrict__ ldec,
    const float* __restrict__ Dvec, float* __restrict__ yout,
    float* __restrict__ states, float* __restrict__ cumout)
{
    extern __shared__ char smem[];
    const uint32_t sb = smem_to_u32(smem);
    const int c = blockIdx.x;
    const int h = blockIdx.y;
    const int b = blockIdx.z;
    const int t = threadIdx.x;
    const int warp = t >> 5;
    const int lane = t & 31;
    const int lr = lane >> 2;
    const int lc = lane & 3;

    const size_t base = (size_t)b * SEQLEN + (size_t)c * LCHUNK;
    const int xcol = h * HEADDIM;
    const size_t cumbase = (size_t)(((b * NHEADS + h) * NCHUNK) + c) * LCHUNK;

    float* Lsm = (float*)(smem + SC_L);
    float* stg = (float*)(smem + SC_STG);

    // ---- load B, C (bf16-split, swizzled 128B rows [time][n]) ----
    {
        const uint32_t CH = sb + SC_GA, CL = CH + 16384;
        const uint32_t BH = sb + SC_GA + 32768, BL = BH + 16384;
        #pragma unroll
        for (int i = 0; i < 16; i++) {
            int idx = t + i * 256;          // 0..4095
            int s = idx >> 5, col2 = idx & 31;
            const float* row = xbc + (base + s) * CONV_DIM + D_INNER;
            float2 vB = *(const float2*)(row + col2 * 2);
            float2 vC = *(const float2*)(row + 64 + col2 * 2);
            uint32_t hp, lp;
            split2(vB.x, vB.y, hp, lp);
            *(uint32_t*)(smem + (a128(BH, s, col2) - sb)) = hp;
            *(uint32_t*)(smem + (a128(BL, s, col2) - sb)) = lp;
            split2(vC.x, vC.y, hp, lp);
            *(uint32_t*)(smem + (a128(CH, s, col2) - sb)) = hp;
            *(uint32_t*)(smem + (a128(CL, s, col2) - sb)) = lp;
        }
    }

    // ---- log-decay prefix (warp 0) + cum output ----
    if (warp == 0) {
        float v0 = ldec[(base + lane * 4 + 0) * NHEADS + h];
        float v1 = ldec[(base + lane * 4 + 1) * NHEADS + h];
        float v2 = ldec[(base + lane * 4 + 2) * NHEADS + h];
        float v3 = ldec[(base + lane * 4 + 3) * NHEADS + h];
        float p0 = v0, p1 = p0 + v1, p2 = p1 + v2, p3 = p2 + v3;
        float inc = p3;
        #pragma unroll
        for (int o = 1; o < 32; o <<= 1) {
            float n = __shfl_up_sync(0xffffffffu, inc, o);
            if (lane >= o) inc += n;
        }
        float excl = inc - p3;
        Lsm[lane*4+0] = excl + p0;
        Lsm[lane*4+1] = excl + p1;
        Lsm[lane*4+2] = excl + p2;
        Lsm[lane*4+3] = excl + p3;
        cumout[cumbase + lane*4+0] = __expf(excl + p0);
        cumout[cumbase + lane*4+1] = __expf(excl + p1);
        cumout[cumbase + lane*4+2] = __expf(excl + p2);
        cumout[cumbase + lane*4+3] = __expf(excl + p3);
    }

    // ---- load X transposed (bf16-split, swizzled 256B rows [p][l]) ----
    #pragma unroll 1
    for (int ti = 0; ti < 16; ti++) {
        int lt = ti >> 2, pt = ti & 3;
        #pragma unroll
        for (int rep = 0; rep < 4; rep++) {
            int row = (t >> 5) + rep * 8;
            int colp = t & 31;
            stg[row * 33 + colp] =
                xbc[(base + lt * 32 + row) * CONV_DIM + xcol + pt * 32 + colp];
        }
        __syncthreads();
        int ploc = t >> 3;
        int j = t & 7;
        #pragma unroll
        for (int k = 0; k < 2; k++) {
            int pr = j * 2 + k;              // 0..15 (pair of l's)
            float v0 = stg[(pr * 2) * 33 + ploc];
            float v1 = stg[(pr * 2 + 1) * 33 + ploc];
            int p = pt * 32 + ploc;
            int col2 = lt * 16 + pr;
            uint32_t hp, lp;
            split2(v0, v1, hp, lp);
            *(uint32_t*)(smem + (a256(sb + SC_XTH, p, col2) - sb)) = hp;
            *(uint32_t*)(smem + (a256(sb + SC_XTL, p, col2) - sb)) = lp;
        }
        __syncthreads();
    }

    // ---- step 1: G = C·B^T  (M=128 l, N=128 s, K=64 n) ----
    const int wm = warp >> 2, wn = warp & 3;
    const int rowA = wm * 64 + ((lane >> 3) & 1) * 8 + (lane & 7);
    const int rowB = wn * 32 + ((lane >> 4) & 1) * 8 + (lane & 7);
    const int cAq = (lane >> 4) & 1;
    const int cBq = (lane >> 3) & 1;
    const int rA7 = rowA & 7, rB7 = rowB & 7;

    float acc1[4][4][4];
    #pragma unroll
    for (int mt = 0; mt < 4; mt++)
        #pragma unroll
        for (int nt = 0; nt < 4; nt++)
            #pragma unroll
            for (int q = 0; q < 4; q++) acc1[mt][nt][q] = 0.f;

    {
        const uint32_t aCH = sb + SC_GA + (uint32_t)rowA * 128;
        const uint32_t aCL = aCH + 16384;
        const uint32_t aBH = sb + SC_GA + 32768 + (uint32_t)rowB * 128;
        const uint32_t aBL = aBH + 16384;
        #pragma unroll
        for (int ks = 0; ks < 4; ks++) {
            uint32_t offA = (uint32_t)((((ks * 2 + cAq) ^ rA7) & 7) * 16);
            uint32_t offB = (uint32_t)((((ks * 2 + cBq) ^ rB7) & 7) * 16);
            uint32_t bh[4][2], bl[4][2];
            #pragma unroll
            for (int ntp = 0; ntp < 2; ntp++) {
                uint32_t r0, r1, r2, r3;
                ldsm_x4(r0, r1, r2, r3, aBH + ntp * 2048 + offB);
                bh[ntp*2][0]=r0; bh[ntp*2][1]=r1; bh[ntp*2+1][0]=r2; bh[ntp*2+1][1]=r3;
                ldsm_x4(r0, r1, r2, r3, aBL + ntp * 2048 + offB);
                bl[ntp*2][0]=r0; bl[ntp*2][1]=r1; bl[ntp*2+1][0]=r2; bl[ntp*2+1][1]=r3;
            }
            #pragma unroll
            for (int mt = 0; mt < 4; mt++) {
                uint32_t ah[4], al[4];
                ldsm_x4(ah[0], ah[1], ah[2], ah[3], aCH + mt * 2048 + offA);
                ldsm_x4(al[0], al[1], al[2], al[3], aCL + mt * 2048 + offA);
                #pragma unroll
                for (int nt = 0; nt < 4; nt++) {
                    mma_bf16(acc1[mt][nt], ah, bh[nt]);
                    mma_bf16(acc1[mt][nt], ah, bl[nt]);
                    mma_bf16(acc1[mt][nt], al, bh[nt]);
                }
            }
        }
    }

    // ---- WB[n][s] = exp(L_last - L_s) * B[s][n]  (before B is overwritten) --
    {
        const float Llast = Lsm[127];
        const uint32_t BH = sb + SC_GA + 32768, BL = BH + 16384;
        int n = t >> 2;
        int s0 = (t & 3) * 32;
        #pragma unroll
        for (int sp = 0; sp < 16; sp++) {
            int sA = s0 + sp * 2, sB2 = sA + 1;
            uint32_t wA = *(uint32_t*)(smem + (a128(BH, sA, n >> 1) - sb));
            uint32_t lA = *(uint32_t*)(smem + (a128(BL, sA, n >> 1) - sb));
            uint32_t wB = *(uint32_t*)(smem + (a128(BH, sB2, n >> 1) - sb));
            uint32_t lB = *(uint32_t*)(smem + (a128(BL, sB2, n >> 1) - sb));
            uint32_t hbA = (n & 1) ? (wA & 0xffff0000u) : (wA << 16);
            uint32_t lbA = (n & 1) ? (lA & 0xffff0000u) : (lA << 16);
            uint32_t hbB = (n & 1) ? (wB & 0xffff0000u) : (wB << 16);
            uint32_t lbB = (n & 1) ? (lB & 0xffff0000u) : (lB << 16);
            float bA = __uint_as_float(hbA) + __uint_as_float(lbA);
            float bB = __uint_as_float(hbB) + __uint_as_float(lbB);
            float vA = bA * __expf(Llast - Lsm[sA]);
            float vB = bB * __expf(Llast - Lsm[sB2]);
            uint32_t hp, lp;
            split2(vA, vB, hp, lp);
            *(uint32_t*)(smem + (a256(sb + SC_WBH, n, sA >> 1) - sb)) = hp;
            *(uint32_t*)(smem + (a256(sb + SC_WBL, n, sA >> 1) - sb)) = lp;
        }
    }
    __syncthreads();

    // ---- write G (overwrites C/B region): scale+mask, split bf16 ----
    {
        const uint32_t GH = sb + SC_GA, GL = GH + 32768;
        #pragma unroll
        for (int mt = 0; mt < 4; mt++) {
            int l0 = wm * 64 + mt * 16 + lr;
            int l1 = l0 + 8;
            #pragma unroll
            for (int nt = 0; nt < 4; nt++) {
                int s0 = wn * 32 + nt * 8 + lc * 2;
                float Ll0 = Lsm[l0], Ll1 = Lsm[l1];
                float Ls0 = Lsm[s0], Ls1 = Lsm[s0 + 1];
                float e00 = (s0     <= l0) ? acc1[mt][nt][0] * __expf(Ll0 - Ls0) : 0.f;
                float e01 = (s0 + 1 <= l0) ? acc1[mt][nt][1] * __expf(Ll0 - Ls1) : 0.f;
                float e10 = (s0     <= l1) ? acc1[mt][nt][2] * __expf(Ll1 - Ls0) : 0.f;
                float e11 = (s0 + 1 <= l1) ? acc1[mt][nt][3] * __expf(Ll1 - Ls1) : 0.f;
                uint32_t hp, lp;
                split2(e00, e01, hp, lp);
                *(uint32_t*)(smem + (a256(GH, l0, s0 >> 1) - sb)) = hp;
                *(uint32_t*)(smem + (a256(GL, l0, s0 >> 1) - sb)) = lp;
                split2(e10, e11, hp, lp);
                *(uint32_t*)(smem + (a256(GH, l1, s0 >> 1) - sb)) = hp;
                *(uint32_t*)(smem + (a256(GL, l1, s0 >> 1) - sb)) = lp;
            }
        }
    }
    __syncthreads();

    // ---- step 3: Y = G @ X   (M=128 l, N=128 p, K=128 s) ----
    {
        float acc3[4][4][4];
        #pragma unroll
        for (int mt = 0; mt < 4; mt++)
            #pragma unroll
            for (int nt = 0; nt < 4; nt++)
                #pragma unroll
                for (int q = 0; q < 4; q++) acc3[mt][nt][q] = 0.f;

        const uint32_t aGH = sb + SC_GA + (uint32_t)rowA * 256;
        const uint32_t aGL = aGH + 32768;
        const uint32_t aXH = sb + SC_XTH + (uint32_t)rowB * 256;
        const uint32_t aXL = aXH + 32768;
        #pragma unroll
        for (int ks = 0; ks < 8; ks++) {
            int cqa = ks * 2 + cAq;
            int cqb = ks * 2 + cBq;
            uint32_t offA = (uint32_t)(((((cqa & 7) ^ rA7)) | (cqa & 8)) * 16);
            uint32_t offB = (uint32_t)(((((cqb & 7) ^ rB7)) | (cqb & 8)) * 16);
            uint32_t bh[4][2], bl[4][2];
            #pragma unroll
            for (int ntp = 0; ntp < 2; ntp++) {
                uint32_t r0, r1, r2, r3;
                ldsm_x4(r0, r1, r2, r3, aXH + ntp * 4096 + offB);
                bh[ntp*2][0]=r0; bh[ntp*2][1]=r1; bh[ntp*2+1][0]=r2; bh[ntp*2+1][1]=r3;
                ldsm_x4(r0, r1, r2, r3, aXL + ntp * 4096 + offB);
                bl[ntp*2][0]=r0; bl[ntp*2][1]=r1; bl[ntp*2+1][0]=r2; bl[ntp*2+1][1]=r3;
            }
            #pragma unroll
            for (int mt = 0; mt < 4; mt++) {
                uint32_t ah[4], al[4];
                ldsm_x4(ah[0], ah[1], ah[2], ah[3], aGH + mt * 4096 + offA);
                ldsm_x4(al[0], al[1], al[2], al[3], aGL + mt * 4096 + offA);
                #pragma unroll
                for (int nt = 0; nt < 4; nt++) {
                    mma_bf16(acc3[mt][nt], ah, bh[nt]);
                    mma_bf16(acc3[mt][nt], ah, bl[nt]);
                    mma_bf16(acc3[mt][nt], al, bh[nt]);
                }
            }
        }
        // epilogue: y = acc + D*x
        const float Dh = Dvec[h];
        #pragma unroll
        for (int mt = 0; mt < 4; mt++) {
            int l0 = wm * 64 + mt * 16 + lr;
            int l1 = l0 + 8;
            #pragma unroll
            for (int nt = 0; nt < 4; nt++) {
                int p0 = wn * 32 + nt * 8 + lc * 2;
                float2 x0 = *(const float2*)(xbc + (base + l0) * CONV_DIM + xcol + p0);
                float2 x1 = *(const float2*)(xbc + (base + l1) * CONV_DIM + xcol + p0);
                *(float2*)(yout + (base + l0) * D_INNER + xcol + p0) =
                    make_float2(fmaf(Dh, x0.x, acc3[mt][nt][0]),
                                fmaf(Dh, x0.y, acc3[mt][nt][1]));
                *(float2*)(yout + (base + l1) * D_INNER + xcol + p0) =
                    make_float2(fmaf(Dh, x1.x, acc3[mt][nt][2]),
                                fmaf(Dh, x1.y, acc3[mt][nt][3]));
            }
        }
    }

    // ---- step 4: S_end[p][n] = X^T @ WB^T  (M=128 p, N=64 n, K=128 s) ----
    {
        const int wm4 = warp >> 1, wn4 = warp & 1;
        const int rowA4 = wm4 * 32 + ((lane >> 3) & 1) * 8 + (lane & 7);
        const int rowB4 = wn4 * 32 + ((lane >> 4) & 1) * 8 + (lane & 7);
        const int rA47 = rowA4 & 7, rB47 = rowB4 & 7;

        float acc4[2][4][4];
        #pragma unroll
        for (int mt = 0; mt < 2; mt++)
            #pragma unroll
            for (int nt = 0; nt < 4; nt++)
                #pragma unroll
                for (int q = 0; q < 4; q++) acc4[mt][nt][q] = 0.f;

        const uint32_t aXH = sb + SC_XTH + (uint32_t)rowA4 * 256;
        const uint32_t aXL = aXH + 32768;
        const uint32_t aWH = sb + SC_WBH + (uint32_t)rowB4 * 256;
        const uint32_t aWL = aWH + 16384;
        #pragma unroll
        for (int ks = 0; ks < 8; ks++) {
            int cqa = ks * 2 + cAq;
            int cqb = ks * 2 + cBq;
            uint32_t offA = (uint32_t)(((((cqa & 7) ^ rA47)) | (cqa & 8)) * 16);
            uint32_t offB = (uint32_t)(((((cqb & 7) ^ rB47)) | (cqb & 8)) * 16);
            uint32_t bh[4][2], bl[4][2];
            #pragma unroll
            for (int ntp = 0; ntp < 2; ntp++) {
                uint32_t r0, r1, r2, r3;
                ldsm_x4(r0, r1, r2, r3, aWH + ntp * 4096 + offB);
                bh[ntp*2][0]=r0; bh[ntp*2][1]=r1; bh[ntp*2+1][0]=r2; bh[ntp*2+1][1]=r3;
                ldsm_x4(r0, r1, r2, r3, aWL + ntp * 4096 + offB);
                bl[ntp*2][0]=r0; bl[ntp*2][1]=r1; bl[ntp*2+1][0]=r2; bl[ntp*2+1][1]=r3;
            }
            #pragma unroll
            for (int mt = 0; mt < 2; mt++) {
                uint32_t ah[4], al[4];
                ldsm_x4(ah[0], ah[1], ah[2], ah[3], aXH + mt * 4096 + offA);
                ldsm_x4(al[0], al[1], al[2], al[3], aXL + mt * 4096 + offA);
                #pragma unroll
                for (int nt = 0; nt < 4; nt++) {
                    mma_bf16(acc4[mt][nt], ah, bh[nt]);
                    mma_bf16(acc4[mt][nt], ah, bl[nt]);
                    mma_bf16(acc4[mt][nt], al, bh[nt]);
                }
            }
        }
        float* stbase = states +
            ((size_t)(((b * NHEADS + h) * NCHUNK) + c) * HEADDIM) * D_STATE;
        #pragma unroll
        for (int mt = 0; mt < 2; mt++) {
            int p0 = wm4 * 32 + mt * 16 + lr;
            int p1 = p0 + 8;
            #pragma unroll
            for (int nt = 0; nt < 4; nt++) {
                int n0 = wn4 * 32 + nt * 8 + lc * 2;
                *(float2*)(stbase + (size_t)p0 * D_STATE + n0) =
                    make_float2(acc4[mt][nt][0], acc4[mt][nt][1]);
                *(float2*)(stbase + (size_t)p1 * D_STATE + n0) =
                    make_float2(acc4[mt][nt][2], acc4[mt][nt][3]);
            }
        }
    }
}

// ---------------- chunked scan: stage 2 (combine, p-sliced) ----------------
__global__ __launch_bounds__(256) void scan_combine_kernel(
    float* __restrict__ states, const float* __restrict__ cum)
{
    const int h   = blockIdx.x;
    const int b   = blockIdx.y;
    const int sl  = blockIdx.z;
    const int tid = threadIdx.x;

    __shared__ float dprod[NCHUNK];
    if (tid < NCHUNK)
        dprod[tid] = cum[(size_t)(((b * NHEADS + h) * NCHUNK) + tid) * LCHUNK + LCHUNK - 1];
    __syncthreads();

    const size_t chunk_stride = (size_t)HEADDIM * D_STATE;
    float* base = states + (size_t)((b * NHEADS + h) * NCHUNK) * chunk_stride
                         + (size_t)sl * 1024;

    float4 e = make_float4(0.f, 0.f, 0.f, 0.f);
    const int idx = tid;

    for (int c = 0; c < NCHUNK; c++) {
        float d = dprod[c];
        float4* p = (float4*)(base + c * chunk_stride);
        float4 s = p[idx];
        p[idx] = e;
        e.x = fmaf(e.x, d, s.x);
        e.y = fmaf(e.y, d, s.y);
        e.z = fmaf(e.z, d, s.z);
        e.w = fmaf(e.w, d, s.w);
    }
}

// ---------------- chunked scan: stage 3 (smem-staged, f32x2) ---------------
__global__ __launch_bounds__(128) void scan_fix_kernel(
    const float* __restrict__ states, const float* __restrict__ cum,
    const float* __restrict__ xbc, float* __restrict__ yout)
{
    const int c = blockIdx.x;
    if (c == 0) return;
    const int h = blockIdx.y;
    const int b = blockIdx.z;
    const int p = threadIdx.x;

    __shared__ __align__(16) float sC  [2][SBLK][64];
    __shared__ __align__(16) float scum[2][SBLK];

    ulonglong2 ent2[16];
    const float* st = states +
        ((size_t)(((b * NHEADS + h) * NCHUNK) + c) * HEADDIM + p) * D_STATE;
    #pragma unroll
    for (int q = 0; q < 16; q++) ent2[q] = *(const ulonglong2*)(st + q * 4);

    const size_t base = (size_t)b * SEQLEN + (size_t)c * LCHUNK;
    const size_t cumbase = (size_t)(((b * NHEADS + h) * NCHUNK) + c) * LCHUNK;
    const int ycol = h * HEADDIM + p;

    const uint32_t sC_a   = smem_to_u32(sC);
    const uint32_t scum_a = smem_to_u32(scum);

    auto stage = [&](int buf, int l0) {
        #pragma unroll
        for (int i = 0; i < 2; i++) {
            int idx = p + i * 128;
            int stp = idx >> 4;
            int q   = idx & 15;
            const float* src = xbc + (base + l0 + stp) * CONV_DIM + D_INNER + 64 + q * 4;
            uint32_t dst = sC_a + (uint32_t)((buf * SBLK + stp) * 64 + q * 4) * 4;
            asm volatile("cp.async.cg.shared.global [%0], [%1], 16;"
                         :: "r"(dst), "l"(src));
        }
        if (p < SBLK) {
            const float* src = cum + cumbase + l0 + p;
            uint32_t dst = scum_a + (uint32_t)(buf * SBLK + p) * 4;
            asm volatile("cp.async.ca.shared.global [%0], [%1], 4;"
                         :: "r"(dst), "l"(src));
        }
        asm volatile("cp.async.commit_group;");
    };

    stage(0, 0);
    stage(1, SBLK);

    for (int blk = 0; blk < NBLK; blk++) {
        if (blk >= NBLK - 2) asm volatile("cp.async.wait_group 0;");
        else                 asm volatile("cp.async.wait_group 1;");
        __syncthreads();
        const int cur = blk & 1;
        const int l0 = blk * SBLK;

        #pragma unroll 4
        for (int j = 0; j < SBLK; j++) {
            const ulonglong2* C2 = (const ulonglong2*)&sC[cur][j][0];
            unsigned long long a0 = 0ull, a1 = 0ull, b0 = 0ull, b1 = 0ull;
            #pragma unroll
            for (int q = 0; q < 16; q += 2) {
                ulonglong2 cv0 = C2[q];
                ulonglong2 cv1 = C2[q+1];
                FMA2(a0, ent2[q].x,   cv0.x, a0);
                FMA2(b0, ent2[q].y,   cv0.y, b0);
                FMA2(a1, ent2[q+1].x, cv1.x, a1);
                FMA2(b1, ent2[q+1].y, cv1.y, b1);
            }
            float p0, p1, dot = 0.f;
            UNPACK2(p0, p1, a0); dot += p0 + p1;
            UNPACK2(p0, p1, a1); dot += p0 + p1;
            UNPACK2(p0, p1, b0); dot += p0 + p1;
            UNPACK2(p0, p1, b1); dot += p0 + p1;
            float cm = scum[cur][j];
            float* yp = yout + (base + l0 + j) * D_INNER + ycol;
            *yp = fmaf(cm, dot, *yp);
        }
        __syncthreads();
        if (blk + 2 < NBLK) stage(cur, (blk + 2) * SBLK);
    }
}

// ---------------- RMSNorm + gate, fused bf16 split output ------------------
__global__ __launch_bounds__(256) void rms_gate_kernel(
    const float* __restrict__ y, const float* __restrict__ zx,
    const float* __restrict__ rmsw,
    __nv_bfloat16* __restrict__ ygh, __nv_bfloat16* __restrict__ ygl)
{
    int r = blockIdx.x;
    const float*  yr = y  + (size_t)r * D_INNER;
    const float*  zr = zx + (size_t)r * D_IN_PROJ;
    const float4* y4 = (const float4*)yr;

    int tid = threadIdx.x;
    float ss = 0.f;
    #pragma unroll
    for (int i = 0; i < 2; i++) {
        float4 v = y4[tid + i * 256];
        ss += v.x*v.x + v.y*v.y + v.z*v.z + v.w*v.w;
    }
    #pragma unroll
    for (int o = 16; o > 0; o >>= 1) ss += __shfl_xor_sync(0xffffffffu, ss, o);
    __shared__ float red[8];
    if ((tid & 31) == 0) red[tid >> 5] = ss;
    __syncthreads();
    if (tid == 0) {
        float t = 0.f;
        #pragma unroll
        for (int i = 0; i < 8; i++) t += red[i];
        red[0] = rsqrtf(t * (1.f / D_INNER) + RMS_EPS);
    }
    __syncthreads();
    float rs = red[0];

    const float4* z4 = (const float4*)zr;
    const float4* w4 = (const float4*)rmsw;
    uint2* gh = (uint2*)(ygh + (size_t)r * D_INNER);
    uint2* gl = (uint2*)(ygl + (size_t)r * D_INNER);
    #pragma unroll
    for (int i = 0; i < 2; i++) {
        int c = tid + i * 256;
        float4 v = y4[c];
        float4 z = z4[c];
        float4 w = w4[c];
        float4 o;
        o.x = v.x * rs * w.x * fast_sigmoid(z.x);
        o.y = v.y * rs * w.y * fast_sigmoid(z.y);
        o.z = v.z * rs * w.z * fast_sigmoid(z.z);
        o.w = v.w * rs * w.w * fast_sigmoid(z.w);
        uint32_t h01, l01, h23, l23;
        split2(o.x, o.y, h01, l01);
        split2(o.z, o.w, h23, l23);
        gh[c] = make_uint2(h01, h23);
        gl[c] = make_uint2(l01, l23);
    }
}

// ---------------- launcher -------------------------------------------------
extern "C" void kernel_launch(void* const* d_in, const int* in_sizes, int n_in,
                              void* d_out, int out_size)
{
    const float* u        = (const float*)d_in[0];
    const float* in_proj  = (const float*)d_in[1];
    const float* conv_w   = (const float*)d_in[2];
    const float* conv_b   = (const float*)d_in[3];
    const float* dt_bias  = (const float*)d_in[4];
    const float* A_log    = (const float*)d_in[5];
    const float* Dv       = (const float*)d_in[6];
    const float* rms_w    = (const float*)d_in[7];
    const float* out_w    = (const float*)d_in[8];
    float* out = (float*)d_out;

    float *zx, *xbc, *ldec, *y, *st, *cum;
    __nv_bfloat16 *uhi, *ulo, *w1hi, *w1lo, *w2hi, *w2lo, *yghi, *yglo;
    cudaGetSymbolAddress((void**)&zx,   g_zx);
    cudaGetSymbolAddress((void**)&xbc,  g_xbc);
    cudaGetSymbolAddress((void**)&ldec, g_ldec);
    cudaGetSymbolAddress((void**)&y,    g_y);
    cudaGetSymbolAddress((void**)&st,   g_st);
    cudaGetSymbolAddress((void**)&cum,  g_cum);
    cudaGetSymbolAddress((void**)&uhi,  g_uhi);
    cudaGetSymbolAddress((void**)&ulo,  g_ulo);
    cudaGetSymbolAddress((void**)&w1hi, g_w1hi);
    cudaGetSymbolAddress((void**)&w1lo, g_w1lo);
    cudaGetSymbolAddress((void**)&w2hi, g_w2hi);
    cudaGetSymbolAddress((void**)&w2lo, g_w2lo);
    cudaGetSymbolAddress((void**)&yghi, g_yghi);
    cudaGetSymbolAddress((void**)&yglo, g_yglo);

    cudaFuncSetAttribute(gemm_bf16x3,
        cudaFuncAttributeMaxDynamicSharedMemorySize, GB_SMEM_BYTES);
    cudaFuncSetAttribute(scan_matmul_kernel,
        cudaFuncAttributeMaxDynamicSharedMemorySize, SC_SMEM);

    static cudaStream_t s1 = nullptr;
    static cudaEvent_t evFork = nullptr, evJoin = nullptr;
    if (!s1) {
        cudaStreamCreateWithFlags(&s1, cudaStreamNonBlocking);
        cudaEventCreateWithFlags(&evFork, cudaEventDisableTiming);
        cudaEventCreateWithFlags(&evJoin, cudaEventDisableTiming);
    }

    // 0) split u, w1
    {
        int n4u = NROWS * D_MODEL / 4;
        split_kernel<<<(n4u + 255) / 256, 256>>>(u, uhi, ulo, n4u);
        int n4w1 = D_IN_PROJ * D_MODEL / 4;
        split_kernel<<<(n4w1 + 255) / 256, 256>>>(in_proj, w1hi, w1lo, n4w1);
    }
    // 1a) in_proj GEMM, xBC+dt columns
    {
        const int Nxbc = D_IN_PROJ - D_INNER;
        dim3 grid((Nxbc + GB_N - 1) / GB_N, NROWS / GB_M);
        gemm_bf16x3<<<grid, 256, GB_SMEM_BYTES>>>(
            uhi, ulo,
            w1hi + (size_t)D_INNER * D_MODEL, w1lo + (size_t)D_INNER * D_MODEL,
            zx + D_INNER, NROWS, Nxbc, D_MODEL, D_IN_PROJ);
    }
    // fork: 1b) z columns + w2 split on side stream
    cudaEventRecord(evFork, 0);
    cudaStreamWaitEvent(s1, evFork, 0);
    {
        dim3 grid(D_INNER / GB_N, NROWS / GB_M);
        gemm_bf16x3<<<grid, 256, GB_SMEM_BYTES, s1>>>(
            uhi, ulo, w1hi, w1lo, zx, NROWS, D_INNER, D_MODEL, D_IN_PROJ);
        int n4w2 = D_MODEL * D_INNER / 4;
        split_kernel<<<(n4w2 + 255) / 256, 256, 0, s1>>>(out_w, w2hi, w2lo, n4w2);
    }
    cudaEventRecord(evJoin, s1);

    // 2) conv + silu
    {
        dim3 grid((CONV_DIM + 255) / 256, SEQLEN / 256, BATCH);
        conv_kernel<<<grid, 256>>>(zx, conv_w, conv_b, xbc);
    }
    // 3) log-decay precompute
    decay_kernel<<<(NROWS * NHEADS + 255) / 256, 256>>>(zx, dt_bias, A_log, ldec);
    // 4) chunked SSM scan — intra-chunk via tensor cores
    {
        dim3 grid(NCHUNK, NHEADS, BATCH);
        scan_matmul_kernel<<<grid, 256, SC_SMEM>>>(xbc, ldec, Dv, y, st, cum);
    }
    {
        dim3 grid(NHEADS, BATCH, 8);
        scan_combine_kernel<<<grid, 256>>>(st, cum);
    }
    {
        dim3 grid(NCHUNK, NHEADS, BATCH);
        scan_fix_kernel<<<grid, 128>>>(st, cum, xbc, y);
    }
    cudaStreamWaitEvent(0, evJoin, 0);
    // 5) rmsnorm + gate
    rms_gate_kernel<<<NROWS, 256>>>(y, zx, rms_w, yghi, yglo);
    // 6) out_proj GEMM
    {
        dim3 grid(D_MODEL / GB_N, NROWS / GB_M);
        gemm_bf16x3<<<grid, 256, GB_SMEM_BYTES>>>(yghi, yglo, w2hi, w2lo, out,
                                                  NROWS, D_MODEL, D_INNER, D_MODEL);
    }
}

// round 14
// speedup vs baseline: 1.4646x; 1.0740x over previous
#include <cuda_runtime.h>
#include <cuda_bf16.h>
#include <cstdint>
#include <math.h>

// ---------------- problem constants ----------------
#define D_MODEL   1024
#define D_INNER   2048
#define D_STATE   64
#define HEADDIM   128
#define NHEADS    16
#define D_CONV    4
#define CONV_DIM  2176
#define D_IN_PROJ 4240
#define BATCH     2
#define SEQLEN    4096
#define NROWS     (BATCH*SEQLEN)  // 8192
#define RMS_EPS   1e-5f

#define LCHUNK    128
#define NCHUNK    (SEQLEN/LCHUNK)   // 32

// ---------------- scratch ----------------
__device__ float g_zx  [(size_t)NROWS * D_IN_PROJ];
__device__ float g_xbc [(size_t)NROWS * CONV_DIM];
__device__ float g_ldec[(size_t)NROWS * NHEADS];
__device__ float g_y   [(size_t)NROWS * D_INNER];
__device__ float g_st  [(size_t)BATCH * NHEADS * NCHUNK * HEADDIM * D_STATE];
__device__ float g_cum [(size_t)BATCH * NHEADS * NCHUNK * LCHUNK];
__device__ __nv_bfloat16 g_uhi [(size_t)NROWS * D_MODEL];
__device__ __nv_bfloat16 g_ulo [(size_t)NROWS * D_MODEL];
__device__ __nv_bfloat16 g_w1hi[(size_t)D_IN_PROJ * D_MODEL];
__device__ __nv_bfloat16 g_w1lo[(size_t)D_IN_PROJ * D_MODEL];
__device__ __nv_bfloat16 g_w2hi[(size_t)D_MODEL * D_INNER];
__device__ __nv_bfloat16 g_w2lo[(size_t)D_MODEL * D_INNER];
__device__ __nv_bfloat16 g_yghi[(size_t)NROWS * D_INNER];
__device__ __nv_bfloat16 g_yglo[(size_t)NROWS * D_INNER];

// ================= helpers =================
__device__ __forceinline__ uint32_t smem_to_u32(const void* p) {
    uint32_t a;
    asm("{ .reg .u64 t; cvta.to.shared.u64 t, %1; cvt.u32.u64 %0, t; }"
        : "=r"(a) : "l"(p));
    return a;
}
__device__ __forceinline__ uint32_t pack_bf16(float lo_elem, float hi_elem) {
    uint32_t r;
    asm("cvt.rn.bf16x2.f32 %0, %1, %2;" : "=r"(r) : "f"(hi_elem), "f"(lo_elem));
    return r;
}
__device__ __forceinline__ void mma_bf16(float* d, const uint32_t* a,
                                         const uint32_t* b) {
    asm volatile(
        "mma.sync.aligned.m16n8k16.row.col.f32.bf16.bf16.f32 "
        "{%0,%1,%2,%3},{%4,%5,%6,%7},{%8,%9},{%0,%1,%2,%3};"
        : "+f"(d[0]), "+f"(d[1]), "+f"(d[2]), "+f"(d[3])
        : "r"(a[0]), "r"(a[1]), "r"(a[2]), "r"(a[3]), "r"(b[0]), "r"(b[1]));
}
__device__ __forceinline__ void ldsm_x4(uint32_t& r0, uint32_t& r1,
                                        uint32_t& r2, uint32_t& r3,
                                        uint32_t addr) {
    asm volatile("ldmatrix.sync.aligned.m8n8.x4.shared.b16 {%0,%1,%2,%3}, [%4];"
                 : "=r"(r0), "=r"(r1), "=r"(r2), "=r"(r3) : "r"(addr));
}
__device__ __forceinline__ float fast_sigmoid(float x) {
    return __fdividef(1.f, 1.f + __expf(-x));
}
__device__ __forceinline__ void split2(float a, float b, uint32_t& hp, uint32_t& lp) {
    hp = pack_bf16(a, b);
    float h0 = __uint_as_float(hp << 16);
    float h1 = __uint_as_float(hp & 0xffff0000u);
    lp = pack_bf16(a - h0, b - h1);
}
// swizzled addressing: 128B rows (64 bf16), col2 = uint32 index 0..31
__device__ __forceinline__ uint32_t a128(uint32_t base, int row, int col2) {
    return base + (uint32_t)(row * 128 + ((((col2 >> 2) ^ row) & 7) * 16) + (col2 & 3) * 4);
}
// swizzled addressing: 256B rows (128 bf16), col2 0..63
__device__ __forceinline__ uint32_t a256(uint32_t base, int row, int col2) {
    int cq = col2 >> 2;
    int ph = (((cq & 7) ^ (row & 7)) | (cq & 8));
    return base + (uint32_t)(row * 256 + ph * 16 + (col2 & 3) * 4);
}

// ================= split kernel ============================================
__global__ __launch_bounds__(256) void split_kernel(
    const float* __restrict__ in, __nv_bfloat16* __restrict__ hi,
    __nv_bfloat16* __restrict__ lo, int n4)
{
    int i = blockIdx.x * 256 + threadIdx.x;
    if (i >= n4) return;
    float4 v = ((const float4*)in)[i];
    uint32_t h01, l01, h23, l23;
    split2(v.x, v.y, h01, l01);
    split2(v.z, v.w, h23, l23);
    ((uint2*)hi)[i] = make_uint2(h01, h23);
    ((uint2*)lo)[i] = make_uint2(l01, l23);
}

// ================= GEMM (bf16x3, ldmatrix + 3-stage cp.async) ==============
#define GB_M 128
#define GB_N 128
#define GB_K 32
#define GB_STAGE 32768
#define GB_SMEM_BYTES (3 * GB_STAGE)

__global__ __launch_bounds__(256, 2) void gemm_bf16x3(
    const __nv_bfloat16* __restrict__ Ahi, const __nv_bfloat16* __restrict__ Alo,
    const __nv_bfloat16* __restrict__ Bhi, const __nv_bfloat16* __restrict__ Blo,
    float* __restrict__ C, int M, int N, int K, int ldc)
{
    extern __shared__ char smem[];
    const uint32_t sbase = smem_to_u32(smem);
    const int tid = threadIdx.x;
    const int bm  = blockIdx.y * GB_M;
    const int bn  = blockIdx.x * GB_N;
    const int nch = K / GB_K;

    const int warp = tid >> 5;
    const int lane = tid & 31;
    const int wm = warp >> 2;
    const int wn = warp & 3;
    const int lr = lane >> 2;
    const int lc = lane & 3;

    float acc[4][4][4];
    #pragma unroll
    for (int mt = 0; mt < 4; mt++)
        #pragma unroll
        for (int nt = 0; nt < 4; nt++)
            #pragma unroll
            for (int q = 0; q < 4; q++) acc[mt][nt][q] = 0.f;

    auto load_stage = [&](int buf, int kt) {
        #pragma unroll
        for (int i = 0; i < 8; i++) {
            int idx = tid + i * 256;
            int cq = idx & 3;
            int r  = (idx >> 2) & 127;
            int t  = idx >> 9;
            uint32_t so = sbase + (uint32_t)buf * GB_STAGE + (uint32_t)t * 8192 +
                          (uint32_t)r * 64 + (uint32_t)((cq ^ ((r >> 1) & 3)) * 16);
            const __nv_bfloat16* g;
            if (t == 0)      g = Ahi + (size_t)(bm + r) * K;
            else if (t == 1) g = Alo + (size_t)(bm + r) * K;
            else {
                int gn = bn + r; if (gn >= N) gn = N - 1;
                g = (t == 2 ? Bhi : Blo) + (size_t)gn * K;
            }
            g += kt + cq * 8;
            asm volatile("cp.async.cg.shared.global [%0], [%1], 16;"
                         :: "r"(so), "l"(g));
        }
        asm volatile("cp.async.commit_group;");
    };

    load_stage(0, 0);
    if (nch > 1) load_stage(1, GB_K);

    const int rowA = wm * 64 + ((lane >> 3) & 1) * 8 + (lane & 7);
    const int rowB = wn * 32 + ((lane >> 4) & 1) * 8 + (lane & 7);
    const int sel  = ((lane & 7) >> 1) & 3;
    const int cAq  = (lane >> 4) & 1;
    const int cBq  = (lane >> 3) & 1;

    for (int c = 0; c < nch; c++) {
        if (c == nch - 1) asm volatile("cp.async.wait_group 0;");
        else              asm volatile("cp.async.wait_group 1;");
        __syncthreads();
        if (c + 2 < nch) load_stage((c + 2) % 3, (c + 2) * GB_K);

        const uint32_t stg = sbase + (uint32_t)(c % 3) * GB_STAGE;
        const uint32_t baseAhi = stg + (uint32_t)rowA * 64;
        const uint32_t baseAlo = baseAhi + 8192;
        const uint32_t baseBhi = stg + 16384 + (uint32_t)rowB * 64;
        const uint32_t baseBlo = baseBhi + 8192;

        #pragma unroll
        for (int ks = 0; ks < 2; ks++) {
            const uint32_t cAo = (uint32_t)(((ks * 2 + cAq) ^ sel) * 16);
            const uint32_t cBo = (uint32_t)(((ks * 2 + cBq) ^ sel) * 16);

            uint32_t bh[4][2], bl[4][2];
            #pragma unroll
            for (int ntp = 0; ntp < 2; ntp++) {
                uint32_t r0, r1, r2, r3;
                ldsm_x4(r0, r1, r2, r3, baseBhi + ntp * 1024 + cBo);
                bh[ntp*2][0] = r0; bh[ntp*2][1] = r1;
                bh[ntp*2+1][0] = r2; bh[ntp*2+1][1] = r3;
                ldsm_x4(r0, r1, r2, r3, baseBlo + ntp * 1024 + cBo);
                bl[ntp*2][0] = r0; bl[ntp*2][1] = r1;
                bl[ntp*2+1][0] = r2; bl[ntp*2+1][1] = r3;
            }
            #pragma unroll
            for (int mt = 0; mt < 4; mt++) {
                uint32_t ah[4], al[4];
                ldsm_x4(ah[0], ah[1], ah[2], ah[3], baseAhi + mt * 1024 + cAo);
                ldsm_x4(al[0], al[1], al[2], al[3], baseAlo + mt * 1024 + cAo);
                #pragma unroll
                for (int nt = 0; nt < 4; nt++) {
                    mma_bf16(acc[mt][nt], ah, bh[nt]);
                    mma_bf16(acc[mt][nt], ah, bl[nt]);
                    mma_bf16(acc[mt][nt], al, bh[nt]);
                }
            }
        }
    }

    #pragma unroll
    for (int mt = 0; mt < 4; mt++) {
        int row = bm + wm * 64 + mt * 16 + lr;
        #pragma unroll
        for (int nt = 0; nt < 4; nt++) {
            int col = bn + wn * 32 + nt * 8 + lc * 2;
            if (col + 1 < N) {
                *(float2*)(C + (size_t)row * ldc + col) =
                    make_float2(acc[mt][nt][0], acc[mt][nt][1]);
                *(float2*)(C + (size_t)(row + 8) * ldc + col) =
                    make_float2(acc[mt][nt][2], acc[mt][nt][3]);
            }
        }
    }
}

// ---------------- depthwise causal conv (k=4) + bias + SiLU ----------------
__global__ __launch_bounds__(256) void conv_kernel(
    const float* __restrict__ zx, const float* __restrict__ cw,
    const float* __restrict__ cb, float* __restrict__ xbc)
{
    int c = blockIdx.x * 256 + threadIdx.x;
    if (c >= CONV_DIM) return;
    int strip = blockIdx.y;
    int b     = blockIdx.z;
    int l0    = strip * 256;

    float w0 = cw[c*4+0], w1 = cw[c*4+1], w2 = cw[c*4+2], w3 = cw[c*4+3];
    float bias = cb[c];

    size_t colbase = (size_t)D_INNER + c;
    size_t rb = (size_t)b * SEQLEN;

    float xm3 = (l0-3 >= 0) ? zx[(rb + l0-3) * D_IN_PROJ + colbase] : 0.f;
    float xm2 = (l0-2 >= 0) ? zx[(rb + l0-2) * D_IN_PROJ + colbase] : 0.f;
    float xm1 = (l0-1 >= 0) ? zx[(rb + l0-1) * D_IN_PROJ + colbase] : 0.f;

    for (int l = l0; l < l0 + 256; l++) {
        float xv = zx[(rb + l) * D_IN_PROJ + colbase];
        float a = bias;
        a = fmaf(w0, xm3, a);
        a = fmaf(w1, xm2, a);
        a = fmaf(w2, xm1, a);
        a = fmaf(w3, xv,  a);
        float sv = a * fast_sigmoid(a);
        xbc[(rb + l) * CONV_DIM + c] = sv;
        xm3 = xm2; xm2 = xm1; xm1 = xv;
    }
}

// ---------------- dt -> softplus -> LOG decay ------------------------------
__global__ __launch_bounds__(256) void decay_kernel(
    const float* __restrict__ zx, const float* __restrict__ dt_bias,
    const float* __restrict__ A_log, float* __restrict__ ldec)
{
    int idx = blockIdx.x * 256 + threadIdx.x;
    if (idx >= NROWS * NHEADS) return;
    int r = idx >> 4;
    int h = idx & 15;
    float raw = zx[(size_t)r * D_IN_PROJ + (D_IN_PROJ - NHEADS) + h] + dt_bias[h];
    float sp  = (raw > 20.f) ? raw : log1pf(expf(raw));
    float A   = -expf(A_log[h]);
    ldec[idx] = sp * A;
}

// ================= chunked matmul scan (intra-chunk) ======================
#define SC_XTH 0u
#define SC_XTL 32768u
#define SC_GA  65536u
#define SC_WBH 131072u
#define SC_WBL 147456u
#define SC_L   163840u
#define SC_STG 164352u
#define SC_SMEM 181248u          // + 128*33*4 staging

__global__ __launch_bounds__(256, 1) void scan_matmul_kernel(
    const float* __restrict__ xbc, const float* __restrict__ ldec,
    const float* __restrict__ Dvec, float* __restrict__ yout,
    float* __restrict__ states, float* __restrict__ cumout)
{
    extern __shared__ char smem[];
    const uint32_t sb = smem_to_u32(smem);
    const int c = blockIdx.x;
    const int h = blockIdx.y;
    const int b = blockIdx.z;
    const int t = threadIdx.x;
    const int warp = t >> 5;
    const int lane = t & 31;
    const int lr = lane >> 2;
    const int lc = lane & 3;

    const size_t base = (size_t)b * SEQLEN + (size_t)c * LCHUNK;
    const int xcol = h * HEADDIM;
    const size_t cumbase = (size_t)(((b * NHEADS + h) * NCHUNK) + c) * LCHUNK;

    float* Lsm = (float*)(smem + SC_L);
    float* stg = (float*)(smem + SC_STG);

    // ---- load B, C (bf16-split, swizzled 128B rows [time][n]) ----
    {
        const uint32_t CH = sb + SC_GA, CL = CH + 16384;
        const uint32_t BH = sb + SC_GA + 32768, BL = BH + 16384;
        #pragma unroll
        for (int i = 0; i < 16; i++) {
            int idx = t + i * 256;
            int s = idx >> 5, col2 = idx & 31;
            const float* row = xbc + (base + s) * CONV_DIM + D_INNER;
            float2 vB = *(const float2*)(row + col2 * 2);
            float2 vC = *(const float2*)(row + 64 + col2 * 2);
            uint32_t hp, lp;
            split2(vB.x, vB.y, hp, lp);
            *(uint32_t*)(smem + (a128(BH, s, col2) - sb)) = hp;
            *(uint32_t*)(smem + (a128(BL, s, col2) - sb)) = lp;
            split2(vC.x, vC.y, hp, lp);
            *(uint32_t*)(smem + (a128(CH, s, col2) - sb)) = hp;
            *(uint32_t*)(smem + (a128(CL, s, col2) - sb)) = lp;
        }
    }

    // ---- log-decay prefix (warp 0) + cum output ----
    if (warp == 0) {
        float v0 = ldec[(base + lane * 4 + 0) * NHEADS + h];
        float v1 = ldec[(base + lane * 4 + 1) * NHEADS + h];
        float v2 = ldec[(base + lane * 4 + 2) * NHEADS + h];
        float v3 = ldec[(base + lane * 4 + 3) * NHEADS + h];
        float p0 = v0, p1 = p0 + v1, p2 = p1 + v2, p3 = p2 + v3;
        float inc = p3;
        #pragma unroll
        for (int o = 1; o < 32; o <<= 1) {
            float n = __shfl_up_sync(0xffffffffu, inc, o);
            if (lane >= o) inc += n;
        }
        float excl = inc - p3;
        Lsm[lane*4+0] = excl + p0;
        Lsm[lane*4+1] = excl + p1;
        Lsm[lane*4+2] = excl + p2;
        Lsm[lane*4+3] = excl + p3;
        cumout[cumbase + lane*4+0] = __expf(excl + p0);
        cumout[cumbase + lane*4+1] = __expf(excl + p1);
        cumout[cumbase + lane*4+2] = __expf(excl + p2);
        cumout[cumbase + lane*4+3] = __expf(excl + p3);
    }

    // ---- X transpose: 4 strips of 128l x 32p, 2 syncs each ----
    #pragma unroll 1
    for (int pt = 0; pt < 4; pt++) {
        #pragma unroll
        for (int i = 0; i < 16; i++) {
            int idx = t + i * 256;          // 0..4095
            int row = idx >> 5;             // l 0..127
            int colp = idx & 31;
            stg[row * 33 + colp] =
                xbc[(base + row) * CONV_DIM + xcol + pt * 32 + colp];
        }
        __syncthreads();
        #pragma unroll
        for (int i = 0; i < 8; i++) {
            int idx = t + i * 256;          // 0..2047
            int ploc = idx >> 6;            // 0..31
            int col2 = idx & 63;            // l-pair
            float v0 = stg[(col2 * 2) * 33 + ploc];
            float v1 = stg[(col2 * 2 + 1) * 33 + ploc];
            int p = pt * 32 + ploc;
            uint32_t hp, lp;
            split2(v0, v1, hp, lp);
            *(uint32_t*)(smem + (a256(sb + SC_XTH, p, col2) - sb)) = hp;
            *(uint32_t*)(smem + (a256(sb + SC_XTL, p, col2) - sb)) = lp;
        }
        __syncthreads();
    }

    // ---- step 1: G = C·B^T  (M=128 l, N=128 s, K=64 n) ----
    const int wm = warp >> 2, wn = warp & 3;
    const int rowA = wm * 64 + ((lane >> 3) & 1) * 8 + (lane & 7);
    const int rowB = wn * 32 + ((lane >> 4) & 1) * 8 + (lane & 7);
    const int cAq = (lane >> 4) & 1;
    const int cBq = (lane >> 3) & 1;
    const int rA7 = rowA & 7, rB7 = rowB & 7;

    float acc1[4][4][4];
    #pragma unroll
    for (int mt = 0; mt < 4; mt++)
        #pragma unroll
        for (int nt = 0; nt < 4; nt++)
            #pragma unroll
            for (int q = 0; q < 4; q++) acc1[mt][nt][q] = 0.f;

    {
        const uint32_t aCH = sb + SC_GA + (uint32_t)rowA * 128;
        const uint32_t aCL = aCH + 16384;
        const uint32_t aBH = sb + SC_GA + 32768 + (uint32_t)rowB * 128;
        const uint32_t aBL = aBH + 16384;
        #pragma unroll
        for (int ks = 0; ks < 4; ks++) {
            uint32_t offA = (uint32_t)((((ks * 2 + cAq) ^ rA7) & 7) * 16);
            uint32_t offB = (uint32_t)((((ks * 2 + cBq) ^ rB7) & 7) * 16);
            uint32_t bh[4][2], bl[4][2];
            #pragma unroll
            for (int ntp = 0; ntp < 2; ntp++) {
                uint32_t r0, r1, r2, r3;
                ldsm_x4(r0, r1, r2, r3, aBH + ntp * 2048 + offB);
                bh[ntp*2][0]=r0; bh[ntp*2][1]=r1; bh[ntp*2+1][0]=r2; bh[ntp*2+1][1]=r3;
                ldsm_x4(r0, r1, r2, r3, aBL + ntp * 2048 + offB);
                bl[ntp*2][0]=r0; bl[ntp*2][1]=r1; bl[ntp*2+1][0]=r2; bl[ntp*2+1][1]=r3;
            }
            #pragma unroll
            for (int mt = 0; mt < 4; mt++) {
                uint32_t ah[4], al[4];
                ldsm_x4(ah[0], ah[1], ah[2], ah[3], aCH + mt * 2048 + offA);
                ldsm_x4(al[0], al[1], al[2], al[3], aCL + mt * 2048 + offA);
                #pragma unroll
                for (int nt = 0; nt < 4; nt++) {
                    mma_bf16(acc1[mt][nt], ah, bh[nt]);
                    mma_bf16(acc1[mt][nt], ah, bl[nt]);
                    mma_bf16(acc1[mt][nt], al, bh[nt]);
                }
            }
        }
    }

    // ---- WB[n][s] = exp(L_last - L_s) * B[s][n] ----
    {
        const float Llast = Lsm[127];
        const uint32_t BH = sb + SC_GA + 32768, BL = BH + 16384;
        int n = t >> 2;
        int s0 = (t & 3) * 32;
        #pragma unroll
        for (int sp = 0; sp < 16; sp++) {
            int sA = s0 + sp * 2, sB2 = sA + 1;
            uint32_t wA = *(uint32_t*)(smem + (a128(BH, sA, n >> 1) - sb));
            uint32_t lA = *(uint32_t*)(smem + (a128(BL, sA, n >> 1) - sb));
            uint32_t wB = *(uint32_t*)(smem + (a128(BH, sB2, n >> 1) - sb));
            uint32_t lB = *(uint32_t*)(smem + (a128(BL, sB2, n >> 1) - sb));
            uint32_t hbA = (n & 1) ? (wA & 0xffff0000u) : (wA << 16);
            uint32_t lbA = (n & 1) ? (lA & 0xffff0000u) : (lA << 16);
            uint32_t hbB = (n & 1) ? (wB & 0xffff0000u) : (wB << 16);
            uint32_t lbB = (n & 1) ? (lB & 0xffff0000u) : (lB << 16);
            float bA = __uint_as_float(hbA) + __uint_as_float(lbA);
            float bB = __uint_as_float(hbB) + __uint_as_float(lbB);
            float vA = bA * __expf(Llast - Lsm[sA]);
            float vB = bB * __expf(Llast - Lsm[sB2]);
            uint32_t hp, lp;
            split2(vA, vB, hp, lp);
            *(uint32_t*)(smem + (a256(sb + SC_WBH, n, sA >> 1) - sb)) = hp;
            *(uint32_t*)(smem + (a256(sb + SC_WBL, n, sA >> 1) - sb)) = lp;
        }
    }
    __syncthreads();

    // ---- write G (overwrites C/B region): scale+mask, split bf16 ----
    {
        const uint32_t GH = sb + SC_GA, GL = GH + 32768;
        #pragma unroll
        for (int mt = 0; mt < 4; mt++) {
            int l0 = wm * 64 + mt * 16 + lr;
            int l1 = l0 + 8;
            #pragma unroll
            for (int nt = 0; nt < 4; nt++) {
                int s0 = wn * 32 + nt * 8 + lc * 2;
                float Ll0 = Lsm[l0], Ll1 = Lsm[l1];
                float Ls0 = Lsm[s0], Ls1 = Lsm[s0 + 1];
                float e00 = (s0     <= l0) ? acc1[mt][nt][0] * __expf(Ll0 - Ls0) : 0.f;
                float e01 = (s0 + 1 <= l0) ? acc1[mt][nt][1] * __expf(Ll0 - Ls1) : 0.f;
                float e10 = (s0     <= l1) ? acc1[mt][nt][2] * __expf(Ll1 - Ls0) : 0.f;
                float e11 = (s0 + 1 <= l1) ? acc1[mt][nt][3] * __expf(Ll1 - Ls1) : 0.f;
                uint32_t hp, lp;
                split2(e00, e01, hp, lp);
                *(uint32_t*)(smem + (a256(GH, l0, s0 >> 1) - sb)) = hp;
                *(uint32_t*)(smem + (a256(GL, l0, s0 >> 1) - sb)) = lp;
                split2(e10, e11, hp, lp);
                *(uint32_t*)(smem + (a256(GH, l1, s0 >> 1) - sb)) = hp;
                *(uint32_t*)(smem + (a256(GL, l1, s0 >> 1) - sb)) = lp;
            }
        }
    }
    __syncthreads();

    // ---- step 3: Y = G @ X   (M=128 l, N=128 p, K=128 s) ----
    {
        float acc3[4][4][4];
        #pragma unroll
        for (int mt = 0; mt < 4; mt++)
            #pragma unroll
            for (int nt = 0; nt < 4; nt++)
                #pragma unroll
                for (int q = 0; q < 4; q++) acc3[mt][nt][q] = 0.f;

        const uint32_t aGH = sb + SC_GA + (uint32_t)rowA * 256;
        const uint32_t aGL = aGH + 32768;
        const uint32_t aXH = sb + SC_XTH + (uint32_t)rowB * 256;
        const uint32_t aXL = aXH + 32768;
        #pragma unroll
        for (int ks = 0; ks < 8; ks++) {
            int cqa = ks * 2 + cAq;
            int cqb = ks * 2 + cBq;
            uint32_t offA = (uint32_t)(((((cqa & 7) ^ rA7)) | (cqa & 8)) * 16);
            uint32_t offB = (uint32_t)(((((cqb & 7) ^ rB7)) | (cqb & 8)) * 16);
            uint32_t bh[4][2], bl[4][2];
            #pragma unroll
            for (int ntp = 0; ntp < 2; ntp++) {
                uint32_t r0, r1, r2, r3;
                ldsm_x4(r0, r1, r2, r3, aXH + ntp * 4096 + offB);
                bh[ntp*2][0]=r0; bh[ntp*2][1]=r1; bh[ntp*2+1][0]=r2; bh[ntp*2+1][1]=r3;
                ldsm_x4(r0, r1, r2, r3, aXL + ntp * 4096 + offB);
                bl[ntp*2][0]=r0; bl[ntp*2][1]=r1; bl[ntp*2+1][0]=r2; bl[ntp*2+1][1]=r3;
            }
            #pragma unroll
            for (int mt = 0; mt < 4; mt++) {
                uint32_t ah[4], al[4];
                ldsm_x4(ah[0], ah[1], ah[2], ah[3], aGH + mt * 4096 + offA);
                ldsm_x4(al[0], al[1], al[2], al[3], aGL + mt * 4096 + offA);
                #pragma unroll
                for (int nt = 0; nt < 4; nt++) {
                    mma_bf16(acc3[mt][nt], ah, bh[nt]);
                    mma_bf16(acc3[mt][nt], ah, bl[nt]);
                    mma_bf16(acc3[mt][nt], al, bh[nt]);
                }
            }
        }
        const float Dh = Dvec[h];
        #pragma unroll
        for (int mt = 0; mt < 4; mt++) {
            int l0 = wm * 64 + mt * 16 + lr;
            int l1 = l0 + 8;
            #pragma unroll
            for (int nt = 0; nt < 4; nt++) {
                int p0 = wn * 32 + nt * 8 + lc * 2;
                float2 x0 = *(const float2*)(xbc + (base + l0) * CONV_DIM + xcol + p0);
                float2 x1 = *(const float2*)(xbc + (base + l1) * CONV_DIM + xcol + p0);
                *(float2*)(yout + (base + l0) * D_INNER + xcol + p0) =
                    make_float2(fmaf(Dh, x0.x, acc3[mt][nt][0]),
                                fmaf(Dh, x0.y, acc3[mt][nt][1]));
                *(float2*)(yout + (base + l1) * D_INNER + xcol + p0) =
                    make_float2(fmaf(Dh, x1.x, acc3[mt][nt][2]),
                                fmaf(Dh, x1.y, acc3[mt][nt][3]));
            }
        }
    }

    // ---- step 4: S_end[p][n] = X^T @ WB^T  (M=128 p, N=64 n, K=128 s) ----
    {
        const int wm4 = warp >> 1, wn4 = warp & 1;
        const int rowA4 = wm4 * 32 + ((lane >> 3) & 1) * 8 + (lane & 7);
        const int rowB4 = wn4 * 32 + ((lane >> 4) & 1) * 8 + (lane & 7);
        const int rA47 = rowA4 & 7, rB47 = rowB4 & 7;

        float acc4[2][4][4];
        #pragma unroll
        for (int mt = 0; mt < 2; mt++)
            #pragma unroll
            for (int nt = 0; nt < 4; nt++)
                #pragma unroll
                for (int q = 0; q < 4; q++) acc4[mt][nt][q] = 0.f;

        const uint32_t aXH = sb + SC_XTH + (uint32_t)rowA4 * 256;
        const uint32_t aXL = aXH + 32768;
        const uint32_t aWH = sb + SC_WBH + (uint32_t)rowB4 * 256;
        const uint32_t aWL = aWH + 16384;
        #pragma unroll
        for (int ks = 0; ks < 8; ks++) {
            int cqa = ks * 2 + cAq;
            int cqb = ks * 2 + cBq;
            uint32_t offA = (uint32_t)(((((cqa & 7) ^ rA47)) | (cqa & 8)) * 16);
            uint32_t offB = (uint32_t)(((((cqb & 7) ^ rB47)) | (cqb & 8)) * 16);
            uint32_t bh[4][2], bl[4][2];
            #pragma unroll
            for (int ntp = 0; ntp < 2; ntp++) {
                uint32_t r0, r1, r2, r3;
                ldsm_x4(r0, r1, r2, r3, aWH + ntp * 4096 + offB);
                bh[ntp*2][0]=r0; bh[ntp*2][1]=r1; bh[ntp*2+1][0]=r2; bh[ntp*2+1][1]=r3;
                ldsm_x4(r0, r1, r2, r3, aWL + ntp * 4096 + offB);
                bl[ntp*2][0]=r0; bl[ntp*2][1]=r1; bl[ntp*2+1][0]=r2; bl[ntp*2+1][1]=r3;
            }
            #pragma unroll
            for (int mt = 0; mt < 2; mt++) {
                uint32_t ah[4], al[4];
                ldsm_x4(ah[0], ah[1], ah[2], ah[3], aXH + mt * 4096 + offA);
                ldsm_x4(al[0], al[1], al[2], al[3], aXL + mt * 4096 + offA);
                #pragma unroll
                for (int nt = 0; nt < 4; nt++) {
                    mma_bf16(acc4[mt][nt], ah, bh[nt]);
                    mma_bf16(acc4[mt][nt], ah, bl[nt]);
                    mma_bf16(acc4[mt][nt], al, bh[nt]);
                }
            }
        }
        float* stbase = states +
            ((size_t)(((b * NHEADS + h) * NCHUNK) + c) * HEADDIM) * D_STATE;
        #pragma unroll
        for (int mt = 0; mt < 2; mt++) {
            int p0 = wm4 * 32 + mt * 16 + lr;
            int p1 = p0 + 8;
            #pragma unroll
            for (int nt = 0; nt < 4; nt++) {
                int n0 = wn4 * 32 + nt * 8 + lc * 2;
                *(float2*)(stbase + (size_t)p0 * D_STATE + n0) =
                    make_float2(acc4[mt][nt][0], acc4[mt][nt][1]);
                *(float2*)(stbase + (size_t)p1 * D_STATE + n0) =
                    make_float2(acc4[mt][nt][2], acc4[mt][nt][3]);
            }
        }
    }
}

// ---------------- chunked scan: stage 2 (combine, p-sliced) ----------------
__global__ __launch_bounds__(256) void scan_combine_kernel(
    float* __restrict__ states, const float* __restrict__ cum)
{
    const int h   = blockIdx.x;
    const int b   = blockIdx.y;
    const int sl  = blockIdx.z;
    const int tid = threadIdx.x;

    __shared__ float dprod[NCHUNK];
    if (tid < NCHUNK)
        dprod[tid] = cum[(size_t)(((b * NHEADS + h) * NCHUNK) + tid) * LCHUNK + LCHUNK - 1];
    __syncthreads();

    const size_t chunk_stride = (size_t)HEADDIM * D_STATE;
    float* base = states + (size_t)((b * NHEADS + h) * NCHUNK) * chunk_stride
                         + (size_t)sl * 1024;

    float4 e = make_float4(0.f, 0.f, 0.f, 0.f);
    const int idx = tid;

    for (int c = 0; c < NCHUNK; c++) {
        float d = dprod[c];
        float4* p = (float4*)(base + c * chunk_stride);
        float4 s = p[idx];
        p[idx] = e;
        e.x = fmaf(e.x, d, s.x);
        e.y = fmaf(e.y, d, s.y);
        e.z = fmaf(e.z, d, s.z);
        e.w = fmaf(e.w, d, s.w);
    }
}

// ---------------- chunked scan: stage 3 (tensor-core GEMM) -----------------
// Y[l][p] += (cum_l*C[l]) @ S_entry[p]^T ; M=128, N=128, K=64.
#define FX_AH 0u
#define FX_AL 16384u
#define FX_BH 32768u
#define FX_BL 49152u
#define FX_CUM 65536u
#define FX_SMEM 66048u

__global__ __launch_bounds__(256) void scan_fix_mm(
    const float* __restrict__ states, const float* __restrict__ cum,
    const float* __restrict__ xbc, float* __restrict__ yout)
{
    extern __shared__ char smem[];
    const uint32_t sb = smem_to_u32(smem);
    const int c = blockIdx.x + 1;        // chunk 0 needs no fix
    const int h = blockIdx.y;
    const int b = blockIdx.z;
    const int t = threadIdx.x;
    const int warp = t >> 5, lane = t & 31;
    const int lr = lane >> 2, lc = lane & 3;
    const int wm = warp >> 2, wn = warp & 3;

    const size_t base = (size_t)b * SEQLEN + (size_t)c * LCHUNK;
    const size_t cumbase = (size_t)(((b * NHEADS + h) * NCHUNK) + c) * LCHUNK;
    const int xcol = h * HEADDIM;
    float* cum_sm = (float*)(smem + FX_CUM);

    if (t < 128) cum_sm[t] = cum[cumbase + t];
    __syncthreads();

    const float* stbase = states +
        ((size_t)(((b * NHEADS + h) * NCHUNK) + c) * HEADDIM) * D_STATE;
    #pragma unroll
    for (int i = 0; i < 16; i++) {
        int idx = t + i * 256;
        int r = idx >> 5, col2 = idx & 31;
        float cm = cum_sm[r];
        float2 vC = *(const float2*)(xbc + (base + r) * CONV_DIM + D_INNER + 64 + col2 * 2);
        uint32_t hp, lp;
        split2(vC.x * cm, vC.y * cm, hp, lp);
        *(uint32_t*)(smem + (a128(sb + FX_AH, r, col2) - sb)) = hp;
        *(uint32_t*)(smem + (a128(sb + FX_AL, r, col2) - sb)) = lp;
        float2 vS = *(const float2*)(stbase + (size_t)r * D_STATE + col2 * 2);
        split2(vS.x, vS.y, hp, lp);
        *(uint32_t*)(smem + (a128(sb + FX_BH, r, col2) - sb)) = hp;
        *(uint32_t*)(smem + (a128(sb + FX_BL, r, col2) - sb)) = lp;
    }
    __syncthreads();

    const int rowA = wm * 64 + ((lane >> 3) & 1) * 8 + (lane & 7);
    const int rowB = wn * 32 + ((lane >> 4) & 1) * 8 + (lane & 7);
    const int cAq = (lane >> 4) & 1;
    const int cBq = (lane >> 3) & 1;
    const int rA7 = rowA & 7, rB7 = rowB & 7;

    float acc[4][4][4];
    #pragma unroll
    for (int mt = 0; mt < 4; mt++)
        #pragma unroll
        for (int nt = 0; nt < 4; nt++)
            #pragma unroll
            for (int q = 0; q < 4; q++) acc[mt][nt][q] = 0.f;

    {
        const uint32_t aAH = sb + FX_AH + (uint32_t)rowA * 128;
        const uint32_t aAL = aAH + 16384;
        const uint32_t aBH = sb + FX_BH + (uint32_t)rowB * 128;
        const uint32_t aBL = aBH + 16384;
        #pragma unroll
        for (int ks = 0; ks < 4; ks++) {
            uint32_t offA = (uint32_t)((((ks * 2 + cAq) ^ rA7) & 7) * 16);
            uint32_t offB = (uint32_t)((((ks * 2 + cBq) ^ rB7) & 7) * 16);
            uint32_t bh[4][2], bl[4][2];
            #pragma unroll
            for (int ntp = 0; ntp < 2; ntp++) {
                uint32_t r0, r1, r2, r3;
                ldsm_x4(r0, r1, r2, r3, aBH + ntp * 2048 + offB);
                bh[ntp*2][0]=r0; bh[ntp*2][1]=r1; bh[ntp*2+1][0]=r2; bh[ntp*2+1][1]=r3;
                ldsm_x4(r0, r1, r2, r3, aBL + ntp * 2048 + offB);
                bl[ntp*2][0]=r0; bl[ntp*2][1]=r1; bl[ntp*2+1][0]=r2; bl[ntp*2+1][1]=r3;
            }
            #pragma unroll
            for (int mt = 0; mt < 4; mt++) {
                uint32_t ah[4], al[4];
                ldsm_x4(ah[0], ah[1], ah[2], ah[3], aAH + mt * 2048 + offA);
                ldsm_x4(al[0], al[1], al[2], al[3], aAL + mt * 2048 + offA);
                #pragma unroll
                for (int nt = 0; nt < 4; nt++) {
                    mma_bf16(acc[mt][nt], ah, bh[nt]);
                    mma_bf16(acc[mt][nt], ah, bl[nt]);
                    mma_bf16(acc[mt][nt], al, bh[nt]);
                }
            }
        }
    }

    #pragma unroll
    for (int mt = 0; mt < 4; mt++) {
        int l0 = wm * 64 + mt * 16 + lr;
        int l1 = l0 + 8;
        #pragma unroll
        for (int nt = 0; nt < 4; nt++) {
            int p0 = wn * 32 + nt * 8 + lc * 2;
            float2* y0 = (float2*)(yout + (base + l0) * D_INNER + xcol + p0);
            float2* y1 = (float2*)(yout + (base + l1) * D_INNER + xcol + p0);
            float2 v0 = *y0, v1 = *y1;
            v0.x += acc[mt][nt][0]; v0.y += acc[mt][nt][1];
            v1.x += acc[mt][nt][2]; v1.y += acc[mt][nt][3];
            *y0 = v0; *y1 = v1;
        }
    }
}

// ---------------- RMSNorm + gate, fused bf16 split output ------------------
__global__ __launch_bounds__(256) void rms_gate_kernel(
    const float* __restrict__ y, const float* __restrict__ zx,
    const float* __restrict__ rmsw,
    __nv_bfloat16* __restrict__ ygh, __nv_bfloat16* __restrict__ ygl)
{
    int r = blockIdx.x;
    const float*  yr = y  + (size_t)r * D_INNER;
    const float*  zr = zx + (size_t)r * D_IN_PROJ;
    const float4* y4 = (const float4*)yr;

    int tid = threadIdx.x;
    float ss = 0.f;
    #pragma unroll
    for (int i = 0; i < 2; i++) {
        float4 v = y4[tid + i * 256];
        ss += v.x*v.x + v.y*v.y + v.z*v.z + v.w*v.w;
    }
    #pragma unroll
    for (int o = 16; o > 0; o >>= 1) ss += __shfl_xor_sync(0xffffffffu, ss, o);
    __shared__ float red[8];
    if ((tid & 31) == 0) red[tid >> 5] = ss;
    __syncthreads();
    if (tid == 0) {
        float t = 0.f;
        #pragma unroll
        for (int i = 0; i < 8; i++) t += red[i];
        red[0] = rsqrtf(t * (1.f / D_INNER) + RMS_EPS);
    }
    __syncthreads();
    float rs = red[0];

    const float4* z4 = (const float4*)zr;
    const float4* w4 = (const float4*)rmsw;
    uint2* gh = (uint2*)(ygh + (size_t)r * D_INNER);
    uint2* gl = (uint2*)(ygl + (size_t)r * D_INNER);
    #pragma unroll
    for (int i = 0; i < 2; i++) {
        int c = tid + i * 256;
        float4 v = y4[c];
        float4 z = z4[c];
        float4 w = w4[c];
        float4 o;
        o.x = v.x * rs * w.x * fast_sigmoid(z.x);
        o.y = v.y * rs * w.y * fast_sigmoid(z.y);
        o.z = v.z * rs * w.z * fast_sigmoid(z.z);
        o.w = v.w * rs * w.w * fast_sigmoid(z.w);
        uint32_t h01, l01, h23, l23;
        split2(o.x, o.y, h01, l01);
        split2(o.z, o.w, h23, l23);
        gh[c] = make_uint2(h01, h23);
        gl[c] = make_uint2(l01, l23);
    }
}

// ---------------- launcher -------------------------------------------------
extern "C" void kernel_launch(void* const* d_in, const int* in_sizes, int n_in,
                              void* d_out, int out_size)
{
    const float* u        = (const float*)d_in[0];
    const float* in_proj  = (const float*)d_in[1];
    const float* conv_w   = (const float*)d_in[2];
    const float* conv_b   = (const float*)d_in[3];
    const float* dt_bias  = (const float*)d_in[4];
    const float* A_log    = (const float*)d_in[5];
    const float* Dv       = (const float*)d_in[6];
    const float* rms_w    = (const float*)d_in[7];
    const float* out_w    = (const float*)d_in[8];
    float* out = (float*)d_out;

    float *zx, *xbc, *ldec, *y, *st, *cum;
    __nv_bfloat16 *uhi, *ulo, *w1hi, *w1lo, *w2hi, *w2lo, *yghi, *yglo;
    cudaGetSymbolAddress((void**)&zx,   g_zx);
    cudaGetSymbolAddress((void**)&xbc,  g_xbc);
    cudaGetSymbolAddress((void**)&ldec, g_ldec);
    cudaGetSymbolAddress((void**)&y,    g_y);
    cudaGetSymbolAddress((void**)&st,   g_st);
    cudaGetSymbolAddress((void**)&cum,  g_cum);
    cudaGetSymbolAddress((void**)&uhi,  g_uhi);
    cudaGetSymbolAddress((void**)&ulo,  g_ulo);
    cudaGetSymbolAddress((void**)&w1hi, g_w1hi);
    cudaGetSymbolAddress((void**)&w1lo, g_w1lo);
    cudaGetSymbolAddress((void**)&w2hi, g_w2hi);
    cudaGetSymbolAddress((void**)&w2lo, g_w2lo);
    cudaGetSymbolAddress((void**)&yghi, g_yghi);
    cudaGetSymbolAddress((void**)&yglo, g_yglo);

    cudaFuncSetAttribute(gemm_bf16x3,
        cudaFuncAttributeMaxDynamicSharedMemorySize, GB_SMEM_BYTES);
    cudaFuncSetAttribute(scan_matmul_kernel,
        cudaFuncAttributeMaxDynamicSharedMemorySize, SC_SMEM);
    cudaFuncSetAttribute(scan_fix_mm,
        cudaFuncAttributeMaxDynamicSharedMemorySize, FX_SMEM);

    static cudaStream_t s1 = nullptr;
    static cudaEvent_t evFork = nullptr, evJoin = nullptr;
    if (!s1) {
        cudaStreamCreateWithFlags(&s1, cudaStreamNonBlocking);
        cudaEventCreateWithFlags(&evFork, cudaEventDisableTiming);
        cudaEventCreateWithFlags(&evJoin, cudaEventDisableTiming);
    }

    // 0) split u, w1
    {
        int n4u = NROWS * D_MODEL / 4;
        split_kernel<<<(n4u + 255) / 256, 256>>>(u, uhi, ulo, n4u);
        int n4w1 = D_IN_PROJ * D_MODEL / 4;
        split_kernel<<<(n4w1 + 255) / 256, 256>>>(in_proj, w1hi, w1lo, n4w1);
    }
    // 1a) in_proj GEMM, xBC+dt columns
    {
        const int Nxbc = D_IN_PROJ - D_INNER;
        dim3 grid((Nxbc + GB_N - 1) / GB_N, NROWS / GB_M);
        gemm_bf16x3<<<grid, 256, GB_SMEM_BYTES>>>(
            uhi, ulo,
            w1hi + (size_t)D_INNER * D_MODEL, w1lo + (size_t)D_INNER * D_MODEL,
            zx + D_INNER, NROWS, Nxbc, D_MODEL, D_IN_PROJ);
    }
    // fork: 1b) z columns + w2 split on side stream
    cudaEventRecord(evFork, 0);
    cudaStreamWaitEvent(s1, evFork, 0);
    {
        dim3 grid(D_INNER / GB_N, NROWS / GB_M);
        gemm_bf16x3<<<grid, 256, GB_SMEM_BYTES, s1>>>(
            uhi, ulo, w1hi, w1lo, zx, NROWS, D_INNER, D_MODEL, D_IN_PROJ);
        int n4w2 = D_MODEL * D_INNER / 4;
        split_kernel<<<(n4w2 + 255) / 256, 256, 0, s1>>>(out_w, w2hi, w2lo, n4w2);
    }
    cudaEventRecord(evJoin, s1);

    // 2) conv + silu
    {
        dim3 grid((CONV_DIM + 255) / 256, SEQLEN / 256, BATCH);
        conv_kernel<<<grid, 256>>>(zx, conv_w, conv_b, xbc);
    }
    // 3) log-decay precompute
    decay_kernel<<<(NROWS * NHEADS + 255) / 256, 256>>>(zx, dt_bias, A_log, ldec);
    // 4) chunked SSM scan — all tensor-core
    {
        dim3 grid(NCHUNK, NHEADS, BATCH);
        scan_matmul_kernel<<<grid, 256, SC_SMEM>>>(xbc, ldec, Dv, y, st, cum);
    }
    {
        dim3 grid(NHEADS, BATCH, 8);
        scan_combine_kernel<<<grid, 256>>>(st, cum);
    }
    {
        dim3 grid(NCHUNK - 1, NHEADS, BATCH);
        scan_fix_mm<<<grid, 256, FX_SMEM>>>(st, cum, xbc, y);
    }
    cudaStreamWaitEvent(0, evJoin, 0);
    // 5) rmsnorm + gate
    rms_gate_kernel<<<NROWS, 256>>>(y, zx, rms_w, yghi, yglo);
    // 6) out_proj GEMM
    {
        dim3 grid(D_MODEL / GB_N, NROWS / GB_M);
        gemm_bf16x3<<<grid, 256, GB_SMEM_BYTES>>>(yghi, yglo, w2hi, w2lo, out,
                                                  NROWS, D_MODEL, D_INNER, D_MODEL);
    }
}

// round 15
// speedup vs baseline: 2.7812x; 1.8989x over previous
#include <cuda_runtime.h>
#include <cuda_bf16.h>
#include <cuda_fp16.h>
#include <cstdint>
#include <math.h>

// ---------------- problem constants ----------------
#define D_MODEL   1024
#define D_INNER   2048
#define D_STATE   64
#define HEADDIM   128
#define NHEADS    16
#define D_CONV    4
#define CONV_DIM  2176
#define D_IN_PROJ 4240
#define BATCH     2
#define SEQLEN    4096
#define NROWS     (BATCH*SEQLEN)  // 8192
#define RMS_EPS   1e-5f

#define LCHUNK    128
#define NCHUNK    (SEQLEN/LCHUNK)   // 32

// ---------------- scratch ----------------
__device__ float g_zx  [(size_t)NROWS * D_IN_PROJ];
__device__ float g_xbc [(size_t)NROWS * CONV_DIM];
__device__ float g_ldec[(size_t)NROWS * NHEADS];
__device__ float g_y   [(size_t)NROWS * D_INNER];
__device__ float g_st  [(size_t)BATCH * NHEADS * NCHUNK * HEADDIM * D_STATE];
__device__ float g_cum [(size_t)BATCH * NHEADS * NCHUNK * LCHUNK];
__device__ __half g_uh [(size_t)NROWS * D_MODEL];
__device__ __half g_w1h[(size_t)D_IN_PROJ * D_MODEL];
__device__ __half g_w2h[(size_t)D_MODEL * D_INNER];
__device__ __half g_ygh[(size_t)NROWS * D_INNER];

// ================= helpers =================
__device__ __forceinline__ uint32_t smem_to_u32(const void* p) {
    uint32_t a;
    asm("{ .reg .u64 t; cvta.to.shared.u64 t, %1; cvt.u32.u64 %0, t; }"
        : "=r"(a) : "l"(p));
    return a;
}
// pack two floats into fp16x2 (a -> low half, b -> high half)
__device__ __forceinline__ uint32_t packh2(float a, float b) {
    uint32_t r;
    asm("cvt.rn.f16x2.f32 %0, %1, %2;" : "=r"(r) : "f"(b), "f"(a));
    return r;
}
__device__ __forceinline__ float2 h2f2(uint32_t w) {
    __half2 h = *(__half2*)&w;
    return __half22float2(h);
}
__device__ __forceinline__ void mma_fp16(float* d, const uint32_t* a,
                                         const uint32_t* b) {
    asm volatile(
        "mma.sync.aligned.m16n8k16.row.col.f32.f16.f16.f32 "
        "{%0,%1,%2,%3},{%4,%5,%6,%7},{%8,%9},{%0,%1,%2,%3};"
        : "+f"(d[0]), "+f"(d[1]), "+f"(d[2]), "+f"(d[3])
        : "r"(a[0]), "r"(a[1]), "r"(a[2]), "r"(a[3]), "r"(b[0]), "r"(b[1]));
}
__device__ __forceinline__ void ldsm_x4(uint32_t& r0, uint32_t& r1,
                                        uint32_t& r2, uint32_t& r3,
                                        uint32_t addr) {
    asm volatile("ldmatrix.sync.aligned.m8n8.x4.shared.b16 {%0,%1,%2,%3}, [%4];"
                 : "=r"(r0), "=r"(r1), "=r"(r2), "=r"(r3) : "r"(addr));
}
__device__ __forceinline__ float fast_sigmoid(float x) {
    return __fdividef(1.f, 1.f + __expf(-x));
}
// swizzled addressing: 128B rows (64 fp16), col2 = uint32 index 0..31
__device__ __forceinline__ uint32_t a128(uint32_t base, int row, int col2) {
    return base + (uint32_t)(row * 128 + ((((col2 >> 2) ^ row) & 7) * 16) + (col2 & 3) * 4);
}
// swizzled addressing: 256B rows (128 fp16), col2 0..63
__device__ __forceinline__ uint32_t a256(uint32_t base, int row, int col2) {
    int cq = col2 >> 2;
    int ph = (((cq & 7) ^ (row & 7)) | (cq & 8));
    return base + (uint32_t)(row * 256 + ph * 16 + (col2 & 3) * 4);
}

// ================= split kernel: fp32 -> fp16 ==============================
__global__ __launch_bounds__(256) void split_kernel(
    const float* __restrict__ in, __half* __restrict__ out, int n4)
{
    int i = blockIdx.x * 256 + threadIdx.x;
    if (i >= n4) return;
    float4 v = ((const float4*)in)[i];
    ((uint2*)out)[i] = make_uint2(packh2(v.x, v.y), packh2(v.z, v.w));
}

// ================= GEMM (fp16, ldmatrix + 3-stage cp.async) ================
#define GB_M 128
#define GB_N 128
#define GB_K 32
#define GB_STAGE 16384
#define GB_SMEM_BYTES (3 * GB_STAGE)   // 49152

__global__ __launch_bounds__(256, 2) void gemm_fp16(
    const __half* __restrict__ A, const __half* __restrict__ B,
    float* __restrict__ C, int M, int N, int K, int ldc)
{
    extern __shared__ char smem[];
    const uint32_t sbase = smem_to_u32(smem);
    const int tid = threadIdx.x;
    const int bm  = blockIdx.y * GB_M;
    const int bn  = blockIdx.x * GB_N;
    const int nch = K / GB_K;

    const int warp = tid >> 5;
    const int lane = tid & 31;
    const int wm = warp >> 2;
    const int wn = warp & 3;
    const int lr = lane >> 2;
    const int lc = lane & 3;

    float acc[4][4][4];
    #pragma unroll
    for (int mt = 0; mt < 4; mt++)
        #pragma unroll
        for (int nt = 0; nt < 4; nt++)
            #pragma unroll
            for (int q = 0; q < 4; q++) acc[mt][nt][q] = 0.f;

    auto load_stage = [&](int buf, int kt) {
        #pragma unroll
        for (int i = 0; i < 4; i++) {
            int idx = tid + i * 256;       // 0..1023
            int cq = idx & 3;
            int r  = (idx >> 2) & 127;
            int t  = idx >> 9;             // 0: A, 1: B
            uint32_t so = sbase + (uint32_t)buf * GB_STAGE + (uint32_t)t * 8192 +
                          (uint32_t)r * 64 + (uint32_t)((cq ^ ((r >> 1) & 3)) * 16);
            const __half* g;
            if (t == 0) g = A + (size_t)(bm + r) * K;
            else {
                int gn = bn + r; if (gn >= N) gn = N - 1;
                g = B + (size_t)gn * K;
            }
            g += kt + cq * 8;
            asm volatile("cp.async.cg.shared.global [%0], [%1], 16;"
                         :: "r"(so), "l"(g));
        }
        asm volatile("cp.async.commit_group;");
    };

    load_stage(0, 0);
    if (nch > 1) load_stage(1, GB_K);

    const int rowA = wm * 64 + ((lane >> 3) & 1) * 8 + (lane & 7);
    const int rowB = wn * 32 + ((lane >> 4) & 1) * 8 + (lane & 7);
    const int sel  = ((lane & 7) >> 1) & 3;
    const int cAq  = (lane >> 4) & 1;
    const int cBq  = (lane >> 3) & 1;

    for (int c = 0; c < nch; c++) {
        if (c == nch - 1) asm volatile("cp.async.wait_group 0;");
        else              asm volatile("cp.async.wait_group 1;");
        __syncthreads();
        if (c + 2 < nch) load_stage((c + 2) % 3, (c + 2) * GB_K);

        const uint32_t stg = sbase + (uint32_t)(c % 3) * GB_STAGE;
        const uint32_t baseA = stg + (uint32_t)rowA * 64;
        const uint32_t baseB = stg + 8192 + (uint32_t)rowB * 64;

        #pragma unroll
        for (int ks = 0; ks < 2; ks++) {
            const uint32_t cAo = (uint32_t)(((ks * 2 + cAq) ^ sel) * 16);
            const uint32_t cBo = (uint32_t)(((ks * 2 + cBq) ^ sel) * 16);

            uint32_t bh[4][2];
            #pragma unroll
            for (int ntp = 0; ntp < 2; ntp++) {
                uint32_t r0, r1, r2, r3;
                ldsm_x4(r0, r1, r2, r3, baseB + ntp * 1024 + cBo);
                bh[ntp*2][0] = r0; bh[ntp*2][1] = r1;
                bh[ntp*2+1][0] = r2; bh[ntp*2+1][1] = r3;
            }
            #pragma unroll
            for (int mt = 0; mt < 4; mt++) {
                uint32_t ah[4];
                ldsm_x4(ah[0], ah[1], ah[2], ah[3], baseA + mt * 1024 + cAo);
                #pragma unroll
                for (int nt = 0; nt < 4; nt++)
                    mma_fp16(acc[mt][nt], ah, bh[nt]);
            }
        }
    }

    #pragma unroll
    for (int mt = 0; mt < 4; mt++) {
        int row = bm + wm * 64 + mt * 16 + lr;
        #pragma unroll
        for (int nt = 0; nt < 4; nt++) {
            int col = bn + wn * 32 + nt * 8 + lc * 2;
            if (col + 1 < N) {
                *(float2*)(C + (size_t)row * ldc + col) =
                    make_float2(acc[mt][nt][0], acc[mt][nt][1]);
                *(float2*)(C + (size_t)(row + 8) * ldc + col) =
                    make_float2(acc[mt][nt][2], acc[mt][nt][3]);
            }
        }
    }
}

// ---------------- depthwise causal conv (k=4) + bias + SiLU ----------------
__global__ __launch_bounds__(256) void conv_kernel(
    const float* __restrict__ zx, const float* __restrict__ cw,
    const float* __restrict__ cb, float* __restrict__ xbc)
{
    int c = blockIdx.x * 256 + threadIdx.x;
    if (c >= CONV_DIM) return;
    int strip = blockIdx.y;
    int b     = blockIdx.z;
    int l0    = strip * 256;

    float w0 = cw[c*4+0], w1 = cw[c*4+1], w2 = cw[c*4+2], w3 = cw[c*4+3];
    float bias = cb[c];

    size_t colbase = (size_t)D_INNER + c;
    size_t rb = (size_t)b * SEQLEN;

    float xm3 = (l0-3 >= 0) ? zx[(rb + l0-3) * D_IN_PROJ + colbase] : 0.f;
    float xm2 = (l0-2 >= 0) ? zx[(rb + l0-2) * D_IN_PROJ + colbase] : 0.f;
    float xm1 = (l0-1 >= 0) ? zx[(rb + l0-1) * D_IN_PROJ + colbase] : 0.f;

    for (int l = l0; l < l0 + 256; l++) {
        float xv = zx[(rb + l) * D_IN_PROJ + colbase];
        float a = bias;
        a = fmaf(w0, xm3, a);
        a = fmaf(w1, xm2, a);
        a = fmaf(w2, xm1, a);
        a = fmaf(w3, xv,  a);
        float sv = a * fast_sigmoid(a);
        xbc[(rb + l) * CONV_DIM + c] = sv;
        xm3 = xm2; xm2 = xm1; xm1 = xv;
    }
}

// ---------------- dt -> softplus -> LOG decay ------------------------------
__global__ __launch_bounds__(256) void decay_kernel(
    const float* __restrict__ zx, const float* __restrict__ dt_bias,
    const float* __restrict__ A_log, float* __restrict__ ldec)
{
    int idx = blockIdx.x * 256 + threadIdx.x;
    if (idx >= NROWS * NHEADS) return;
    int r = idx >> 4;
    int h = idx & 15;
    float raw = zx[(size_t)r * D_IN_PROJ + (D_IN_PROJ - NHEADS) + h] + dt_bias[h];
    float sp  = (raw > 20.f) ? raw : log1pf(expf(raw));
    float A   = -expf(A_log[h]);
    ldec[idx] = sp * A;
}

// ================= chunked matmul scan (intra-chunk, fp16) =================
#define SM_XT  0u         // 32KB  XT[128p][128l]
#define SM_CB  32768u     // C @32768 (16KB), B @49152 (16KB); later G (32KB)
#define SM_WB  65536u     // 16KB  WB[64n][128s]
#define SM_L   81920u     // 512B
#define SM_STG 82432u     // 16896B
#define SM_SMEM 99328u

__global__ __launch_bounds__(256, 2) void scan_matmul_kernel(
    const float* __restrict__ xbc, const float* __restrict__ ldec,
    const float* __restrict__ Dvec, float* __restrict__ yout,
    float* __restrict__ states, float* __restrict__ cumout)
{
    extern __shared__ char smem[];
    const uint32_t sb = smem_to_u32(smem);
    const int c = blockIdx.x;
    const int h = blockIdx.y;
    const int b = blockIdx.z;
    const int t = threadIdx.x;
    const int warp = t >> 5;
    const int lane = t & 31;
    const int lr = lane >> 2;
    const int lc = lane & 3;

    const size_t base = (size_t)b * SEQLEN + (size_t)c * LCHUNK;
    const int xcol = h * HEADDIM;
    const size_t cumbase = (size_t)(((b * NHEADS + h) * NCHUNK) + c) * LCHUNK;

    float* Lsm = (float*)(smem + SM_L);
    float* stg = (float*)(smem + SM_STG);

    // ---- load B, C (fp16, swizzled 128B rows [time][n]) ----
    {
        const uint32_t CH = sb + SM_CB;
        const uint32_t BH = sb + SM_CB + 16384;
        #pragma unroll
        for (int i = 0; i < 16; i++) {
            int idx = t + i * 256;
            int s = idx >> 5, col2 = idx & 31;
            const float* row = xbc + (base + s) * CONV_DIM + D_INNER;
            float2 vB = *(const float2*)(row + col2 * 2);
            float2 vC = *(const float2*)(row + 64 + col2 * 2);
            *(uint32_t*)(smem + (a128(BH, s, col2) - sb)) = packh2(vB.x, vB.y);
            *(uint32_t*)(smem + (a128(CH, s, col2) - sb)) = packh2(vC.x, vC.y);
        }
    }

    // ---- log-decay prefix (warp 0) + cum output ----
    if (warp == 0) {
        float v0 = ldec[(base + lane * 4 + 0) * NHEADS + h];
        float v1 = ldec[(base + lane * 4 + 1) * NHEADS + h];
        float v2 = ldec[(base + lane * 4 + 2) * NHEADS + h];
        float v3 = ldec[(base + lane * 4 + 3) * NHEADS + h];
        float p0 = v0, p1 = p0 + v1, p2 = p1 + v2, p3 = p2 + v3;
        float inc = p3;
        #pragma unroll
        for (int o = 1; o < 32; o <<= 1) {
            float n = __shfl_up_sync(0xffffffffu, inc, o);
            if (lane >= o) inc += n;
        }
        float excl = inc - p3;
        Lsm[lane*4+0] = excl + p0;
        Lsm[lane*4+1] = excl + p1;
        Lsm[lane*4+2] = excl + p2;
        Lsm[lane*4+3] = excl + p3;
        cumout[cumbase + lane*4+0] = __expf(excl + p0);
        cumout[cumbase + lane*4+1] = __expf(excl + p1);
        cumout[cumbase + lane*4+2] = __expf(excl + p2);
        cumout[cumbase + lane*4+3] = __expf(excl + p3);
    }

    // ---- X transpose: 4 strips of 128l x 32p ----
    #pragma unroll 1
    for (int pt = 0; pt < 4; pt++) {
        #pragma unroll
        for (int i = 0; i < 16; i++) {
            int idx = t + i * 256;
            int row = idx >> 5;
            int colp = idx & 31;
            stg[row * 33 + colp] =
                xbc[(base + row) * CONV_DIM + xcol + pt * 32 + colp];
        }
        __syncthreads();
        #pragma unroll
        for (int i = 0; i < 8; i++) {
            int idx = t + i * 256;
            int ploc = idx >> 6;
            int col2 = idx & 63;
            float v0 = stg[(col2 * 2) * 33 + ploc];
            float v1 = stg[(col2 * 2 + 1) * 33 + ploc];
            int p = pt * 32 + ploc;
            *(uint32_t*)(smem + (a256(sb + SM_XT, p, col2) - sb)) = packh2(v0, v1);
        }
        __syncthreads();
    }

    // ---- step 1: G = C·B^T  (M=128 l, N=128 s, K=64 n) ----
    const int wm = warp >> 2, wn = warp & 3;
    const int rowA = wm * 64 + ((lane >> 3) & 1) * 8 + (lane & 7);
    const int rowB = wn * 32 + ((lane >> 4) & 1) * 8 + (lane & 7);
    const int cAq = (lane >> 4) & 1;
    const int cBq = (lane >> 3) & 1;
    const int rA7 = rowA & 7, rB7 = rowB & 7;

    float acc1[4][4][4];
    #pragma unroll
    for (int mt = 0; mt < 4; mt++)
        #pragma unroll
        for (int nt = 0; nt < 4; nt++)
            #pragma unroll
            for (int q = 0; q < 4; q++) acc1[mt][nt][q] = 0.f;

    {
        const uint32_t aC = sb + SM_CB + (uint32_t)rowA * 128;
        const uint32_t aB = sb + SM_CB + 16384 + (uint32_t)rowB * 128;
        #pragma unroll
        for (int ks = 0; ks < 4; ks++) {
            uint32_t offA = (uint32_t)((((ks * 2 + cAq) ^ rA7) & 7) * 16);
            uint32_t offB = (uint32_t)((((ks * 2 + cBq) ^ rB7) & 7) * 16);
            uint32_t bh[4][2];
            #pragma unroll
            for (int ntp = 0; ntp < 2; ntp++) {
                uint32_t r0, r1, r2, r3;
                ldsm_x4(r0, r1, r2, r3, aB + ntp * 2048 + offB);
                bh[ntp*2][0]=r0; bh[ntp*2][1]=r1; bh[ntp*2+1][0]=r2; bh[ntp*2+1][1]=r3;
            }
            #pragma unroll
            for (int mt = 0; mt < 4; mt++) {
                uint32_t ah[4];
                ldsm_x4(ah[0], ah[1], ah[2], ah[3], aC + mt * 2048 + offA);
                #pragma unroll
                for (int nt = 0; nt < 4; nt++)
                    mma_fp16(acc1[mt][nt], ah, bh[nt]);
            }
        }
    }

    // ---- WB[n][s] = exp(L_last - L_s) * B[s][n] ----
    {
        const float Llast = Lsm[127];
        const uint32_t BH = sb + SM_CB + 16384;
        int n = t >> 2;
        int s0 = (t & 3) * 32;
        #pragma unroll
        for (int sp = 0; sp < 16; sp++) {
            int sA = s0 + sp * 2, sB2 = sA + 1;
            float2 fA = h2f2(*(uint32_t*)(smem + (a128(BH, sA, n >> 1) - sb)));
            float2 fB = h2f2(*(uint32_t*)(smem + (a128(BH, sB2, n >> 1) - sb)));
            float bA = (n & 1) ? fA.y : fA.x;
            float bB = (n & 1) ? fB.y : fB.x;
            float vA = bA * __expf(Llast - Lsm[sA]);
            float vB = bB * __expf(Llast - Lsm[sB2]);
            *(uint32_t*)(smem + (a256(sb + SM_WB, n, sA >> 1) - sb)) = packh2(vA, vB);
        }
    }
    __syncthreads();

    // ---- write G (overwrites C/B region): scale+mask, fp16 ----
    {
        const uint32_t GH = sb + SM_CB;
        #pragma unroll
        for (int mt = 0; mt < 4; mt++) {
            int l0 = wm * 64 + mt * 16 + lr;
            int l1 = l0 + 8;
            #pragma unroll
            for (int nt = 0; nt < 4; nt++) {
                int s0 = wn * 32 + nt * 8 + lc * 2;
                float Ll0 = Lsm[l0], Ll1 = Lsm[l1];
                float Ls0 = Lsm[s0], Ls1 = Lsm[s0 + 1];
                float e00 = (s0     <= l0) ? acc1[mt][nt][0] * __expf(Ll0 - Ls0) : 0.f;
                float e01 = (s0 + 1 <= l0) ? acc1[mt][nt][1] * __expf(Ll0 - Ls1) : 0.f;
                float e10 = (s0     <= l1) ? acc1[mt][nt][2] * __expf(Ll1 - Ls0) : 0.f;
                float e11 = (s0 + 1 <= l1) ? acc1[mt][nt][3] * __expf(Ll1 - Ls1) : 0.f;
                *(uint32_t*)(smem + (a256(GH, l0, s0 >> 1) - sb)) = packh2(e00, e01);
                *(uint32_t*)(smem + (a256(GH, l1, s0 >> 1) - sb)) = packh2(e10, e11);
            }
        }
    }
    __syncthreads();

    // ---- step 3: Y = G @ X   (M=128 l, N=128 p, K=128 s) ----
    {
        float acc3[4][4][4];
        #pragma unroll
        for (int mt = 0; mt < 4; mt++)
            #pragma unroll
            for (int nt = 0; nt < 4; nt++)
                #pragma unroll
                for (int q = 0; q < 4; q++) acc3[mt][nt][q] = 0.f;

        const uint32_t aG = sb + SM_CB + (uint32_t)rowA * 256;
        const uint32_t aX = sb + SM_XT + (uint32_t)rowB * 256;
        #pragma unroll
        for (int ks = 0; ks < 8; ks++) {
            int cqa = ks * 2 + cAq;
            int cqb = ks * 2 + cBq;
            uint32_t offA = (uint32_t)(((((cqa & 7) ^ rA7)) | (cqa & 8)) * 16);
            uint32_t offB = (uint32_t)(((((cqb & 7) ^ rB7)) | (cqb & 8)) * 16);
            uint32_t bh[4][2];
            #pragma unroll
            for (int ntp = 0; ntp < 2; ntp++) {
                uint32_t r0, r1, r2, r3;
                ldsm_x4(r0, r1, r2, r3, aX + ntp * 4096 + offB);
                bh[ntp*2][0]=r0; bh[ntp*2][1]=r1; bh[ntp*2+1][0]=r2; bh[ntp*2+1][1]=r3;
            }
            #pragma unroll
            for (int mt = 0; mt < 4; mt++) {
                uint32_t ah[4];
                ldsm_x4(ah[0], ah[1], ah[2], ah[3], aG + mt * 4096 + offA);
                #pragma unroll
                for (int nt = 0; nt < 4; nt++)
                    mma_fp16(acc3[mt][nt], ah, bh[nt]);
            }
        }
        const float Dh = Dvec[h];
        #pragma unroll
        for (int mt = 0; mt < 4; mt++) {
            int l0 = wm * 64 + mt * 16 + lr;
            int l1 = l0 + 8;
            #pragma unroll
            for (int nt = 0; nt < 4; nt++) {
                int p0 = wn * 32 + nt * 8 + lc * 2;
                float2 x0 = *(const float2*)(xbc + (base + l0) * CONV_DIM + xcol + p0);
                float2 x1 = *(const float2*)(xbc + (base + l1) * CONV_DIM + xcol + p0);
                *(float2*)(yout + (base + l0) * D_INNER + xcol + p0) =
                    make_float2(fmaf(Dh, x0.x, acc3[mt][nt][0]),
                                fmaf(Dh, x0.y, acc3[mt][nt][1]));
                *(float2*)(yout + (base + l1) * D_INNER + xcol + p0) =
                    make_float2(fmaf(Dh, x1.x, acc3[mt][nt][2]),
                                fmaf(Dh, x1.y, acc3[mt][nt][3]));
            }
        }
    }

    // ---- step 4: S_end[p][n] = X^T @ WB^T  (M=128 p, N=64 n, K=128 s) ----
    {
        const int wm4 = warp >> 1, wn4 = warp & 1;
        const int rowA4 = wm4 * 32 + ((lane >> 3) & 1) * 8 + (lane & 7);
        const int rowB4 = wn4 * 32 + ((lane >> 4) & 1) * 8 + (lane & 7);
        const int rA47 = rowA4 & 7, rB47 = rowB4 & 7;

        float acc4[2][4][4];
        #pragma unroll
        for (int mt = 0; mt < 2; mt++)
            #pragma unroll
            for (int nt = 0; nt < 4; nt++)
                #pragma unroll
                for (int q = 0; q < 4; q++) acc4[mt][nt][q] = 0.f;

        const uint32_t aX = sb + SM_XT + (uint32_t)rowA4 * 256;
        const uint32_t aW = sb + SM_WB + (uint32_t)rowB4 * 256;
        #pragma unroll
        for (int ks = 0; ks < 8; ks++) {
            int cqa = ks * 2 + cAq;
            int cqb = ks * 2 + cBq;
            uint32_t offA = (uint32_t)(((((cqa & 7) ^ rA47)) | (cqa & 8)) * 16);
            uint32_t offB = (uint32_t)(((((cqb & 7) ^ rB47)) | (cqb & 8)) * 16);
            uint32_t bh[4][2];
            #pragma unroll
            for (int ntp = 0; ntp < 2; ntp++) {
                uint32_t r0, r1, r2, r3;
                ldsm_x4(r0, r1, r2, r3, aW + ntp * 4096 + offB);
                bh[ntp*2][0]=r0; bh[ntp*2][1]=r1; bh[ntp*2+1][0]=r2; bh[ntp*2+1][1]=r3;
            }
            #pragma unroll
            for (int mt = 0; mt < 2; mt++) {
                uint32_t ah[4];
                ldsm_x4(ah[0], ah[1], ah[2], ah[3], aX + mt * 4096 + offA);
                #pragma unroll
                for (int nt = 0; nt < 4; nt++)
                    mma_fp16(acc4[mt][nt], ah, bh[nt]);
            }
        }
        float* stbase = states +
            ((size_t)(((b * NHEADS + h) * NCHUNK) + c) * HEADDIM) * D_STATE;
        #pragma unroll
        for (int mt = 0; mt < 2; mt++) {
            int p0 = wm4 * 32 + mt * 16 + lr;
            int p1 = p0 + 8;
            #pragma unroll
            for (int nt = 0; nt < 4; nt++) {
                int n0 = wn4 * 32 + nt * 8 + lc * 2;
                *(float2*)(stbase + (size_t)p0 * D_STATE + n0) =
                    make_float2(acc4[mt][nt][0], acc4[mt][nt][1]);
                *(float2*)(stbase + (size_t)p1 * D_STATE + n0) =
                    make_float2(acc4[mt][nt][2], acc4[mt][nt][3]);
            }
        }
    }
}

// ---------------- chunked scan: stage 2 (combine, p-sliced) ----------------
__global__ __launch_bounds__(256) void scan_combine_kernel(
    float* __restrict__ states, const float* __restrict__ cum)
{
    const int h   = blockIdx.x;
    const int b   = blockIdx.y;
    const int sl  = blockIdx.z;
    const int tid = threadIdx.x;

    __shared__ float dprod[NCHUNK];
    if (tid < NCHUNK)
        dprod[tid] = cum[(size_t)(((b * NHEADS + h) * NCHUNK) + tid) * LCHUNK + LCHUNK - 1];
    __syncthreads();

    const size_t chunk_stride = (size_t)HEADDIM * D_STATE;
    float* base = states + (size_t)((b * NHEADS + h) * NCHUNK) * chunk_stride
                         + (size_t)sl * 1024;

    float4 e = make_float4(0.f, 0.f, 0.f, 0.f);
    const int idx = tid;

    for (int c = 0; c < NCHUNK; c++) {
        float d = dprod[c];
        float4* p = (float4*)(base + c * chunk_stride);
        float4 s = p[idx];
        p[idx] = e;
        e.x = fmaf(e.x, d, s.x);
        e.y = fmaf(e.y, d, s.y);
        e.z = fmaf(e.z, d, s.z);
        e.w = fmaf(e.w, d, s.w);
    }
}

// ---------------- chunked scan: stage 3 (fp16 tensor-core GEMM) ------------
#define FX_A 0u
#define FX_B 16384u
#define FX_CUM 32768u
#define FX_SMEM 33280u

__global__ __launch_bounds__(256) void scan_fix_mm(
    const float* __restrict__ states, const float* __restrict__ cum,
    const float* __restrict__ xbc, float* __restrict__ yout)
{
    extern __shared__ char smem[];
    const uint32_t sb = smem_to_u32(smem);
    const int c = blockIdx.x + 1;
    const int h = blockIdx.y;
    const int b = blockIdx.z;
    const int t = threadIdx.x;
    const int warp = t >> 5, lane = t & 31;
    const int lr = lane >> 2, lc = lane & 3;
    const int wm = warp >> 2, wn = warp & 3;

    const size_t base = (size_t)b * SEQLEN + (size_t)c * LCHUNK;
    const size_t cumbase = (size_t)(((b * NHEADS + h) * NCHUNK) + c) * LCHUNK;
    const int xcol = h * HEADDIM;
    float* cum_sm = (float*)(smem + FX_CUM);

    if (t < 128) cum_sm[t] = cum[cumbase + t];
    __syncthreads();

    const float* stbase = states +
        ((size_t)(((b * NHEADS + h) * NCHUNK) + c) * HEADDIM) * D_STATE;
    #pragma unroll
    for (int i = 0; i < 16; i++) {
        int idx = t + i * 256;
        int r = idx >> 5, col2 = idx & 31;
        float cm = cum_sm[r];
        float2 vC = *(const float2*)(xbc + (base + r) * CONV_DIM + D_INNER + 64 + col2 * 2);
        *(uint32_t*)(smem + (a128(sb + FX_A, r, col2) - sb)) =
            packh2(vC.x * cm, vC.y * cm);
        float2 vS = *(const float2*)(stbase + (size_t)r * D_STATE + col2 * 2);
        *(uint32_t*)(smem + (a128(sb + FX_B, r, col2) - sb)) = packh2(vS.x, vS.y);
    }
    __syncthreads();

    const int rowA = wm * 64 + ((lane >> 3) & 1) * 8 + (lane & 7);
    const int rowB = wn * 32 + ((lane >> 4) & 1) * 8 + (lane & 7);
    const int cAq = (lane >> 4) & 1;
    const int cBq = (lane >> 3) & 1;
    const int rA7 = rowA & 7, rB7 = rowB & 7;

    float acc[4][4][4];
    #pragma unroll
    for (int mt = 0; mt < 4; mt++)
        #pragma unroll
        for (int nt = 0; nt < 4; nt++)
            #pragma unroll
            for (int q = 0; q < 4; q++) acc[mt][nt][q] = 0.f;

    {
        const uint32_t aA = sb + FX_A + (uint32_t)rowA * 128;
        const uint32_t aB = sb + FX_B + (uint32_t)rowB * 128;
        #pragma unroll
        for (int ks = 0; ks < 4; ks++) {
            uint32_t offA = (uint32_t)((((ks * 2 + cAq) ^ rA7) & 7) * 16);
            uint32_t offB = (uint32_t)((((ks * 2 + cBq) ^ rB7) & 7) * 16);
            uint32_t bh[4][2];
            #pragma unroll
            for (int ntp = 0; ntp < 2; ntp++) {
                uint32_t r0, r1, r2, r3;
                ldsm_x4(r0, r1, r2, r3, aB + ntp * 2048 + offB);
                bh[ntp*2][0]=r0; bh[ntp*2][1]=r1; bh[ntp*2+1][0]=r2; bh[ntp*2+1][1]=r3;
            }
            #pragma unroll
            for (int mt = 0; mt < 4; mt++) {
                uint32_t ah[4];
                ldsm_x4(ah[0], ah[1], ah[2], ah[3], aA + mt * 2048 + offA);
                #pragma unroll
                for (int nt = 0; nt < 4; nt++)
                    mma_fp16(acc[mt][nt], ah, bh[nt]);
            }
        }
    }

    #pragma unroll
    for (int mt = 0; mt < 4; mt++) {
        int l0 = wm * 64 + mt * 16 + lr;
        int l1 = l0 + 8;
        #pragma unroll
        for (int nt = 0; nt < 4; nt++) {
            int p0 = wn * 32 + nt * 8 + lc * 2;
            float2* y0 = (float2*)(yout + (base + l0) * D_INNER + xcol + p0);
            float2* y1 = (float2*)(yout + (base + l1) * D_INNER + xcol + p0);
            float2 v0 = *y0, v1 = *y1;
            v0.x += acc[mt][nt][0]; v0.y += acc[mt][nt][1];
            v1.x += acc[mt][nt][2]; v1.y += acc[mt][nt][3];
            *y0 = v0; *y1 = v1;
        }
    }
}

// ---------------- RMSNorm + gate, fp16 output ------------------------------
__global__ __launch_bounds__(256) void rms_gate_kernel(
    const float* __restrict__ y, const float* __restrict__ zx,
    const float* __restrict__ rmsw, __half* __restrict__ yg)
{
    int r = blockIdx.x;
    const float*  yr = y  + (size_t)r * D_INNER;
    const float*  zr = zx + (size_t)r * D_IN_PROJ;
    const float4* y4 = (const float4*)yr;

    int tid = threadIdx.x;
    float ss = 0.f;
    #pragma unroll
    for (int i = 0; i < 2; i++) {
        float4 v = y4[tid + i * 256];
        ss += v.x*v.x + v.y*v.y + v.z*v.z + v.w*v.w;
    }
    #pragma unroll
    for (int o = 16; o > 0; o >>= 1) ss += __shfl_xor_sync(0xffffffffu, ss, o);
    __shared__ float red[8];
    if ((tid & 31) == 0) red[tid >> 5] = ss;
    __syncthreads();
    if (tid == 0) {
        float t = 0.f;
        #pragma unroll
        for (int i = 0; i < 8; i++) t += red[i];
        red[0] = rsqrtf(t * (1.f / D_INNER) + RMS_EPS);
    }
    __syncthreads();
    float rs = red[0];

    const float4* z4 = (const float4*)zr;
    const float4* w4 = (const float4*)rmsw;
    uint2* gh = (uint2*)(yg + (size_t)r * D_INNER);
    #pragma unroll
    for (int i = 0; i < 2; i++) {
        int c = tid + i * 256;
        float4 v = y4[c];
        float4 z = z4[c];
        float4 w = w4[c];
        float4 o;
        o.x = v.x * rs * w.x * fast_sigmoid(z.x);
        o.y = v.y * rs * w.y * fast_sigmoid(z.y);
        o.z = v.z * rs * w.z * fast_sigmoid(z.z);
        o.w = v.w * rs * w.w * fast_sigmoid(z.w);
        gh[c] = make_uint2(packh2(o.x, o.y), packh2(o.z, o.w));
    }
}

// ---------------- launcher -------------------------------------------------
extern "C" void kernel_launch(void* const* d_in, const int* in_sizes, int n_in,
                              void* d_out, int out_size)
{
    const float* u        = (const float*)d_in[0];
    const float* in_proj  = (const float*)d_in[1];
    const float* conv_w   = (const float*)d_in[2];
    const float* conv_b   = (const float*)d_in[3];
    const float* dt_bias  = (const float*)d_in[4];
    const float* A_log    = (const float*)d_in[5];
    const float* Dv       = (const float*)d_in[6];
    const float* rms_w    = (const float*)d_in[7];
    const float* out_w    = (const float*)d_in[8];
    float* out = (float*)d_out;

    float *zx, *xbc, *ldec, *y, *st, *cum;
    __half *uh, *w1h, *w2h, *ygh;
    cudaGetSymbolAddress((void**)&zx,   g_zx);
    cudaGetSymbolAddress((void**)&xbc,  g_xbc);
    cudaGetSymbolAddress((void**)&ldec, g_ldec);
    cudaGetSymbolAddress((void**)&y,    g_y);
    cudaGetSymbolAddress((void**)&st,   g_st);
    cudaGetSymbolAddress((void**)&cum,  g_cum);
    cudaGetSymbolAddress((void**)&uh,   g_uh);
    cudaGetSymbolAddress((void**)&w1h,  g_w1h);
    cudaGetSymbolAddress((void**)&w2h,  g_w2h);
    cudaGetSymbolAddress((void**)&ygh,  g_ygh);

    cudaFuncSetAttribute(gemm_fp16,
        cudaFuncAttributeMaxDynamicSharedMemorySize, GB_SMEM_BYTES);
    cudaFuncSetAttribute(scan_matmul_kernel,
        cudaFuncAttributeMaxDynamicSharedMemorySize, SM_SMEM);
    cudaFuncSetAttribute(scan_fix_mm,
        cudaFuncAttributeMaxDynamicSharedMemorySize, FX_SMEM);

    static cudaStream_t s1 = nullptr;
    static cudaEvent_t evFork = nullptr, evJoin = nullptr;
    if (!s1) {
        cudaStreamCreateWithFlags(&s1, cudaStreamNonBlocking);
        cudaEventCreateWithFlags(&evFork, cudaEventDisableTiming);
        cudaEventCreateWithFlags(&evJoin, cudaEventDisableTiming);
    }

    // 0) convert u, w1 to fp16
    {
        int n4u = NROWS * D_MODEL / 4;
        split_kernel<<<(n4u + 255) / 256, 256>>>(u, uh, n4u);
        int n4w1 = D_IN_PROJ * D_MODEL / 4;
        split_kernel<<<(n4w1 + 255) / 256, 256>>>(in_proj, w1h, n4w1);
    }
    // 1a) in_proj GEMM, xBC+dt columns
    {
        const int Nxbc = D_IN_PROJ - D_INNER;
        dim3 grid((Nxbc + GB_N - 1) / GB_N, NROWS / GB_M);
        gemm_fp16<<<grid, 256, GB_SMEM_BYTES>>>(
            uh, w1h + (size_t)D_INNER * D_MODEL,
            zx + D_INNER, NROWS, Nxbc, D_MODEL, D_IN_PROJ);
    }
    // fork: 1b) z columns + w2 convert on side stream
    cudaEventRecord(evFork, 0);
    cudaStreamWaitEvent(s1, evFork, 0);
    {
        dim3 grid(D_INNER / GB_N, NROWS / GB_M);
        gemm_fp16<<<grid, 256, GB_SMEM_BYTES, s1>>>(
            uh, w1h, zx, NROWS, D_INNER, D_MODEL, D_IN_PROJ);
        int n4w2 = D_MODEL * D_INNER / 4;
        split_kernel<<<(n4w2 + 255) / 256, 256, 0, s1>>>(out_w, w2h, n4w2);
    }
    cudaEventRecord(evJoin, s1);

    // 2) conv + silu
    {
        dim3 grid((CONV_DIM + 255) / 256, SEQLEN / 256, BATCH);
        conv_kernel<<<grid, 256>>>(zx, conv_w, conv_b, xbc);
    }
    // 3) log-decay precompute
    decay_kernel<<<(NROWS * NHEADS + 255) / 256, 256>>>(zx, dt_bias, A_log, ldec);
    // 4) chunked SSM scan — all tensor-core
    {
        dim3 grid(NCHUNK, NHEADS, BATCH);
        scan_matmul_kernel<<<grid, 256, SM_SMEM>>>(xbc, ldec, Dv, y, st, cum);
    }
    {
        dim3 grid(NHEADS, BATCH, 8);
        scan_combine_kernel<<<grid, 256>>>(st, cum);
    }
    {
        dim3 grid(NCHUNK - 1, NHEADS, BATCH);
        scan_fix_mm<<<grid, 256, FX_SMEM>>>(st, cum, xbc, y);
    }
    cudaStreamWaitEvent(0, evJoin, 0);
    // 5) rmsnorm + gate
    rms_gate_kernel<<<NROWS, 256>>>(y, zx, rms_w, ygh);
    // 6) out_proj GEMM
    {
        dim3 grid(D_MODEL / GB_N, NROWS / GB_M);
        gemm_fp16<<<grid, 256, GB_SMEM_BYTES>>>(ygh, w2h, out,
                                                NROWS, D_MODEL, D_INNER, D_MODEL);
    }
}

// round 16
// speedup vs baseline: 2.9162x; 1.0485x over previous
#include <cuda_runtime.h>
#include <cuda_bf16.h>
#include <cuda_fp16.h>
#include <cstdint>
#include <math.h>

// ---------------- problem constants ----------------
#define D_MODEL   1024
#define D_INNER   2048
#define D_STATE   64
#define HEADDIM   128
#define NHEADS    16
#define D_CONV    4
#define CONV_DIM  2176
#define D_IN_PROJ 4240
#define BATCH     2
#define SEQLEN    4096
#define NROWS     (BATCH*SEQLEN)  // 8192
#define RMS_EPS   1e-5f

#define LCHUNK    128
#define NCHUNK    (SEQLEN/LCHUNK)   // 32

// ---------------- scratch ----------------
__device__ float g_zx  [(size_t)NROWS * D_IN_PROJ];
__device__ float g_xbc [(size_t)NROWS * CONV_DIM];
__device__ float g_ldec[(size_t)NROWS * NHEADS];
__device__ float g_y   [(size_t)NROWS * D_INNER];
__device__ float g_st  [(size_t)BATCH * NHEADS * NCHUNK * HEADDIM * D_STATE];
__device__ float g_cum [(size_t)BATCH * NHEADS * NCHUNK * LCHUNK];
__device__ __half g_uh [(size_t)NROWS * D_MODEL];
__device__ __half g_w1h[(size_t)D_IN_PROJ * D_MODEL];
__device__ __half g_w2h[(size_t)D_MODEL * D_INNER];
__device__ __half g_ygh[(size_t)NROWS * D_INNER];

// ================= helpers =================
__device__ __forceinline__ uint32_t smem_to_u32(const void* p) {
    uint32_t a;
    asm("{ .reg .u64 t; cvta.to.shared.u64 t, %1; cvt.u32.u64 %0, t; }"
        : "=r"(a) : "l"(p));
    return a;
}
__device__ __forceinline__ uint32_t packh2(float a, float b) {
    uint32_t r;
    asm("cvt.rn.f16x2.f32 %0, %1, %2;" : "=r"(r) : "f"(b), "f"(a));
    return r;
}
__device__ __forceinline__ float2 h2f2(uint32_t w) {
    __half2 h = *(__half2*)&w;
    return __half22float2(h);
}
__device__ __forceinline__ void mma_fp16(float* d, const uint32_t* a,
                                         const uint32_t* b) {
    asm volatile(
        "mma.sync.aligned.m16n8k16.row.col.f32.f16.f16.f32 "
        "{%0,%1,%2,%3},{%4,%5,%6,%7},{%8,%9},{%0,%1,%2,%3};"
        : "+f"(d[0]), "+f"(d[1]), "+f"(d[2]), "+f"(d[3])
        : "r"(a[0]), "r"(a[1]), "r"(a[2]), "r"(a[3]), "r"(b[0]), "r"(b[1]));
}
__device__ __forceinline__ void ldsm_x4(uint32_t& r0, uint32_t& r1,
                                        uint32_t& r2, uint32_t& r3,
                                        uint32_t addr) {
    asm volatile("ldmatrix.sync.aligned.m8n8.x4.shared.b16 {%0,%1,%2,%3}, [%4];"
                 : "=r"(r0), "=r"(r1), "=r"(r2), "=r"(r3) : "r"(addr));
}
__device__ __forceinline__ float fast_sigmoid(float x) {
    return __fdividef(1.f, 1.f + __expf(-x));
}
// swizzled addressing: 128B rows (64 fp16), col2 = uint32 index 0..31
__device__ __forceinline__ uint32_t a128(uint32_t base, int row, int col2) {
    return base + (uint32_t)(row * 128 + ((((col2 >> 2) ^ row) & 7) * 16) + (col2 & 3) * 4);
}
// swizzled addressing: 256B rows (128 fp16), col2 0..63
__device__ __forceinline__ uint32_t a256(uint32_t base, int row, int col2) {
    int cq = col2 >> 2;
    int ph = (((cq & 7) ^ (row & 7)) | (cq & 8));
    return base + (uint32_t)(row * 256 + ph * 16 + (col2 & 3) * 4);
}

// ================= split kernel: fp32 -> fp16 ==============================
__global__ __launch_bounds__(256) void split_kernel(
    const float* __restrict__ in, __half* __restrict__ out, int n4)
{
    int i = blockIdx.x * 256 + threadIdx.x;
    if (i >= n4) return;
    float4 v = ((const float4*)in)[i];
    ((uint2*)out)[i] = make_uint2(packh2(v.x, v.y), packh2(v.z, v.w));
}

// ================= GEMM (fp16, K=64 chunks, 3-stage cp.async) ==============
#define GB_M 128
#define GB_N 128
#define GB_K 64
#define GB_STAGE 32768              // A 16KB + B 16KB, 128B rows
#define GB_SMEM_BYTES (3 * GB_STAGE)   // 98304

__global__ __launch_bounds__(256, 2) void gemm_fp16(
    const __half* __restrict__ A, const __half* __restrict__ B,
    float* __restrict__ C, int M, int N, int K, int ldc)
{
    extern __shared__ char smem[];
    const uint32_t sbase = smem_to_u32(smem);
    const int tid = threadIdx.x;
    const int bm  = blockIdx.y * GB_M;
    const int bn  = blockIdx.x * GB_N;
    const int nch = K / GB_K;

    const int warp = tid >> 5;
    const int lane = tid & 31;
    const int wm = warp >> 2;
    const int wn = warp & 3;
    const int lr = lane >> 2;
    const int lc = lane & 3;

    float acc[4][4][4];
    #pragma unroll
    for (int mt = 0; mt < 4; mt++)
        #pragma unroll
        for (int nt = 0; nt < 4; nt++)
            #pragma unroll
            for (int q = 0; q < 4; q++) acc[mt][nt][q] = 0.f;

    auto load_stage = [&](int buf, int kt) {
        #pragma unroll
        for (int i = 0; i < 8; i++) {
            int idx = tid + i * 256;       // 0..2047 16B-chunks
            int cq = idx & 7;              // 16B chunk within 128B row
            int r  = (idx >> 3) & 127;
            int t  = idx >> 10;            // 0: A, 1: B
            uint32_t so = sbase + (uint32_t)buf * GB_STAGE + (uint32_t)t * 16384 +
                          (uint32_t)r * 128 + (uint32_t)(((cq ^ r) & 7) * 16);
            const __half* g;
            if (t == 0) g = A + (size_t)(bm + r) * K;
            else {
                int gn = bn + r; if (gn >= N) gn = N - 1;
                g = B + (size_t)gn * K;
            }
            g += kt + cq * 8;
            asm volatile("cp.async.cg.shared.global [%0], [%1], 16;"
                         :: "r"(so), "l"(g));
        }
        asm volatile("cp.async.commit_group;");
    };

    load_stage(0, 0);
    if (nch > 1) load_stage(1, GB_K);

    const int rowA = wm * 64 + ((lane >> 3) & 1) * 8 + (lane & 7);
    const int rowB = wn * 32 + ((lane >> 4) & 1) * 8 + (lane & 7);
    const int cAq  = (lane >> 4) & 1;
    const int cBq  = (lane >> 3) & 1;
    const int rA7  = rowA & 7;
    const int rB7  = rowB & 7;

    for (int c = 0; c < nch; c++) {
        if (c == nch - 1) asm volatile("cp.async.wait_group 0;");
        else              asm volatile("cp.async.wait_group 1;");
        __syncthreads();
        if (c + 2 < nch) load_stage((c + 2) % 3, (c + 2) * GB_K);

        const uint32_t stg = sbase + (uint32_t)(c % 3) * GB_STAGE;
        const uint32_t baseA = stg + (uint32_t)rowA * 128;
        const uint32_t baseB = stg + 16384 + (uint32_t)rowB * 128;

        #pragma unroll
        for (int ks = 0; ks < 4; ks++) {
            const uint32_t cAo = (uint32_t)((((ks * 2 + cAq) ^ rA7) & 7) * 16);
            const uint32_t cBo = (uint32_t)((((ks * 2 + cBq) ^ rB7) & 7) * 16);

            uint32_t bh[4][2];
            #pragma unroll
            for (int ntp = 0; ntp < 2; ntp++) {
                uint32_t r0, r1, r2, r3;
                ldsm_x4(r0, r1, r2, r3, baseB + ntp * 2048 + cBo);
                bh[ntp*2][0] = r0; bh[ntp*2][1] = r1;
                bh[ntp*2+1][0] = r2; bh[ntp*2+1][1] = r3;
            }
            #pragma unroll
            for (int mt = 0; mt < 4; mt++) {
                uint32_t ah[4];
                ldsm_x4(ah[0], ah[1], ah[2], ah[3], baseA + mt * 2048 + cAo);
                #pragma unroll
                for (int nt = 0; nt < 4; nt++)
                    mma_fp16(acc[mt][nt], ah, bh[nt]);
            }
        }
    }

    #pragma unroll
    for (int mt = 0; mt < 4; mt++) {
        int row = bm + wm * 64 + mt * 16 + lr;
        #pragma unroll
        for (int nt = 0; nt < 4; nt++) {
            int col = bn + wn * 32 + nt * 8 + lc * 2;
            if (col + 1 < N) {
                *(float2*)(C + (size_t)row * ldc + col) =
                    make_float2(acc[mt][nt][0], acc[mt][nt][1]);
                *(float2*)(C + (size_t)(row + 8) * ldc + col) =
                    make_float2(acc[mt][nt][2], acc[mt][nt][3]);
            }
        }
    }
}

// ---------------- depthwise causal conv (k=4) + bias + SiLU ----------------
__global__ __launch_bounds__(256) void conv_kernel(
    const float* __restrict__ zx, const float* __restrict__ cw,
    const float* __restrict__ cb, float* __restrict__ xbc)
{
    int c = blockIdx.x * 256 + threadIdx.x;
    if (c >= CONV_DIM) return;
    int strip = blockIdx.y;
    int b     = blockIdx.z;
    int l0    = strip * 256;

    float w0 = cw[c*4+0], w1 = cw[c*4+1], w2 = cw[c*4+2], w3 = cw[c*4+3];
    float bias = cb[c];

    size_t colbase = (size_t)D_INNER + c;
    size_t rb = (size_t)b * SEQLEN;

    float xm3 = (l0-3 >= 0) ? zx[(rb + l0-3) * D_IN_PROJ + colbase] : 0.f;
    float xm2 = (l0-2 >= 0) ? zx[(rb + l0-2) * D_IN_PROJ + colbase] : 0.f;
    float xm1 = (l0-1 >= 0) ? zx[(rb + l0-1) * D_IN_PROJ + colbase] : 0.f;

    for (int l = l0; l < l0 + 256; l++) {
        float xv = zx[(rb + l) * D_IN_PROJ + colbase];
        float a = bias;
        a = fmaf(w0, xm3, a);
        a = fmaf(w1, xm2, a);
        a = fmaf(w2, xm1, a);
        a = fmaf(w3, xv,  a);
        float sv = a * fast_sigmoid(a);
        xbc[(rb + l) * CONV_DIM + c] = sv;
        xm3 = xm2; xm2 = xm1; xm1 = xv;
    }
}

// ---------------- dt -> softplus -> LOG decay ------------------------------
__global__ __launch_bounds__(256) void decay_kernel(
    const float* __restrict__ zx, const float* __restrict__ dt_bias,
    const float* __restrict__ A_log, float* __restrict__ ldec)
{
    int idx = blockIdx.x * 256 + threadIdx.x;
    if (idx >= NROWS * NHEADS) return;
    int r = idx >> 4;
    int h = idx & 15;
    float raw = zx[(size_t)r * D_IN_PROJ + (D_IN_PROJ - NHEADS) + h] + dt_bias[h];
    float sp  = (raw > 20.f) ? raw : log1pf(expf(raw));
    float A   = -expf(A_log[h]);
    ldec[idx] = sp * A;
}

// ================= chunked matmul scan (intra-chunk, fp16) =================
#define SM_XT  0u
#define SM_CB  32768u
#define SM_WB  65536u
#define SM_L   81920u
#define SM_STG 82432u
#define SM_SMEM 99328u

__global__ __launch_bounds__(256, 2) void scan_matmul_kernel(
    const float* __restrict__ xbc, const float* __restrict__ ldec,
    const float* __restrict__ Dvec, float* __restrict__ yout,
    float* __restrict__ states, float* __restrict__ cumout)
{
    extern __shared__ char smem[];
    const uint32_t sb = smem_to_u32(smem);
    const int c = blockIdx.x;
    const int h = blockIdx.y;
    const int b = blockIdx.z;
    const int t = threadIdx.x;
    const int warp = t >> 5;
    const int lane = t & 31;
    const int lr = lane >> 2;
    const int lc = lane & 3;

    const size_t base = (size_t)b * SEQLEN + (size_t)c * LCHUNK;
    const int xcol = h * HEADDIM;
    const size_t cumbase = (size_t)(((b * NHEADS + h) * NCHUNK) + c) * LCHUNK;

    float* Lsm = (float*)(smem + SM_L);
    float* stg = (float*)(smem + SM_STG);

    // ---- load B, C (fp16, swizzled 128B rows [time][n]) ----
    {
        const uint32_t CH = sb + SM_CB;
        const uint32_t BH = sb + SM_CB + 16384;
        #pragma unroll
        for (int i = 0; i < 16; i++) {
            int idx = t + i * 256;
            int s = idx >> 5, col2 = idx & 31;
            const float* row = xbc + (base + s) * CONV_DIM + D_INNER;
            float2 vB = *(const float2*)(row + col2 * 2);
            float2 vC = *(const float2*)(row + 64 + col2 * 2);
            *(uint32_t*)(smem + (a128(BH, s, col2) - sb)) = packh2(vB.x, vB.y);
            *(uint32_t*)(smem + (a128(CH, s, col2) - sb)) = packh2(vC.x, vC.y);
        }
    }

    // ---- log-decay prefix (warp 0) + cum output ----
    if (warp == 0) {
        float v0 = ldec[(base + lane * 4 + 0) * NHEADS + h];
        float v1 = ldec[(base + lane * 4 + 1) * NHEADS + h];
        float v2 = ldec[(base + lane * 4 + 2) * NHEADS + h];
        float v3 = ldec[(base + lane * 4 + 3) * NHEADS + h];
        float p0 = v0, p1 = p0 + v1, p2 = p1 + v2, p3 = p2 + v3;
        float inc = p3;
        #pragma unroll
        for (int o = 1; o < 32; o <<= 1) {
            float n = __shfl_up_sync(0xffffffffu, inc, o);
            if (lane >= o) inc += n;
        }
        float excl = inc - p3;
        Lsm[lane*4+0] = excl + p0;
        Lsm[lane*4+1] = excl + p1;
        Lsm[lane*4+2] = excl + p2;
        Lsm[lane*4+3] = excl + p3;
        cumout[cumbase + lane*4+0] = __expf(excl + p0);
        cumout[cumbase + lane*4+1] = __expf(excl + p1);
        cumout[cumbase + lane*4+2] = __expf(excl + p2);
        cumout[cumbase + lane*4+3] = __expf(excl + p3);
    }

    // ---- X transpose: 4 strips of 128l x 32p ----
    #pragma unroll 1
    for (int pt = 0; pt < 4; pt++) {
        #pragma unroll
        for (int i = 0; i < 16; i++) {
            int idx = t + i * 256;
            int row = idx >> 5;
            int colp = idx & 31;
            stg[row * 33 + colp] =
                xbc[(base + row) * CONV_DIM + xcol + pt * 32 + colp];
        }
        __syncthreads();
        #pragma unroll
        for (int i = 0; i < 8; i++) {
            int idx = t + i * 256;
            int ploc = idx >> 6;
            int col2 = idx & 63;
            float v0 = stg[(col2 * 2) * 33 + ploc];
            float v1 = stg[(col2 * 2 + 1) * 33 + ploc];
            int p = pt * 32 + ploc;
            *(uint32_t*)(smem + (a256(sb + SM_XT, p, col2) - sb)) = packh2(v0, v1);
        }
        __syncthreads();
    }

    // ---- step 1: G = C·B^T  (M=128 l, N=128 s, K=64 n) ----
    const int wm = warp >> 2, wn = warp & 3;
    const int rowA = wm * 64 + ((lane >> 3) & 1) * 8 + (lane & 7);
    const int rowB = wn * 32 + ((lane >> 4) & 1) * 8 + (lane & 7);
    const int cAq = (lane >> 4) & 1;
    const int cBq = (lane >> 3) & 1;
    const int rA7 = rowA & 7, rB7 = rowB & 7;

    float acc1[4][4][4];
    #pragma unroll
    for (int mt = 0; mt < 4; mt++)
        #pragma unroll
        for (int nt = 0; nt < 4; nt++)
            #pragma unroll
            for (int q = 0; q < 4; q++) acc1[mt][nt][q] = 0.f;

    {
        const uint32_t aC = sb + SM_CB + (uint32_t)rowA * 128;
        const uint32_t aB = sb + SM_CB + 16384 + (uint32_t)rowB * 128;
        #pragma unroll
        for (int ks = 0; ks < 4; ks++) {
            uint32_t offA = (uint32_t)((((ks * 2 + cAq) ^ rA7) & 7) * 16);
            uint32_t offB = (uint32_t)((((ks * 2 + cBq) ^ rB7) & 7) * 16);
            uint32_t bh[4][2];
            #pragma unroll
            for (int ntp = 0; ntp < 2; ntp++) {
                uint32_t r0, r1, r2, r3;
                ldsm_x4(r0, r1, r2, r3, aB + ntp * 2048 + offB);
                bh[ntp*2][0]=r0; bh[ntp*2][1]=r1; bh[ntp*2+1][0]=r2; bh[ntp*2+1][1]=r3;
            }
            #pragma unroll
            for (int mt = 0; mt < 4; mt++) {
                uint32_t ah[4];
                ldsm_x4(ah[0], ah[1], ah[2], ah[3], aC + mt * 2048 + offA);
                #pragma unroll
                for (int nt = 0; nt < 4; nt++)
                    mma_fp16(acc1[mt][nt], ah, bh[nt]);
            }
        }
    }

    // ---- WB[n][s] = exp(L_last - L_s) * B[s][n] ----
    {
        const float Llast = Lsm[127];
        const uint32_t BH = sb + SM_CB + 16384;
        int n = t >> 2;
        int s0 = (t & 3) * 32;
        #pragma unroll
        for (int sp = 0; sp < 16; sp++) {
            int sA = s0 + sp * 2, sB2 = sA + 1;
            float2 fA = h2f2(*(uint32_t*)(smem + (a128(BH, sA, n >> 1) - sb)));
            float2 fB = h2f2(*(uint32_t*)(smem + (a128(BH, sB2, n >> 1) - sb)));
            float bA = (n & 1) ? fA.y : fA.x;
            float bB = (n & 1) ? fB.y : fB.x;
            float vA = bA * __expf(Llast - Lsm[sA]);
            float vB = bB * __expf(Llast - Lsm[sB2]);
            *(uint32_t*)(smem + (a256(sb + SM_WB, n, sA >> 1) - sb)) = packh2(vA, vB);
        }
    }
    __syncthreads();

    // ---- write G (overwrites C/B region): scale+mask, fp16 ----
    {
        const uint32_t GH = sb + SM_CB;
        #pragma unroll
        for (int mt = 0; mt < 4; mt++) {
            int l0 = wm * 64 + mt * 16 + lr;
            int l1 = l0 + 8;
            #pragma unroll
            for (int nt = 0; nt < 4; nt++) {
                int s0 = wn * 32 + nt * 8 + lc * 2;
                float Ll0 = Lsm[l0], Ll1 = Lsm[l1];
                float Ls0 = Lsm[s0], Ls1 = Lsm[s0 + 1];
                float e00 = (s0     <= l0) ? acc1[mt][nt][0] * __expf(Ll0 - Ls0) : 0.f;
                float e01 = (s0 + 1 <= l0) ? acc1[mt][nt][1] * __expf(Ll0 - Ls1) : 0.f;
                float e10 = (s0     <= l1) ? acc1[mt][nt][2] * __expf(Ll1 - Ls0) : 0.f;
                float e11 = (s0 + 1 <= l1) ? acc1[mt][nt][3] * __expf(Ll1 - Ls1) : 0.f;
                *(uint32_t*)(smem + (a256(GH, l0, s0 >> 1) - sb)) = packh2(e00, e01);
                *(uint32_t*)(smem + (a256(GH, l1, s0 >> 1) - sb)) = packh2(e10, e11);
            }
        }
    }
    __syncthreads();

    // ---- step 3: Y = G @ X   (M=128 l, N=128 p, K=128 s) ----
    {
        float acc3[4][4][4];
        #pragma unroll
        for (int mt = 0; mt < 4; mt++)
            #pragma unroll
            for (int nt = 0; nt < 4; nt++)
                #pragma unroll
                for (int q = 0; q < 4; q++) acc3[mt][nt][q] = 0.f;

        const uint32_t aG = sb + SM_CB + (uint32_t)rowA * 256;
        const uint32_t aX = sb + SM_XT + (uint32_t)rowB * 256;
        #pragma unroll
        for (int ks = 0; ks < 8; ks++) {
            int cqa = ks * 2 + cAq;
            int cqb = ks * 2 + cBq;
            uint32_t offA = (uint32_t)(((((cqa & 7) ^ rA7)) | (cqa & 8)) * 16);
            uint32_t offB = (uint32_t)(((((cqb & 7) ^ rB7)) | (cqb & 8)) * 16);
            uint32_t bh[4][2];
            #pragma unroll
            for (int ntp = 0; ntp < 2; ntp++) {
                uint32_t r0, r1, r2, r3;
                ldsm_x4(r0, r1, r2, r3, aX + ntp * 4096 + offB);
                bh[ntp*2][0]=r0; bh[ntp*2][1]=r1; bh[ntp*2+1][0]=r2; bh[ntp*2+1][1]=r3;
            }
            #pragma unroll
            for (int mt = 0; mt < 4; mt++) {
                uint32_t ah[4];
                ldsm_x4(ah[0], ah[1], ah[2], ah[3], aG + mt * 4096 + offA);
                #pragma unroll
                for (int nt = 0; nt < 4; nt++)
                    mma_fp16(acc3[mt][nt], ah, bh[nt]);
            }
        }
        const float Dh = Dvec[h];
        #pragma unroll
        for (int mt = 0; mt < 4; mt++) {
            int l0 = wm * 64 + mt * 16 + lr;
            int l1 = l0 + 8;
            #pragma unroll
            for (int nt = 0; nt < 4; nt++) {
                int p0 = wn * 32 + nt * 8 + lc * 2;
                float2 x0 = *(const float2*)(xbc + (base + l0) * CONV_DIM + xcol + p0);
                float2 x1 = *(const float2*)(xbc + (base + l1) * CONV_DIM + xcol + p0);
                *(float2*)(yout + (base + l0) * D_INNER + xcol + p0) =
                    make_float2(fmaf(Dh, x0.x, acc3[mt][nt][0]),
                                fmaf(Dh, x0.y, acc3[mt][nt][1]));
                *(float2*)(yout + (base + l1) * D_INNER + xcol + p0) =
                    make_float2(fmaf(Dh, x1.x, acc3[mt][nt][2]),
                                fmaf(Dh, x1.y, acc3[mt][nt][3]));
            }
        }
    }

    // ---- step 4: S_end[p][n] = X^T @ WB^T  (M=128 p, N=64 n, K=128 s) ----
    {
        const int wm4 = warp >> 1, wn4 = warp & 1;
        const int rowA4 = wm4 * 32 + ((lane >> 3) & 1) * 8 + (lane & 7);
        const int rowB4 = wn4 * 32 + ((lane >> 4) & 1) * 8 + (lane & 7);
        const int rA47 = rowA4 & 7, rB47 = rowB4 & 7;

        float acc4[2][4][4];
        #pragma unroll
        for (int mt = 0; mt < 2; mt++)
            #pragma unroll
            for (int nt = 0; nt < 4; nt++)
                #pragma unroll
                for (int q = 0; q < 4; q++) acc4[mt][nt][q] = 0.f;

        const uint32_t aX = sb + SM_XT + (uint32_t)rowA4 * 256;
        const uint32_t aW = sb + SM_WB + (uint32_t)rowB4 * 256;
        #pragma unroll
        for (int ks = 0; ks < 8; ks++) {
            int cqa = ks * 2 + cAq;
            int cqb = ks * 2 + cBq;
            uint32_t offA = (uint32_t)(((((cqa & 7) ^ rA47)) | (cqa & 8)) * 16);
            uint32_t offB = (uint32_t)(((((cqb & 7) ^ rB47)) | (cqb & 8)) * 16);
            uint32_t bh[4][2];
            #pragma unroll
            for (int ntp = 0; ntp < 2; ntp++) {
                uint32_t r0, r1, r2, r3;
                ldsm_x4(r0, r1, r2, r3, aW + ntp * 4096 + offB);
                bh[ntp*2][0]=r0; bh[ntp*2][1]=r1; bh[ntp*2+1][0]=r2; bh[ntp*2+1][1]=r3;
            }
            #pragma unroll
            for (int mt = 0; mt < 2; mt++) {
                uint32_t ah[4];
                ldsm_x4(ah[0], ah[1], ah[2], ah[3], aX + mt * 4096 + offA);
                #pragma unroll
                for (int nt = 0; nt < 4; nt++)
                    mma_fp16(acc4[mt][nt], ah, bh[nt]);
            }
        }
        float* stbase = states +
            ((size_t)(((b * NHEADS + h) * NCHUNK) + c) * HEADDIM) * D_STATE;
        #pragma unroll
        for (int mt = 0; mt < 2; mt++) {
            int p0 = wm4 * 32 + mt * 16 + lr;
            int p1 = p0 + 8;
            #pragma unroll
            for (int nt = 0; nt < 4; nt++) {
                int n0 = wn4 * 32 + nt * 8 + lc * 2;
                *(float2*)(stbase + (size_t)p0 * D_STATE + n0) =
                    make_float2(acc4[mt][nt][0], acc4[mt][nt][1]);
                *(float2*)(stbase + (size_t)p1 * D_STATE + n0) =
                    make_float2(acc4[mt][nt][2], acc4[mt][nt][3]);
            }
        }
    }
}

// ---------------- chunked scan: stage 2 (combine, p-sliced) ----------------
__global__ __launch_bounds__(256) void scan_combine_kernel(
    float* __restrict__ states, const float* __restrict__ cum)
{
    const int h   = blockIdx.x;
    const int b   = blockIdx.y;
    const int sl  = blockIdx.z;
    const int tid = threadIdx.x;

    __shared__ float dprod[NCHUNK];
    if (tid < NCHUNK)
        dprod[tid] = cum[(size_t)(((b * NHEADS + h) * NCHUNK) + tid) * LCHUNK + LCHUNK - 1];
    __syncthreads();

    const size_t chunk_stride = (size_t)HEADDIM * D_STATE;
    float* base = states + (size_t)((b * NHEADS + h) * NCHUNK) * chunk_stride
                         + (size_t)sl * 1024;

    float4 e = make_float4(0.f, 0.f, 0.f, 0.f);
    const int idx = tid;

    for (int c = 0; c < NCHUNK; c++) {
        float d = dprod[c];
        float4* p = (float4*)(base + c * chunk_stride);
        float4 s = p[idx];
        p[idx] = e;
        e.x = fmaf(e.x, d, s.x);
        e.y = fmaf(e.y, d, s.y);
        e.z = fmaf(e.z, d, s.z);
        e.w = fmaf(e.w, d, s.w);
    }
}

// ---------------- chunked scan: stage 3 (fp16 tensor-core GEMM) ------------
#define FX_A 0u
#define FX_B 16384u
#define FX_CUM 32768u
#define FX_SMEM 33280u

__global__ __launch_bounds__(256) void scan_fix_mm(
    const float* __restrict__ states, const float* __restrict__ cum,
    const float* __restrict__ xbc, float* __restrict__ yout)
{
    extern __shared__ char smem[];
    const uint32_t sb = smem_to_u32(smem);
    const int c = blockIdx.x + 1;
    const int h = blockIdx.y;
    const int b = blockIdx.z;
    const int t = threadIdx.x;
    const int warp = t >> 5, lane = t & 31;
    const int lr = lane >> 2, lc = lane & 3;
    const int wm = warp >> 2, wn = warp & 3;

    const size_t base = (size_t)b * SEQLEN + (size_t)c * LCHUNK;
    const size_t cumbase = (size_t)(((b * NHEADS + h) * NCHUNK) + c) * LCHUNK;
    const int xcol = h * HEADDIM;
    float* cum_sm = (float*)(smem + FX_CUM);

    if (t < 128) cum_sm[t] = cum[cumbase + t];
    __syncthreads();

    const float* stbase = states +
        ((size_t)(((b * NHEADS + h) * NCHUNK) + c) * HEADDIM) * D_STATE;
    #pragma unroll
    for (int i = 0; i < 16; i++) {
        int idx = t + i * 256;
        int r = idx >> 5, col2 = idx & 31;
        float cm = cum_sm[r];
        float2 vC = *(const float2*)(xbc + (base + r) * CONV_DIM + D_INNER + 64 + col2 * 2);
        *(uint32_t*)(smem + (a128(sb + FX_A, r, col2) - sb)) =
            packh2(vC.x * cm, vC.y * cm);
        float2 vS = *(const float2*)(stbase + (size_t)r * D_STATE + col2 * 2);
        *(uint32_t*)(smem + (a128(sb + FX_B, r, col2) - sb)) = packh2(vS.x, vS.y);
    }
    __syncthreads();

    const int rowA = wm * 64 + ((lane >> 3) & 1) * 8 + (lane & 7);
    const int rowB = wn * 32 + ((lane >> 4) & 1) * 8 + (lane & 7);
    const int cAq = (lane >> 4) & 1;
    const int cBq = (lane >> 3) & 1;
    const int rA7 = rowA & 7, rB7 = rowB & 7;

    float acc[4][4][4];
    #pragma unroll
    for (int mt = 0; mt < 4; mt++)
        #pragma unroll
        for (int nt = 0; nt < 4; nt++)
            #pragma unroll
            for (int q = 0; q < 4; q++) acc[mt][nt][q] = 0.f;

    {
        const uint32_t aA = sb + FX_A + (uint32_t)rowA * 128;
        const uint32_t aB = sb + FX_B + (uint32_t)rowB * 128;
        #pragma unroll
        for (int ks = 0; ks < 4; ks++) {
            uint32_t offA = (uint32_t)((((ks * 2 + cAq) ^ rA7) & 7) * 16);
            uint32_t offB = (uint32_t)((((ks * 2 + cBq) ^ rB7) & 7) * 16);
            uint32_t bh[4][2];
            #pragma unroll
            for (int ntp = 0; ntp < 2; ntp++) {
                uint32_t r0, r1, r2, r3;
                ldsm_x4(r0, r1, r2, r3, aB + ntp * 2048 + offB);
                bh[ntp*2][0]=r0; bh[ntp*2][1]=r1; bh[ntp*2+1][0]=r2; bh[ntp*2+1][1]=r3;
            }
            #pragma unroll
            for (int mt = 0; mt < 4; mt++) {
                uint32_t ah[4];
                ldsm_x4(ah[0], ah[1], ah[2], ah[3], aA + mt * 2048 + offA);
                #pragma unroll
                for (int nt = 0; nt < 4; nt++)
                    mma_fp16(acc[mt][nt], ah, bh[nt]);
            }
        }
    }

    #pragma unroll
    for (int mt = 0; mt < 4; mt++) {
        int l0 = wm * 64 + mt * 16 + lr;
        int l1 = l0 + 8;
        #pragma unroll
        for (int nt = 0; nt < 4; nt++) {
            int p0 = wn * 32 + nt * 8 + lc * 2;
            float2* y0 = (float2*)(yout + (base + l0) * D_INNER + xcol + p0);
            float2* y1 = (float2*)(yout + (base + l1) * D_INNER + xcol + p0);
            float2 v0 = *y0, v1 = *y1;
            v0.x += acc[mt][nt][0]; v0.y += acc[mt][nt][1];
            v1.x += acc[mt][nt][2]; v1.y += acc[mt][nt][3];
            *y0 = v0; *y1 = v1;
        }
    }
}

// ---------------- RMSNorm + gate, fp16 output ------------------------------
__global__ __launch_bounds__(256) void rms_gate_kernel(
    const float* __restrict__ y, const float* __restrict__ zx,
    const float* __restrict__ rmsw, __half* __restrict__ yg)
{
    int r = blockIdx.x;
    const float*  yr = y  + (size_t)r * D_INNER;
    const float*  zr = zx + (size_t)r * D_IN_PROJ;
    const float4* y4 = (const float4*)yr;

    int tid = threadIdx.x;
    float ss = 0.f;
    #pragma unroll
    for (int i = 0; i < 2; i++) {
        float4 v = y4[tid + i * 256];
        ss += v.x*v.x + v.y*v.y + v.z*v.z + v.w*v.w;
    }
    #pragma unroll
    for (int o = 16; o > 0; o >>= 1) ss += __shfl_xor_sync(0xffffffffu, ss, o);
    __shared__ float red[8];
    if ((tid & 31) == 0) red[tid >> 5] = ss;
    __syncthreads();
    if (tid == 0) {
        float t = 0.f;
        #pragma unroll
        for (int i = 0; i < 8; i++) t += red[i];
        red[0] = rsqrtf(t * (1.f / D_INNER) + RMS_EPS);
    }
    __syncthreads();
    float rs = red[0];

    const float4* z4 = (const float4*)zr;
    const float4* w4 = (const float4*)rmsw;
    uint2* gh = (uint2*)(yg + (size_t)r * D_INNER);
    #pragma unroll
    for (int i = 0; i < 2; i++) {
        int c = tid + i * 256;
        float4 v = y4[c];
        float4 z = z4[c];
        float4 w = w4[c];
        float4 o;
        o.x = v.x * rs * w.x * fast_sigmoid(z.x);
        o.y = v.y * rs * w.y * fast_sigmoid(z.y);
        o.z = v.z * rs * w.z * fast_sigmoid(z.z);
        o.w = v.w * rs * w.w * fast_sigmoid(z.w);
        gh[c] = make_uint2(packh2(o.x, o.y), packh2(o.z, o.w));
    }
}

// ---------------- launcher -------------------------------------------------
extern "C" void kernel_launch(void* const* d_in, const int* in_sizes, int n_in,
                              void* d_out, int out_size)
{
    const float* u        = (const float*)d_in[0];
    const float* in_proj  = (const float*)d_in[1];
    const float* conv_w   = (const float*)d_in[2];
    const float* conv_b   = (const float*)d_in[3];
    const float* dt_bias  = (const float*)d_in[4];
    const float* A_log    = (const float*)d_in[5];
    const float* Dv       = (const float*)d_in[6];
    const float* rms_w    = (const float*)d_in[7];
    const float* out_w    = (const float*)d_in[8];
    float* out = (float*)d_out;

    float *zx, *xbc, *ldec, *y, *st, *cum;
    __half *uh, *w1h, *w2h, *ygh;
    cudaGetSymbolAddress((void**)&zx,   g_zx);
    cudaGetSymbolAddress((void**)&xbc,  g_xbc);
    cudaGetSymbolAddress((void**)&ldec, g_ldec);
    cudaGetSymbolAddress((void**)&y,    g_y);
    cudaGetSymbolAddress((void**)&st,   g_st);
    cudaGetSymbolAddress((void**)&cum,  g_cum);
    cudaGetSymbolAddress((void**)&uh,   g_uh);
    cudaGetSymbolAddress((void**)&w1h,  g_w1h);
    cudaGetSymbolAddress((void**)&w2h,  g_w2h);
    cudaGetSymbolAddress((void**)&ygh,  g_ygh);

    cudaFuncSetAttribute(gemm_fp16,
        cudaFuncAttributeMaxDynamicSharedMemorySize, GB_SMEM_BYTES);
    cudaFuncSetAttribute(scan_matmul_kernel,
        cudaFuncAttributeMaxDynamicSharedMemorySize, SM_SMEM);
    cudaFuncSetAttribute(scan_fix_mm,
        cudaFuncAttributeMaxDynamicSharedMemorySize, FX_SMEM);

    static cudaStream_t s1 = nullptr;
    static cudaEvent_t evFork = nullptr, evJoin = nullptr;
    if (!s1) {
        cudaStreamCreateWithFlags(&s1, cudaStreamNonBlocking);
        cudaEventCreateWithFlags(&evFork, cudaEventDisableTiming);
        cudaEventCreateWithFlags(&evJoin, cudaEventDisableTiming);
    }

    // 0) convert u, w1 to fp16
    {
        int n4u = NROWS * D_MODEL / 4;
        split_kernel<<<(n4u + 255) / 256, 256>>>(u, uh, n4u);
        int n4w1 = D_IN_PROJ * D_MODEL / 4;
        split_kernel<<<(n4w1 + 255) / 256, 256>>>(in_proj, w1h, n4w1);
    }
    // 1a) in_proj GEMM, xBC+dt columns
    {
        const int Nxbc = D_IN_PROJ - D_INNER;
        dim3 grid((Nxbc + GB_N - 1) / GB_N, NROWS / GB_M);
        gemm_fp16<<<grid, 256, GB_SMEM_BYTES>>>(
            uh, w1h + (size_t)D_INNER * D_MODEL,
            zx + D_INNER, NROWS, Nxbc, D_MODEL, D_IN_PROJ);
    }
    // fork: 1b) z columns + w2 convert on side stream
    cudaEventRecord(evFork, 0);
    cudaStreamWaitEvent(s1, evFork, 0);
    {
        dim3 grid(D_INNER / GB_N, NROWS / GB_M);
        gemm_fp16<<<grid, 256, GB_SMEM_BYTES, s1>>>(
            uh, w1h, zx, NROWS, D_INNER, D_MODEL, D_IN_PROJ);
        int n4w2 = D_MODEL * D_INNER / 4;
        split_kernel<<<(n4w2 + 255) / 256, 256, 0, s1>>>(out_w, w2h, n4w2);
    }
    cudaEventRecord(evJoin, s1);

    // 2) conv + silu
    {
        dim3 grid((CONV_DIM + 255) / 256, SEQLEN / 256, BATCH);
        conv_kernel<<<grid, 256>>>(zx, conv_w, conv_b, xbc);
    }
    // 3) log-decay precompute
    decay_kernel<<<(NROWS * NHEADS + 255) / 256, 256>>>(zx, dt_bias, A_log, ldec);
    // 4) chunked SSM scan — all tensor-core
    {
        dim3 grid(NCHUNK, NHEADS, BATCH);
        scan_matmul_kernel<<<grid, 256, SM_SMEM>>>(xbc, ldec, Dv, y, st, cum);
    }
    {
        dim3 grid(NHEADS, BATCH, 8);
        scan_combine_kernel<<<grid, 256>>>(st, cum);
    }
    {
        dim3 grid(NCHUNK - 1, NHEADS, BATCH);
        scan_fix_mm<<<grid, 256, FX_SMEM>>>(st, cum, xbc, y);
    }
    cudaStreamWaitEvent(0, evJoin, 0);
    // 5) rmsnorm + gate
    rms_gate_kernel<<<NROWS, 256>>>(y, zx, rms_w, ygh);
    // 6) out_proj GEMM
    {
        dim3 grid(D_MODEL / GB_N, NROWS / GB_M);
        gemm_fp16<<<grid, 256, GB_SMEM_BYTES>>>(ygh, w2h, out,
                                                NROWS, D_MODEL, D_INNER, D_MODEL);
    }
}